// round 1
// baseline (speedup 1.0000x reference)
#include <cuda_runtime.h>
#include <cstdint>

// ---------------- problem constants ----------------
#define BATCH 2
#define LSEQ  8192
#define DMOD  768
#define NFFT  16384          // 2*LSEQ zero-padded FFT size
#define LOGN  14
#define EMB   64

// ---------------- scratch (static device globals; no runtime alloc) ----------------
__device__ float  g_qT[BATCH * DMOD * LSEQ];   // q transposed [b][d][l]
__device__ float  g_kT[BATCH * DMOD * LSEQ];   // k transposed
__device__ float  g_vT[BATCH * DMOD * LSEQ];   // v transposed
__device__ float  g_u [BATCH * DMOD * LSEQ];   // conv(k)*conv(v)
__device__ float  g_h [DMOD * LSEQ];           // hyena filter [d][l]
__device__ float2 g_Hf[DMOD * NFFT];           // filter spectrum (bit-reversed order)
__device__ float  g_yg[BATCH * LSEQ * DMOD];   // gated output [b][l][d]
__device__ float2 g_tw[NFFT / 2];              // twiddle table exp(-2*pi*i*t/N)

// ---------------- twiddle init ----------------
__global__ void k_twiddle() {
    int i = blockIdx.x * blockDim.x + threadIdx.x;
    if (i < NFFT / 2) {
        double ang = -2.0 * 3.14159265358979323846 * (double)i / (double)NFFT;
        g_tw[i] = make_float2((float)cos(ang), (float)sin(ang));
    }
}

// ---------------- GEMM: C[i][j] = sum_k A[i,k]*B[j,k] (both row-major, K=768) ----------
// 128x128 tile, 256 threads, 8x8 microtile, BK=8.
// Epilogue 1 (qkv): i indexes in_proj_w rows (0..2303), j indexes x rows (0..16383).
// Writes q/k/v in transposed [b][d][l] layout, contiguous along l (coalesced).
__global__ __launch_bounds__(256) void k_gemm_qkv(const float* __restrict__ A,
                                                  const float* __restrict__ B) {
    __shared__ float As[8][132];
    __shared__ float Bs[8][132];
    const int i0 = blockIdx.y * 128;
    const int j0 = blockIdx.x * 128;
    const int tid = threadIdx.x;
    const int tx = tid & 15, ty = tid >> 4;
    const int lr = tid >> 1;            // 0..127
    const int lh = (tid & 1) * 4;       // 0 or 4

    float acc[8][8];
#pragma unroll
    for (int a = 0; a < 8; a++)
#pragma unroll
        for (int b = 0; b < 8; b++) acc[a][b] = 0.f;

    const float* Ar = A + (size_t)(i0 + lr) * 768 + lh;
    const float* Br = B + (size_t)(j0 + lr) * 768 + lh;

    for (int kb = 0; kb < 768; kb += 8) {
        float4 av = *(const float4*)(Ar + kb);
        float4 bv = *(const float4*)(Br + kb);
        As[lh + 0][lr] = av.x; As[lh + 1][lr] = av.y; As[lh + 2][lr] = av.z; As[lh + 3][lr] = av.w;
        Bs[lh + 0][lr] = bv.x; Bs[lh + 1][lr] = bv.y; Bs[lh + 2][lr] = bv.z; Bs[lh + 3][lr] = bv.w;
        __syncthreads();
#pragma unroll
        for (int k = 0; k < 8; k++) {
            float a[8], b[8];
#pragma unroll
            for (int p = 0; p < 8; p++) { a[p] = As[k][ty * 8 + p]; b[p] = Bs[k][tx * 8 + p]; }
#pragma unroll
            for (int ii = 0; ii < 8; ii++)
#pragma unroll
                for (int jj = 0; jj < 8; jj++) acc[ii][jj] += a[ii] * b[jj];
        }
        __syncthreads();
    }

#pragma unroll
    for (int ii = 0; ii < 8; ii++) {
        int n = i0 + ty * 8 + ii;            // 0..2303
        int part = n / DMOD;
        int dch = n - part * DMOD;
        float* tgt = (part == 0) ? g_qT : (part == 1 ? g_kT : g_vT);
        int m0 = j0 + tx * 8;                // multiple of 8, never crosses batch boundary
        int bb = m0 >> 13;
        int l  = m0 & (LSEQ - 1);
        float* p = tgt + ((size_t)bb * DMOD + dch) * LSEQ + l;
        *(float4*)(p)     = make_float4(acc[ii][0], acc[ii][1], acc[ii][2], acc[ii][3]);
        *(float4*)(p + 4) = make_float4(acc[ii][4], acc[ii][5], acc[ii][6], acc[ii][7]);
    }
}

// Epilogue 2 (out-proj): i indexes yg rows (0..16383), j indexes out_proj_w rows (0..767).
__global__ __launch_bounds__(256) void k_gemm_out(float* __restrict__ C,
                                                  const float* __restrict__ Bw) {
    __shared__ float As[8][132];
    __shared__ float Bs[8][132];
    const int i0 = blockIdx.y * 128;
    const int j0 = blockIdx.x * 128;
    const int tid = threadIdx.x;
    const int tx = tid & 15, ty = tid >> 4;
    const int lr = tid >> 1;
    const int lh = (tid & 1) * 4;

    float acc[8][8];
#pragma unroll
    for (int a = 0; a < 8; a++)
#pragma unroll
        for (int b = 0; b < 8; b++) acc[a][b] = 0.f;

    const float* Ar = g_yg + (size_t)(i0 + lr) * 768 + lh;
    const float* Br = Bw + (size_t)(j0 + lr) * 768 + lh;

    for (int kb = 0; kb < 768; kb += 8) {
        float4 av = *(const float4*)(Ar + kb);
        float4 bv = *(const float4*)(Br + kb);
        As[lh + 0][lr] = av.x; As[lh + 1][lr] = av.y; As[lh + 2][lr] = av.z; As[lh + 3][lr] = av.w;
        Bs[lh + 0][lr] = bv.x; Bs[lh + 1][lr] = bv.y; Bs[lh + 2][lr] = bv.z; Bs[lh + 3][lr] = bv.w;
        __syncthreads();
#pragma unroll
        for (int k = 0; k < 8; k++) {
            float a[8], b[8];
#pragma unroll
            for (int p = 0; p < 8; p++) { a[p] = As[k][ty * 8 + p]; b[p] = Bs[k][tx * 8 + p]; }
#pragma unroll
            for (int ii = 0; ii < 8; ii++)
#pragma unroll
                for (int jj = 0; jj < 8; jj++) acc[ii][jj] += a[ii] * b[jj];
        }
        __syncthreads();
    }

#pragma unroll
    for (int ii = 0; ii < 8; ii++) {
        int m = i0 + ty * 8 + ii;
        float* p = C + (size_t)m * DMOD + j0 + tx * 8;
        *(float4*)(p)     = make_float4(acc[ii][0], acc[ii][1], acc[ii][2], acc[ii][3]);
        *(float4*)(p + 4) = make_float4(acc[ii][4], acc[ii][5], acc[ii][6], acc[ii][7]);
    }
}

// ---------------- depthwise causal conv (k=3) + elementwise multiply ----------------
// out[l] = w0*in[l-2] + w1*in[l-1] + w2*in[l] + b   (lax conv == cross-correlation)
__global__ void k_convmul(const float* __restrict__ skw, const float* __restrict__ skb,
                          const float* __restrict__ svw, const float* __restrict__ svb) {
    int bd = blockIdx.x;                 // 0..BATCH*DMOD-1
    int d  = bd % DMOD;
    const float* ki = g_kT + (size_t)bd * LSEQ;
    const float* vi = g_vT + (size_t)bd * LSEQ;
    float* uo = g_u + (size_t)bd * LSEQ;
    float kw0 = skw[d * 3], kw1 = skw[d * 3 + 1], kw2 = skw[d * 3 + 2], kb = skb[d];
    float vw0 = svw[d * 3], vw1 = svw[d * 3 + 1], vw2 = svw[d * 3 + 2], vb = svb[d];
    for (int l = threadIdx.x; l < LSEQ; l += blockDim.x) {
        float k2 = ki[l];
        float k1 = (l >= 1) ? ki[l - 1] : 0.f;
        float k0 = (l >= 2) ? ki[l - 2] : 0.f;
        float v2 = vi[l];
        float v1 = (l >= 1) ? vi[l - 1] : 0.f;
        float v0 = (l >= 2) ? vi[l - 2] : 0.f;
        float kc = kw0 * k0 + kw1 * k1 + kw2 * k2 + kb;
        float vc = vw0 * v0 + vw1 * v1 + vw2 * v2 + vb;
        uo[l] = kc * vc;
    }
}

// ---------------- hyena filter MLP + decay ----------------
// One block handles 32 consecutive l values with 768 threads.
#define FILT_TL 32
__global__ __launch_bounds__(768) void k_filter(const float* __restrict__ w1, const float* __restrict__ b1,
                                                const float* __restrict__ w2, const float* __restrict__ b2,
                                                const float* __restrict__ w3, const float* __restrict__ b3,
                                                const float* __restrict__ ld) {
    __shared__ float pe [FILT_TL][EMB];
    __shared__ float h1s[FILT_TL][EMB];
    __shared__ float h2s[FILT_TL][EMB];
    const int l0 = blockIdx.x * FILT_TL;
    const int tid = threadIdx.x;
    const float TWO_PI = 6.2831853071795864769f;
    const float inv = 1.0f / (float)(LSEQ - 1);

    for (int idx = tid; idx < FILT_TL * EMB; idx += blockDim.x) {
        int li = idx / EMB, e = idx % EMB;
        float t = (float)(l0 + li) * inv;
        float val;
        if (e < 32) val = sinf(t * TWO_PI * (float)(e + 1));
        else        val = cosf(t * TWO_PI * (float)(e - 31));
        pe[li][e] = val;
    }
    __syncthreads();
    for (int idx = tid; idx < FILT_TL * EMB; idx += blockDim.x) {
        int li = idx / EMB, e = idx % EMB;
        float s = b1[e];
        const float* wr = w1 + e * EMB;
#pragma unroll 8
        for (int c = 0; c < EMB; c++) s += pe[li][c] * wr[c];
        h1s[li][e] = s / (1.f + __expf(-s));
    }
    __syncthreads();
    for (int idx = tid; idx < FILT_TL * EMB; idx += blockDim.x) {
        int li = idx / EMB, e = idx % EMB;
        float s = b2[e];
        const float* wr = w2 + e * EMB;
#pragma unroll 8
        for (int c = 0; c < EMB; c++) s += h1s[li][c] * wr[c];
        h2s[li][e] = s / (1.f + __expf(-s));
    }
    __syncthreads();
    // each thread = one channel d, computes all 32 l's (reuses w3 row from L1)
    int d = tid;
    float accl[FILT_TL];
#pragma unroll
    for (int li = 0; li < FILT_TL; li++) accl[li] = 0.f;
    const float* w3r = w3 + d * EMB;
    for (int e = 0; e < EMB; e++) {
        float wv = w3r[e];
#pragma unroll
        for (int li = 0; li < FILT_TL; li++) accl[li] += h2s[li][e] * wv;
    }
    float b3d = b3[d];
    float a = fabsf(ld[d]);
    float* out = g_h + (size_t)d * LSEQ + l0;
#pragma unroll
    for (int li = 0; li < FILT_TL; li++) {
        float dec = __expf(-a * (float)(l0 + li));
        out[li] = (accl[li] + b3d) * dec;
    }
}

// ---------------- FFT helpers (radix-2, in shared memory) ----------------
// Forward: DIF, natural input -> bit-reversed output.
__device__ __forceinline__ void fft_fwd(float2* sm, int tid, int nthr) {
    for (int s = 0; s < LOGN; s++) {
        int mlog = LOGN - 1 - s;
        int m = 1 << mlog;
#pragma unroll 4
        for (int idx = tid; idx < NFFT / 2; idx += nthr) {
            int j  = idx & (m - 1);
            int i0 = ((idx >> mlog) << (mlog + 1)) + j;
            int i1 = i0 + m;
            float2 a = sm[i0], b = sm[i1];
            float2 w = g_tw[j << s];
            float2 su = make_float2(a.x + b.x, a.y + b.y);
            float2 df = make_float2(a.x - b.x, a.y - b.y);
            sm[i0] = su;
            sm[i1] = make_float2(df.x * w.x - df.y * w.y, df.x * w.y + df.y * w.x);
        }
        __syncthreads();
    }
}

// Inverse: DIT, bit-reversed input -> natural output (conjugate twiddles, NO 1/N scale here).
__device__ __forceinline__ void fft_inv(float2* sm, int tid, int nthr) {
    for (int s = 0; s < LOGN; s++) {
        int m = 1 << s;
#pragma unroll 4
        for (int idx = tid; idx < NFFT / 2; idx += nthr) {
            int j  = idx & (m - 1);
            int i0 = ((idx >> s) << (s + 1)) + j;
            int i1 = i0 + m;
            float2 a = sm[i0], b = sm[i1];
            float2 w = g_tw[j << (LOGN - 1 - s)];   // conj applied below
            float2 t = make_float2(b.x * w.x + b.y * w.y, b.y * w.x - b.x * w.y);
            sm[i0] = make_float2(a.x + t.x, a.y + t.y);
            sm[i1] = make_float2(a.x - t.x, a.y - t.y);
        }
        __syncthreads();
    }
}

// ---------------- filter spectrum ----------------
__global__ void k_fft_h() {
    extern __shared__ float2 sm[];
    const int d = blockIdx.x;
    const int tid = threadIdx.x, nthr = blockDim.x;
    const float* src = g_h + (size_t)d * LSEQ;
    for (int i = tid; i < LSEQ; i += nthr) sm[i] = make_float2(src[i], 0.f);
    for (int i = LSEQ + tid; i < NFFT; i += nthr) sm[i] = make_float2(0.f, 0.f);
    __syncthreads();
    fft_fwd(sm, tid, nthr);
    float2* dst = g_Hf + (size_t)d * NFFT;
    for (int i = tid; i < NFFT; i += nthr) dst[i] = sm[i];
}

// ---------------- fused: FFT(u) * Hf -> IFFT -> silu(q) gate -> yg [b][l][d] ------------
__global__ void k_fftconv() {
    extern __shared__ float2 sm[];
    const int bd = blockIdx.x;           // b*DMOD + d
    const int b = bd / DMOD;
    const int d = bd - b * DMOD;
    const int tid = threadIdx.x, nthr = blockDim.x;
    const float* src = g_u + (size_t)bd * LSEQ;
    for (int i = tid; i < LSEQ; i += nthr) sm[i] = make_float2(src[i], 0.f);
    for (int i = LSEQ + tid; i < NFFT; i += nthr) sm[i] = make_float2(0.f, 0.f);
    __syncthreads();
    fft_fwd(sm, tid, nthr);
    const float2* H = g_Hf + (size_t)d * NFFT;
    const float scale = 1.0f / (float)NFFT;
    for (int i = tid; i < NFFT; i += nthr) {
        float2 z = sm[i];
        float2 h = H[i];
        sm[i] = make_float2((z.x * h.x - z.y * h.y) * scale,
                            (z.x * h.y + z.y * h.x) * scale);
    }
    __syncthreads();
    fft_inv(sm, tid, nthr);
    const float* q = g_qT + (size_t)bd * LSEQ;
    for (int l = tid; l < LSEQ; l += nthr) {
        float y = sm[l].x;
        float qq = q[l];
        float g = qq / (1.f + __expf(-qq));
        g_yg[((size_t)b * LSEQ + l) * DMOD + d] = g * y;
    }
}

// ---------------- launch ----------------
extern "C" void kernel_launch(void* const* d_in, const int* in_sizes, int n_in,
                              void* d_out, int out_size) {
    const float* x        = (const float*)d_in[0];
    const float* in_proj  = (const float*)d_in[1];
    const float* sck_w    = (const float*)d_in[2];
    const float* sck_b    = (const float*)d_in[3];
    const float* scv_w    = (const float*)d_in[4];
    const float* scv_b    = (const float*)d_in[5];
    const float* mlp_w1   = (const float*)d_in[6];
    const float* mlp_b1   = (const float*)d_in[7];
    const float* mlp_w2   = (const float*)d_in[8];
    const float* mlp_b2   = (const float*)d_in[9];
    const float* mlp_w3   = (const float*)d_in[10];
    const float* mlp_b3   = (const float*)d_in[11];
    const float* log_dec  = (const float*)d_in[12];
    const float* out_proj = (const float*)d_in[13];
    float* out = (float*)d_out;

    const int smem_fft = NFFT * sizeof(float2);   // 128 KB
    cudaFuncSetAttribute(k_fft_h,   cudaFuncAttributeMaxDynamicSharedMemorySize, smem_fft);
    cudaFuncSetAttribute(k_fftconv, cudaFuncAttributeMaxDynamicSharedMemorySize, smem_fft);

    k_twiddle<<<16, 512>>>();
    // qkv: A = in_proj_w (2304 rows -> grid.y 18), B = x (16384 rows -> grid.x 128)
    k_gemm_qkv<<<dim3(128, 18), 256>>>(in_proj, x);
    k_convmul<<<BATCH * DMOD, 256>>>(sck_w, sck_b, scv_w, scv_b);
    k_filter<<<LSEQ / FILT_TL, 768>>>(mlp_w1, mlp_b1, mlp_w2, mlp_b2, mlp_w3, mlp_b3, log_dec);
    k_fft_h<<<DMOD, 1024, smem_fft>>>();
    k_fftconv<<<BATCH * DMOD, 1024, smem_fft>>>();
    // out: A = yg (16384 rows -> grid.y 128), B = out_proj_w (768 rows -> grid.x 6)
    k_gemm_out<<<dim3(6, 128), 256>>>(out, out_proj);
}

// round 5
// speedup vs baseline: 1.1310x; 1.1310x over previous
#include <cuda_runtime.h>
#include <cstdint>

// ---------------- problem constants ----------------
#define BATCH 2
#define LSEQ  8192
#define DMOD  768
#define NFFT  16384          // 2*LSEQ zero-padded FFT size
#define LOGN  14
#define EMB   64

// ---------------- scratch (static device globals; no runtime alloc) ----------------
__device__ float  g_qT[BATCH * DMOD * LSEQ];   // q transposed [b][d][l]
__device__ float  g_kT[BATCH * DMOD * LSEQ];   // k transposed
__device__ float  g_vT[BATCH * DMOD * LSEQ];   // v transposed
__device__ float  g_u [BATCH * DMOD * LSEQ];   // conv(k)*conv(v)
__device__ float  g_h [DMOD * LSEQ];           // hyena filter [d][l]
__device__ float2 g_Hf[DMOD * NFFT];           // filter spectrum (bit-reversed order)
__device__ float  g_yg[BATCH * LSEQ * DMOD];   // gated output [b][l][d]
__device__ float2 g_tw[NFFT / 2];              // twiddle table exp(-2*pi*i*t/N)

// ---------------- twiddle init ----------------
__global__ void k_twiddle() {
    int i = blockIdx.x * blockDim.x + threadIdx.x;
    if (i < NFFT / 2) {
        double ang = -2.0 * 3.14159265358979323846 * (double)i / (double)NFFT;
        g_tw[i] = make_float2((float)cos(ang), (float)sin(ang));
    }
}

// ---------------- tf32 helpers ----------------
__device__ __forceinline__ uint32_t f2tf(float x) {
    uint32_t r;
    asm("cvt.rna.tf32.f32 %0, %1;" : "=r"(r) : "f"(x));
    return r;
}

#define MMA_TF32(c, a, b)                                                     \
    asm volatile(                                                             \
        "mma.sync.aligned.m16n8k8.row.col.f32.tf32.tf32.f32 "                 \
        "{%0,%1,%2,%3},{%4,%5,%6,%7},{%8,%9},{%0,%1,%2,%3};"                  \
        : "+f"(c[0]), "+f"(c[1]), "+f"(c[2]), "+f"(c[3])                      \
        : "r"(a[0]), "r"(a[1]), "r"(a[2]), "r"(a[3]), "r"(b[0]), "r"(b[1]))

// ---------------- tensor-core GEMM (tf32x3): C[i][j] = sum_k A[i,k]*B[j,k] ----------
// Block tile 128x128, BK=16, 8 warps (2 M x 4 N), warp tile 64x32.
// EPI=0: qkv epilogue (A=in_proj rows i=0..2303, B=x rows j=0..16383)
//        -> writes q/k/v transposed [b][d][l].
// EPI=1: out-proj epilogue (A=g_yg rows, B=out_proj_w rows) -> C[i*768+j].
#define BKP 20   // padded K stride
template <int EPI>
__global__ __launch_bounds__(256) void k_gemm_tc(const float* __restrict__ Aarg,
                                                 const float* __restrict__ B,
                                                 float* __restrict__ C) {
    __shared__ uint32_t Ah[128][BKP], Al[128][BKP];
    __shared__ uint32_t Bh[128][BKP], Bl[128][BKP];

    const float* A = (EPI == 1) ? (const float*)g_yg : Aarg;
    const int i0 = blockIdx.y * 128;
    const int j0 = blockIdx.x * 128;
    const int tid = threadIdx.x;
    const int wid = tid >> 5;
    const int lane = tid & 31;
    const int g  = lane >> 2;      // group id 0..7
    const int tg = lane & 3;       // thread-in-group 0..3
    const int wm = wid >> 2;       // 0..1 -> M offset wm*64
    const int wn = wid & 3;        // 0..3 -> N offset wn*32

    float c[4][4][4];
#pragma unroll
    for (int mi = 0; mi < 4; mi++)
#pragma unroll
        for (int ni = 0; ni < 4; ni++)
#pragma unroll
            for (int r = 0; r < 4; r++) c[mi][ni][r] = 0.f;

    for (int kb = 0; kb < 768; kb += 16) {
        // load + split A and B tiles (128x16 each)
#pragma unroll
        for (int it = 0; it < 2; it++) {
            int id = tid + it * 256;          // 0..511
            int r = id >> 2;
            int kq = (id & 3) * 4;
            float4 va = *(const float4*)(A + (size_t)(i0 + r) * 768 + kb + kq);
            uint32_t h0 = f2tf(va.x), h1 = f2tf(va.y), h2 = f2tf(va.z), h3 = f2tf(va.w);
            *(uint4*)&Ah[r][kq] = make_uint4(h0, h1, h2, h3);
            *(uint4*)&Al[r][kq] = make_uint4(f2tf(va.x - __uint_as_float(h0)),
                                             f2tf(va.y - __uint_as_float(h1)),
                                             f2tf(va.z - __uint_as_float(h2)),
                                             f2tf(va.w - __uint_as_float(h3)));
            float4 vb = *(const float4*)(B + (size_t)(j0 + r) * 768 + kb + kq);
            uint32_t g0 = f2tf(vb.x), g1 = f2tf(vb.y), g2 = f2tf(vb.z), g3 = f2tf(vb.w);
            *(uint4*)&Bh[r][kq] = make_uint4(g0, g1, g2, g3);
            *(uint4*)&Bl[r][kq] = make_uint4(f2tf(vb.x - __uint_as_float(g0)),
                                             f2tf(vb.y - __uint_as_float(g1)),
                                             f2tf(vb.z - __uint_as_float(g2)),
                                             f2tf(vb.w - __uint_as_float(g3)));
        }
        __syncthreads();

#pragma unroll
        for (int ks = 0; ks < 16; ks += 8) {
            uint32_t ah[4][4], al[4][4], bh[4][2], bl[4][2];
#pragma unroll
            for (int mi = 0; mi < 4; mi++) {
                int m = wm * 64 + mi * 16;
                ah[mi][0] = Ah[m + g][ks + tg];
                ah[mi][1] = Ah[m + g + 8][ks + tg];
                ah[mi][2] = Ah[m + g][ks + tg + 4];
                ah[mi][3] = Ah[m + g + 8][ks + tg + 4];
                al[mi][0] = Al[m + g][ks + tg];
                al[mi][1] = Al[m + g + 8][ks + tg];
                al[mi][2] = Al[m + g][ks + tg + 4];
                al[mi][3] = Al[m + g + 8][ks + tg + 4];
            }
#pragma unroll
            for (int ni = 0; ni < 4; ni++) {
                int n = wn * 32 + ni * 8;
                bh[ni][0] = Bh[n + g][ks + tg];
                bh[ni][1] = Bh[n + g][ks + tg + 4];
                bl[ni][0] = Bl[n + g][ks + tg];
                bl[ni][1] = Bl[n + g][ks + tg + 4];
            }
#pragma unroll
            for (int mi = 0; mi < 4; mi++)
#pragma unroll
                for (int ni = 0; ni < 4; ni++) {
                    MMA_TF32(c[mi][ni], ah[mi], bh[ni]);
                    MMA_TF32(c[mi][ni], al[mi], bh[ni]);
                    MMA_TF32(c[mi][ni], ah[mi], bl[ni]);
                }
        }
        __syncthreads();
    }

    // epilogue
#pragma unroll
    for (int mi = 0; mi < 4; mi++) {
#pragma unroll
        for (int ni = 0; ni < 4; ni++) {
            int rm0 = i0 + wm * 64 + mi * 16 + g;   // A-row for c0,c1
            int rm1 = rm0 + 8;                      // A-row for c2,c3
            int cn  = j0 + wn * 32 + ni * 8 + 2 * tg;  // B-row (even)
            if (EPI == 0) {
                int part0 = rm0 / DMOD, dch0 = rm0 - part0 * DMOD;
                int part1 = rm1 / DMOD, dch1 = rm1 - part1 * DMOD;
                float* t0 = (part0 == 0) ? g_qT : (part0 == 1 ? g_kT : g_vT);
                float* t1 = (part1 == 0) ? g_qT : (part1 == 1 ? g_kT : g_vT);
                int bb = cn >> 13;
                int l  = cn & (LSEQ - 1);
                *(float2*)(t0 + ((size_t)bb * DMOD + dch0) * LSEQ + l) =
                    make_float2(c[mi][ni][0], c[mi][ni][1]);
                *(float2*)(t1 + ((size_t)bb * DMOD + dch1) * LSEQ + l) =
                    make_float2(c[mi][ni][2], c[mi][ni][3]);
            } else {
                *(float2*)(C + (size_t)rm0 * DMOD + cn) =
                    make_float2(c[mi][ni][0], c[mi][ni][1]);
                *(float2*)(C + (size_t)rm1 * DMOD + cn) =
                    make_float2(c[mi][ni][2], c[mi][ni][3]);
            }
        }
    }
}

// ---------------- depthwise causal conv (k=3) + elementwise multiply ----------------
__global__ void k_convmul(const float* __restrict__ skw, const float* __restrict__ skb,
                          const float* __restrict__ svw, const float* __restrict__ svb) {
    int bd = blockIdx.x;                 // 0..BATCH*DMOD-1
    int d  = bd % DMOD;
    const float* ki = g_kT + (size_t)bd * LSEQ;
    const float* vi = g_vT + (size_t)bd * LSEQ;
    float* uo = g_u + (size_t)bd * LSEQ;
    float kw0 = skw[d * 3], kw1 = skw[d * 3 + 1], kw2 = skw[d * 3 + 2], kb = skb[d];
    float vw0 = svw[d * 3], vw1 = svw[d * 3 + 1], vw2 = svw[d * 3 + 2], vb = svb[d];
    for (int l = threadIdx.x; l < LSEQ; l += blockDim.x) {
        float k2 = ki[l];
        float k1 = (l >= 1) ? ki[l - 1] : 0.f;
        float k0 = (l >= 2) ? ki[l - 2] : 0.f;
        float v2 = vi[l];
        float v1 = (l >= 1) ? vi[l - 1] : 0.f;
        float v0 = (l >= 2) ? vi[l - 2] : 0.f;
        float kc = kw0 * k0 + kw1 * k1 + kw2 * k2 + kb;
        float vc = vw0 * v0 + vw1 * v1 + vw2 * v2 + vb;
        uo[l] = kc * vc;
    }
}

// ---------------- hyena filter MLP + decay (smem weights reused, expf recurrence) ---
#define FTL 32
__global__ __launch_bounds__(256) void k_filter(const float* __restrict__ w1, const float* __restrict__ b1,
                                                const float* __restrict__ w2, const float* __restrict__ b2,
                                                const float* __restrict__ w3, const float* __restrict__ b3,
                                                const float* __restrict__ ld) {
    __shared__ float ws [EMB][EMB + 1];   // staged w1, then w2 (reused)
    __shared__ float pe [FTL][EMB + 1];
    __shared__ float h1s[FTL][EMB + 1];
    __shared__ float h2s[FTL][EMB + 1];
    const int l0 = blockIdx.x * FTL;
    const int tid = threadIdx.x;
    const float TWO_PI = 6.2831853071795864769f;
    const float inv = 1.0f / (float)(LSEQ - 1);

    // stage w1 + positional encoding
    for (int idx = tid; idx < EMB * EMB; idx += 256)
        ws[idx >> 6][idx & 63] = w1[idx];
    for (int idx = tid; idx < FTL * EMB; idx += 256) {
        int li = idx >> 6, e = idx & 63;
        float t = (float)(l0 + li) * inv;
        pe[li][e] = (e < 32) ? sinf(t * TWO_PI * (float)(e + 1))
                             : cosf(t * TWO_PI * (float)(e - 31));
    }
    __syncthreads();
    // layer 1
    for (int idx = tid; idx < FTL * EMB; idx += 256) {
        int li = idx >> 6, e = idx & 63;
        float s = b1[e];
#pragma unroll 16
        for (int cc = 0; cc < EMB; cc++) s += pe[li][cc] * ws[e][cc];
        h1s[li][e] = s / (1.f + __expf(-s));
    }
    __syncthreads();
    // stage w2 into the same buffer
    for (int idx = tid; idx < EMB * EMB; idx += 256)
        ws[idx >> 6][idx & 63] = w2[idx];
    __syncthreads();
    // layer 2
    for (int idx = tid; idx < FTL * EMB; idx += 256) {
        int li = idx >> 6, e = idx & 63;
        float s = b2[e];
#pragma unroll 16
        for (int cc = 0; cc < EMB; cc++) s += h1s[li][cc] * ws[e][cc];
        h2s[li][e] = s / (1.f + __expf(-s));
    }
    __syncthreads();
    // layer 3 + decay: each thread handles channels d = tid, tid+256, tid+512
    for (int d = tid; d < DMOD; d += 256) {
        float acc[FTL];
#pragma unroll
        for (int li = 0; li < FTL; li++) acc[li] = 0.f;
        const float* w3r = w3 + d * EMB;
#pragma unroll 8
        for (int e = 0; e < EMB; e++) {
            float wv = w3r[e];
#pragma unroll
            for (int li = 0; li < FTL; li++) acc[li] += h2s[li][e] * wv;
        }
        float b3d = b3[d];
        float a = fabsf(ld[d]);
        float dec  = __expf(-a * (float)l0);
        float step = __expf(-a);
        float* outp = g_h + (size_t)d * LSEQ + l0;
#pragma unroll
        for (int li = 0; li < FTL; li++) {
            outp[li] = (acc[li] + b3d) * dec;
            dec *= step;
        }
    }
}

// ---------------- FFT helpers (radix-2, in shared memory) ----------------
__device__ __forceinline__ void fft_fwd(float2* sm, int tid, int nthr) {
    for (int s = 0; s < LOGN; s++) {
        int mlog = LOGN - 1 - s;
        int m = 1 << mlog;
#pragma unroll 4
        for (int idx = tid; idx < NFFT / 2; idx += nthr) {
            int j  = idx & (m - 1);
            int i0 = ((idx >> mlog) << (mlog + 1)) + j;
            int i1 = i0 + m;
            float2 a = sm[i0], b = sm[i1];
            float2 w = g_tw[j << s];
            float2 su = make_float2(a.x + b.x, a.y + b.y);
            float2 df = make_float2(a.x - b.x, a.y - b.y);
            sm[i0] = su;
            sm[i1] = make_float2(df.x * w.x - df.y * w.y, df.x * w.y + df.y * w.x);
        }
        __syncthreads();
    }
}

__device__ __forceinline__ void fft_inv(float2* sm, int tid, int nthr) {
    for (int s = 0; s < LOGN; s++) {
        int m = 1 << s;
#pragma unroll 4
        for (int idx = tid; idx < NFFT / 2; idx += nthr) {
            int j  = idx & (m - 1);
            int i0 = ((idx >> s) << (s + 1)) + j;
            int i1 = i0 + m;
            float2 a = sm[i0], b = sm[i1];
            float2 w = g_tw[j << (LOGN - 1 - s)];
            float2 t = make_float2(b.x * w.x + b.y * w.y, b.y * w.x - b.x * w.y);
            sm[i0] = make_float2(a.x + t.x, a.y + t.y);
            sm[i1] = make_float2(a.x - t.x, a.y - t.y);
        }
        __syncthreads();
    }
}

// ---------------- filter spectrum ----------------
__global__ void k_fft_h() {
    extern __shared__ float2 sm[];
    const int d = blockIdx.x;
    const int tid = threadIdx.x, nthr = blockDim.x;
    const float* src = g_h + (size_t)d * LSEQ;
    for (int i = tid; i < LSEQ; i += nthr) sm[i] = make_float2(src[i], 0.f);
    for (int i = LSEQ + tid; i < NFFT; i += nthr) sm[i] = make_float2(0.f, 0.f);
    __syncthreads();
    fft_fwd(sm, tid, nthr);
    float2* dst = g_Hf + (size_t)d * NFFT;
    for (int i = tid; i < NFFT; i += nthr) dst[i] = sm[i];
}

// ---------------- fused: FFT(u) * Hf -> IFFT -> silu(q) gate -> yg [b][l][d] ------------
__global__ void k_fftconv() {
    extern __shared__ float2 sm[];
    const int bd = blockIdx.x;           // b*DMOD + d
    const int b = bd / DMOD;
    const int d = bd - b * DMOD;
    const int tid = threadIdx.x, nthr = blockDim.x;
    const float* src = g_u + (size_t)bd * LSEQ;
    for (int i = tid; i < LSEQ; i += nthr) sm[i] = make_float2(src[i], 0.f);
    for (int i = LSEQ + tid; i < NFFT; i += nthr) sm[i] = make_float2(0.f, 0.f);
    __syncthreads();
    fft_fwd(sm, tid, nthr);
    const float2* H = g_Hf + (size_t)d * NFFT;
    const float scale = 1.0f / (float)NFFT;
    for (int i = tid; i < NFFT; i += nthr) {
        float2 z = sm[i];
        float2 h = H[i];
        sm[i] = make_float2((z.x * h.x - z.y * h.y) * scale,
                            (z.x * h.y + z.y * h.x) * scale);
    }
    __syncthreads();
    fft_inv(sm, tid, nthr);
    const float* q = g_qT + (size_t)bd * LSEQ;
    for (int l = tid; l < LSEQ; l += nthr) {
        float y = sm[l].x;
        float qq = q[l];
        float gg = qq / (1.f + __expf(-qq));
        g_yg[((size_t)b * LSEQ + l) * DMOD + d] = gg * y;
    }
}

// ---------------- launch ----------------
extern "C" void kernel_launch(void* const* d_in, const int* in_sizes, int n_in,
                              void* d_out, int out_size) {
    const float* x        = (const float*)d_in[0];
    const float* in_proj  = (const float*)d_in[1];
    const float* sck_w    = (const float*)d_in[2];
    const float* sck_b    = (const float*)d_in[3];
    const float* scv_w    = (const float*)d_in[4];
    const float* scv_b    = (const float*)d_in[5];
    const float* mlp_w1   = (const float*)d_in[6];
    const float* mlp_b1   = (const float*)d_in[7];
    const float* mlp_w2   = (const float*)d_in[8];
    const float* mlp_b2   = (const float*)d_in[9];
    const float* mlp_w3   = (const float*)d_in[10];
    const float* mlp_b3   = (const float*)d_in[11];
    const float* log_dec  = (const float*)d_in[12];
    const float* out_proj = (const float*)d_in[13];
    float* out = (float*)d_out;

    const int smem_fft = NFFT * sizeof(float2);   // 128 KB
    cudaFuncSetAttribute(k_fft_h,   cudaFuncAttributeMaxDynamicSharedMemorySize, smem_fft);
    cudaFuncSetAttribute(k_fftconv, cudaFuncAttributeMaxDynamicSharedMemorySize, smem_fft);

    k_twiddle<<<16, 512>>>();
    // qkv: A = in_proj_w (2304 rows -> grid.y 18), B = x (16384 rows -> grid.x 128)
    k_gemm_tc<0><<<dim3(128, 18), 256>>>(in_proj, x, nullptr);
    k_convmul<<<BATCH * DMOD, 256>>>(sck_w, sck_b, scv_w, scv_b);
    k_filter<<<LSEQ / FTL, 256>>>(mlp_w1, mlp_b1, mlp_w2, mlp_b2, mlp_w3, mlp_b3, log_dec);
    k_fft_h<<<DMOD, 1024, smem_fft>>>();
    k_fftconv<<<BATCH * DMOD, 1024, smem_fft>>>();
    // out: A = g_yg (16384 rows -> grid.y 128), B = out_proj_w (768 rows -> grid.x 6)
    k_gemm_tc<1><<<dim3(6, 128), 256>>>(nullptr, out_proj, out);
}

// round 6
// speedup vs baseline: 1.5182x; 1.3424x over previous
#include <cuda_runtime.h>
#include <cstdint>

// ---------------- problem constants ----------------
#define BATCH 2
#define LSEQ  8192
#define DMOD  768
#define NFFT  16384          // 2*LSEQ zero-padded FFT size
#define LOGN  14
#define EMB   64

// ---------------- scratch (static device globals; no runtime alloc) ----------------
__device__ float  g_qT[BATCH * DMOD * LSEQ];   // q transposed [b][d][l]
__device__ float  g_kT[BATCH * DMOD * LSEQ];   // k transposed
__device__ float  g_vT[BATCH * DMOD * LSEQ];   // v transposed
__device__ float  g_h [DMOD * LSEQ];           // hyena filter [d][l]
__device__ float2 g_Hf[DMOD * NFFT];           // filter spectrum, bitrev-indexed: [d][p] = H_d(brev(p))
__device__ float  g_yg[BATCH * LSEQ * DMOD];   // gated output [b][l][d]
__device__ float2 g_tw[NFFT / 2];              // twiddle table exp(-2*pi*i*t/N)

// ---------------- twiddle init ----------------
__global__ void k_twiddle() {
    int i = blockIdx.x * blockDim.x + threadIdx.x;
    if (i < NFFT / 2) {
        double ang = -2.0 * 3.14159265358979323846 * (double)i / (double)NFFT;
        g_tw[i] = make_float2((float)cos(ang), (float)sin(ang));
    }
}

// ---------------- tf32 helpers ----------------
__device__ __forceinline__ uint32_t f2tf(float x) {
    uint32_t r;
    asm("cvt.rna.tf32.f32 %0, %1;" : "=r"(r) : "f"(x));
    return r;
}

#define MMA_TF32(c, a, b)                                                     \
    asm volatile(                                                             \
        "mma.sync.aligned.m16n8k8.row.col.f32.tf32.tf32.f32 "                 \
        "{%0,%1,%2,%3},{%4,%5,%6,%7},{%8,%9},{%0,%1,%2,%3};"                  \
        : "+f"(c[0]), "+f"(c[1]), "+f"(c[2]), "+f"(c[3])                      \
        : "r"(a[0]), "r"(a[1]), "r"(a[2]), "r"(a[3]), "r"(b[0]), "r"(b[1]))

// ---------------- tensor-core GEMM (tf32x3) with register-prefetch pipeline ---------
// C[i][j] = sum_k A[i,k]*B[j,k]; 128x128 tile, BK=16, 8 warps, warp tile 64x32.
#define BKP 20
template <int EPI>
__global__ __launch_bounds__(256) void k_gemm_tc(const float* __restrict__ Aarg,
                                                 const float* __restrict__ B,
                                                 float* __restrict__ C) {
    __shared__ uint32_t Ah[128][BKP], Al[128][BKP];
    __shared__ uint32_t Bh[128][BKP], Bl[128][BKP];

    const float* A = (EPI == 1) ? (const float*)g_yg : Aarg;
    const int i0 = blockIdx.y * 128;
    const int j0 = blockIdx.x * 128;
    const int tid = threadIdx.x;
    const int wid = tid >> 5;
    const int lane = tid & 31;
    const int g  = lane >> 2;
    const int tg = lane & 3;
    const int wm = wid >> 2;
    const int wn = wid & 3;

    // load mapping: rows r0 and r0+64, quad kq0
    const int r0 = tid >> 2;
    const int kq0 = (tid & 3) * 4;
    const float* Ar0 = A + (size_t)(i0 + r0) * 768 + kq0;
    const float* Ar1 = A + (size_t)(i0 + r0 + 64) * 768 + kq0;
    const float* Br0 = B + (size_t)(j0 + r0) * 768 + kq0;
    const float* Br1 = B + (size_t)(j0 + r0 + 64) * 768 + kq0;

    float c[4][4][4];
#pragma unroll
    for (int mi = 0; mi < 4; mi++)
#pragma unroll
        for (int ni = 0; ni < 4; ni++)
#pragma unroll
            for (int r = 0; r < 4; r++) c[mi][ni][r] = 0.f;

    // prologue: load first tile into regs
    float4 va0 = *(const float4*)(Ar0);
    float4 va1 = *(const float4*)(Ar1);
    float4 vb0 = *(const float4*)(Br0);
    float4 vb1 = *(const float4*)(Br1);

    for (int kb = 0; kb < 768; kb += 16) {
        // split + store current regs to smem
        {
            uint32_t h0 = f2tf(va0.x), h1 = f2tf(va0.y), h2 = f2tf(va0.z), h3 = f2tf(va0.w);
            *(uint4*)&Ah[r0][kq0] = make_uint4(h0, h1, h2, h3);
            *(uint4*)&Al[r0][kq0] = make_uint4(f2tf(va0.x - __uint_as_float(h0)),
                                               f2tf(va0.y - __uint_as_float(h1)),
                                               f2tf(va0.z - __uint_as_float(h2)),
                                               f2tf(va0.w - __uint_as_float(h3)));
            uint32_t i0h = f2tf(va1.x), i1h = f2tf(va1.y), i2h = f2tf(va1.z), i3h = f2tf(va1.w);
            *(uint4*)&Ah[r0 + 64][kq0] = make_uint4(i0h, i1h, i2h, i3h);
            *(uint4*)&Al[r0 + 64][kq0] = make_uint4(f2tf(va1.x - __uint_as_float(i0h)),
                                                    f2tf(va1.y - __uint_as_float(i1h)),
                                                    f2tf(va1.z - __uint_as_float(i2h)),
                                                    f2tf(va1.w - __uint_as_float(i3h)));
            uint32_t g0 = f2tf(vb0.x), g1 = f2tf(vb0.y), g2 = f2tf(vb0.z), g3 = f2tf(vb0.w);
            *(uint4*)&Bh[r0][kq0] = make_uint4(g0, g1, g2, g3);
            *(uint4*)&Bl[r0][kq0] = make_uint4(f2tf(vb0.x - __uint_as_float(g0)),
                                               f2tf(vb0.y - __uint_as_float(g1)),
                                               f2tf(vb0.z - __uint_as_float(g2)),
                                               f2tf(vb0.w - __uint_as_float(g3)));
            uint32_t j0h = f2tf(vb1.x), j1h = f2tf(vb1.y), j2h = f2tf(vb1.z), j3h = f2tf(vb1.w);
            *(uint4*)&Bh[r0 + 64][kq0] = make_uint4(j0h, j1h, j2h, j3h);
            *(uint4*)&Bl[r0 + 64][kq0] = make_uint4(f2tf(vb1.x - __uint_as_float(j0h)),
                                                    f2tf(vb1.y - __uint_as_float(j1h)),
                                                    f2tf(vb1.z - __uint_as_float(j2h)),
                                                    f2tf(vb1.w - __uint_as_float(j3h)));
        }
        __syncthreads();

        // prefetch next tile (loads overlap with compute below)
        if (kb + 16 < 768) {
            va0 = *(const float4*)(Ar0 + kb + 16);
            va1 = *(const float4*)(Ar1 + kb + 16);
            vb0 = *(const float4*)(Br0 + kb + 16);
            vb1 = *(const float4*)(Br1 + kb + 16);
        }

#pragma unroll
        for (int ks = 0; ks < 16; ks += 8) {
            uint32_t ah[4][4], al[4][4], bh[4][2], bl[4][2];
#pragma unroll
            for (int mi = 0; mi < 4; mi++) {
                int m = wm * 64 + mi * 16;
                ah[mi][0] = Ah[m + g][ks + tg];
                ah[mi][1] = Ah[m + g + 8][ks + tg];
                ah[mi][2] = Ah[m + g][ks + tg + 4];
                ah[mi][3] = Ah[m + g + 8][ks + tg + 4];
                al[mi][0] = Al[m + g][ks + tg];
                al[mi][1] = Al[m + g + 8][ks + tg];
                al[mi][2] = Al[m + g][ks + tg + 4];
                al[mi][3] = Al[m + g + 8][ks + tg + 4];
            }
#pragma unroll
            for (int ni = 0; ni < 4; ni++) {
                int n = wn * 32 + ni * 8;
                bh[ni][0] = Bh[n + g][ks + tg];
                bh[ni][1] = Bh[n + g][ks + tg + 4];
                bl[ni][0] = Bl[n + g][ks + tg];
                bl[ni][1] = Bl[n + g][ks + tg + 4];
            }
#pragma unroll
            for (int mi = 0; mi < 4; mi++)
#pragma unroll
                for (int ni = 0; ni < 4; ni++) {
                    MMA_TF32(c[mi][ni], ah[mi], bh[ni]);
                    MMA_TF32(c[mi][ni], al[mi], bh[ni]);
                    MMA_TF32(c[mi][ni], ah[mi], bl[ni]);
                }
        }
        __syncthreads();
    }

    // epilogue
#pragma unroll
    for (int mi = 0; mi < 4; mi++) {
#pragma unroll
        for (int ni = 0; ni < 4; ni++) {
            int rm0 = i0 + wm * 64 + mi * 16 + g;
            int rm1 = rm0 + 8;
            int cn  = j0 + wn * 32 + ni * 8 + 2 * tg;
            if (EPI == 0) {
                int part0 = rm0 / DMOD, dch0 = rm0 - part0 * DMOD;
                int part1 = rm1 / DMOD, dch1 = rm1 - part1 * DMOD;
                float* t0 = (part0 == 0) ? g_qT : (part0 == 1 ? g_kT : g_vT);
                float* t1 = (part1 == 0) ? g_qT : (part1 == 1 ? g_kT : g_vT);
                int bb = cn >> 13;
                int l  = cn & (LSEQ - 1);
                *(float2*)(t0 + ((size_t)bb * DMOD + dch0) * LSEQ + l) =
                    make_float2(c[mi][ni][0], c[mi][ni][1]);
                *(float2*)(t1 + ((size_t)bb * DMOD + dch1) * LSEQ + l) =
                    make_float2(c[mi][ni][2], c[mi][ni][3]);
            } else {
                *(float2*)(C + (size_t)rm0 * DMOD + cn) =
                    make_float2(c[mi][ni][0], c[mi][ni][1]);
                *(float2*)(C + (size_t)rm1 * DMOD + cn) =
                    make_float2(c[mi][ni][2], c[mi][ni][3]);
            }
        }
    }
}

// ---------------- hyena filter MLP + decay ----------------
#define FTL 32
__global__ __launch_bounds__(256) void k_filter(const float* __restrict__ w1, const float* __restrict__ b1,
                                                const float* __restrict__ w2, const float* __restrict__ b2,
                                                const float* __restrict__ w3, const float* __restrict__ b3,
                                                const float* __restrict__ ld) {
    __shared__ float ws [EMB][EMB + 1];
    __shared__ float pe [FTL][EMB + 1];
    __shared__ float h1s[FTL][EMB + 1];
    __shared__ float h2s[FTL][EMB + 1];
    const int l0 = blockIdx.x * FTL;
    const int tid = threadIdx.x;
    const float TWO_PI = 6.2831853071795864769f;
    const float inv = 1.0f / (float)(LSEQ - 1);

    for (int idx = tid; idx < EMB * EMB; idx += 256)
        ws[idx >> 6][idx & 63] = w1[idx];
    for (int idx = tid; idx < FTL * EMB; idx += 256) {
        int li = idx >> 6, e = idx & 63;
        float t = (float)(l0 + li) * inv;
        pe[li][e] = (e < 32) ? sinf(t * TWO_PI * (float)(e + 1))
                             : cosf(t * TWO_PI * (float)(e - 31));
    }
    __syncthreads();
    for (int idx = tid; idx < FTL * EMB; idx += 256) {
        int li = idx >> 6, e = idx & 63;
        float s = b1[e];
#pragma unroll 16
        for (int cc = 0; cc < EMB; cc++) s += pe[li][cc] * ws[e][cc];
        h1s[li][e] = s / (1.f + __expf(-s));
    }
    __syncthreads();
    for (int idx = tid; idx < EMB * EMB; idx += 256)
        ws[idx >> 6][idx & 63] = w2[idx];
    __syncthreads();
    for (int idx = tid; idx < FTL * EMB; idx += 256) {
        int li = idx >> 6, e = idx & 63;
        float s = b2[e];
#pragma unroll 16
        for (int cc = 0; cc < EMB; cc++) s += h1s[li][cc] * ws[e][cc];
        h2s[li][e] = s / (1.f + __expf(-s));
    }
    __syncthreads();
    for (int d = tid; d < DMOD; d += 256) {
        float acc[FTL];
#pragma unroll
        for (int li = 0; li < FTL; li++) acc[li] = 0.f;
        const float* w3r = w3 + d * EMB;
#pragma unroll 8
        for (int e = 0; e < EMB; e++) {
            float wv = w3r[e];
#pragma unroll
            for (int li = 0; li < FTL; li++) acc[li] += h2s[li][e] * wv;
        }
        float b3d = b3[d];
        float a = fabsf(ld[d]);
        float dec  = __expf(-a * (float)l0);
        float step = __expf(-a);
        float* outp = g_h + (size_t)d * LSEQ + l0;
#pragma unroll
        for (int li = 0; li < FTL; li++) {
            outp[li] = (acc[li] + b3d) * dec;
            dec *= step;
        }
    }
}

// ---------------- FFT stage helpers (radix-2, in shared memory) ----------------
// Forward DIF stages s = 1..LOGN-1 (stage 0 folded into load).
__device__ __forceinline__ void fft_fwd_13(float2* sm, int tid, int nthr) {
    for (int s = 1; s < LOGN; s++) {
        int mlog = LOGN - 1 - s;
        int m = 1 << mlog;
#pragma unroll 4
        for (int idx = tid; idx < NFFT / 2; idx += nthr) {
            int j  = idx & (m - 1);
            int i0 = ((idx >> mlog) << (mlog + 1)) + j;
            int i1 = i0 + m;
            float2 a = sm[i0], b = sm[i1];
            float2 w = g_tw[j << s];
            float2 su = make_float2(a.x + b.x, a.y + b.y);
            float2 df = make_float2(a.x - b.x, a.y - b.y);
            sm[i0] = su;
            sm[i1] = make_float2(df.x * w.x - df.y * w.y, df.x * w.y + df.y * w.x);
        }
        __syncthreads();
    }
}

// Inverse DIT, bit-reversed input -> natural output (conjugate twiddles, no scale).
__device__ __forceinline__ void fft_inv(float2* sm, int tid, int nthr) {
    for (int s = 0; s < LOGN; s++) {
        int m = 1 << s;
#pragma unroll 4
        for (int idx = tid; idx < NFFT / 2; idx += nthr) {
            int j  = idx & (m - 1);
            int i0 = ((idx >> s) << (s + 1)) + j;
            int i1 = i0 + m;
            float2 a = sm[i0], b = sm[i1];
            float2 w = g_tw[j << (LOGN - 1 - s)];
            float2 t = make_float2(b.x * w.x + b.y * w.y, b.y * w.x - b.x * w.y);
            sm[i0] = make_float2(a.x + t.x, a.y + t.y);
            sm[i1] = make_float2(a.x - t.x, a.y - t.y);
        }
        __syncthreads();
    }
}

__device__ __forceinline__ int brev14(int x) {
    return (int)(__brev((unsigned)x) >> (32 - LOGN));
}

// ---------------- filter spectrum: two-for-one (channels 2c, 2c+1) ----------------
// Output bitrev-indexed: g_Hf[d][p] = H_d(brev(p)).
__global__ void k_fft_h() {
    extern __shared__ float2 sm[];
    const int c = blockIdx.x;
    const int d0 = 2 * c, d1 = 2 * c + 1;
    const int tid = threadIdx.x, nthr = blockDim.x;
    const float* s0 = g_h + (size_t)d0 * LSEQ;
    const float* s1 = g_h + (size_t)d1 * LSEQ;
    // load pair + fold DIF stage 0 (upper half is zero padding)
    for (int i = tid; i < LSEQ; i += nthr) {
        float2 z = make_float2(s0[i], s1[i]);
        float2 w = g_tw[i];
        sm[i] = z;
        sm[i + LSEQ] = make_float2(z.x * w.x - z.y * w.y, z.x * w.y + z.y * w.x);
    }
    __syncthreads();
    fft_fwd_13(sm, tid, nthr);
    // unpack Ha/Hb and store (bitrev-indexed layout)
    float2* Ha = g_Hf + (size_t)d0 * NFFT;
    float2* Hb = g_Hf + (size_t)d1 * NFFT;
    for (int pp = tid; pp <= NFFT / 2; pp += nthr) {
        int p = (pp == NFFT / 2) ? 1 : 2 * pp;
        int k = brev14(p);
        int q = brev14((NFFT - k) & (NFFT - 1));
        float2 z1 = sm[p];
        float2 z2 = sm[q];
        float2 ha = make_float2(0.5f * (z1.x + z2.x), 0.5f * (z1.y - z2.y));
        float2 hb = make_float2(0.5f * (z1.y + z2.y), 0.5f * (z2.x - z1.x));
        Ha[p] = ha;
        Hb[p] = hb;
        Ha[q] = make_float2(ha.x, -ha.y);
        Hb[q] = make_float2(hb.x, -hb.y);
    }
}

// ---------- fused: dwconv(k)*dwconv(v) -> FFT pair -> xH -> IFFT -> gate -> yg ----------
__global__ void k_fftconv(const float* __restrict__ skw, const float* __restrict__ skb,
                          const float* __restrict__ svw, const float* __restrict__ svb) {
    extern __shared__ float2 sm[];
    const int bc = blockIdx.x;               // b*(DMOD/2) + c
    const int b = bc / (DMOD / 2);
    const int c = bc - b * (DMOD / 2);
    const int d0 = 2 * c, d1 = 2 * c + 1;
    const int tid = threadIdx.x, nthr = blockDim.x;

    const float* k0 = g_kT + ((size_t)b * DMOD + d0) * LSEQ;
    const float* k1 = g_kT + ((size_t)b * DMOD + d1) * LSEQ;
    const float* v0 = g_vT + ((size_t)b * DMOD + d0) * LSEQ;
    const float* v1 = g_vT + ((size_t)b * DMOD + d1) * LSEQ;

    // conv weights (broadcast loads)
    float kw00 = skw[d0 * 3], kw01 = skw[d0 * 3 + 1], kw02 = skw[d0 * 3 + 2], kb0 = skb[d0];
    float vw00 = svw[d0 * 3], vw01 = svw[d0 * 3 + 1], vw02 = svw[d0 * 3 + 2], vb0 = svb[d0];
    float kw10 = skw[d1 * 3], kw11 = skw[d1 * 3 + 1], kw12 = skw[d1 * 3 + 2], kb1 = skb[d1];
    float vw10 = svw[d1 * 3], vw11 = svw[d1 * 3 + 1], vw12 = svw[d1 * 3 + 2], vb1 = svb[d1];

    // load + depthwise conv + pack pair + fold DIF stage 0
    for (int l = tid; l < LSEQ; l += nthr) {
        float ka2 = k0[l];
        float ka1 = (l >= 1) ? k0[l - 1] : 0.f;
        float ka0 = (l >= 2) ? k0[l - 2] : 0.f;
        float va2 = v0[l];
        float va1 = (l >= 1) ? v0[l - 1] : 0.f;
        float va0 = (l >= 2) ? v0[l - 2] : 0.f;
        float u0 = (kw00 * ka0 + kw01 * ka1 + kw02 * ka2 + kb0) *
                   (vw00 * va0 + vw01 * va1 + vw02 * va2 + vb0);
        float kb2_ = k1[l];
        float kb1_ = (l >= 1) ? k1[l - 1] : 0.f;
        float kb0_ = (l >= 2) ? k1[l - 2] : 0.f;
        float vb2_ = v1[l];
        float vb1_ = (l >= 1) ? v1[l - 1] : 0.f;
        float vb0_ = (l >= 2) ? v1[l - 2] : 0.f;
        float u1 = (kw10 * kb0_ + kw11 * kb1_ + kw12 * kb2_ + kb1) *
                   (vw10 * vb0_ + vw11 * vb1_ + vw12 * vb2_ + vb1);
        float2 z = make_float2(u0, u1);
        float2 w = g_tw[l];
        sm[l] = z;
        sm[l + LSEQ] = make_float2(z.x * w.x - z.y * w.y, z.x * w.y + z.y * w.x);
    }
    __syncthreads();
    fft_fwd_13(sm, tid, nthr);

    // spectral: unpack pair, multiply by H (bitrev-indexed, coalesced), repack
    const float2* Ha = g_Hf + (size_t)d0 * NFFT;
    const float2* Hb = g_Hf + (size_t)d1 * NFFT;
    const float hscale = 0.5f / (float)NFFT;
    for (int pp = tid; pp <= NFFT / 2; pp += nthr) {
        int p = (pp == NFFT / 2) ? 1 : 2 * pp;
        int k = brev14(p);
        int q = brev14((NFFT - k) & (NFFT - 1));
        float2 z1 = sm[p];
        float2 z2 = sm[q];
        float2 za = make_float2(hscale * (z1.x + z2.x), hscale * (z1.y - z2.y));
        float2 zb = make_float2(hscale * (z1.y + z2.y), hscale * (z2.x - z1.x));
        float2 ha = Ha[p];
        float2 hb = Hb[p];
        float2 ya = make_float2(za.x * ha.x - za.y * ha.y, za.x * ha.y + za.y * ha.x);
        float2 yb = make_float2(zb.x * hb.x - zb.y * hb.y, zb.x * hb.y + zb.y * hb.x);
        sm[p] = make_float2(ya.x - yb.y, ya.y + yb.x);           // W(k) = Ya + i*Yb
        sm[q] = make_float2(ya.x + yb.y, yb.x - ya.y);           // W(N-k) = conj(Ya)+i*conj(Yb)
    }
    __syncthreads();
    fft_inv(sm, tid, nthr);

    // gate with silu(q) and write [b][l][d] (both channels packed as float2)
    const float* q0 = g_qT + ((size_t)b * DMOD + d0) * LSEQ;
    const float* q1 = g_qT + ((size_t)b * DMOD + d1) * LSEQ;
    for (int l = tid; l < LSEQ; l += nthr) {
        float2 y = sm[l];
        float qa = q0[l];
        float qb = q1[l];
        float ga = qa / (1.f + __expf(-qa));
        float gb = qb / (1.f + __expf(-qb));
        *(float2*)&g_yg[((size_t)b * LSEQ + l) * DMOD + d0] = make_float2(ga * y.x, gb * y.y);
    }
}

// ---------------- launch ----------------
extern "C" void kernel_launch(void* const* d_in, const int* in_sizes, int n_in,
                              void* d_out, int out_size) {
    const float* x        = (const float*)d_in[0];
    const float* in_proj  = (const float*)d_in[1];
    const float* sck_w    = (const float*)d_in[2];
    const float* sck_b    = (const float*)d_in[3];
    const float* scv_w    = (const float*)d_in[4];
    const float* scv_b    = (const float*)d_in[5];
    const float* mlp_w1   = (const float*)d_in[6];
    const float* mlp_b1   = (const float*)d_in[7];
    const float* mlp_w2   = (const float*)d_in[8];
    const float* mlp_b2   = (const float*)d_in[9];
    const float* mlp_w3   = (const float*)d_in[10];
    const float* mlp_b3   = (const float*)d_in[11];
    const float* log_dec  = (const float*)d_in[12];
    const float* out_proj = (const float*)d_in[13];
    float* out = (float*)d_out;

    const int smem_fft = NFFT * sizeof(float2);   // 128 KB
    cudaFuncSetAttribute(k_fft_h,   cudaFuncAttributeMaxDynamicSharedMemorySize, smem_fft);
    cudaFuncSetAttribute(k_fftconv, cudaFuncAttributeMaxDynamicSharedMemorySize, smem_fft);

    k_twiddle<<<16, 512>>>();
    k_gemm_tc<0><<<dim3(128, 18), 256>>>(in_proj, x, nullptr);
    k_filter<<<LSEQ / FTL, 256>>>(mlp_w1, mlp_b1, mlp_w2, mlp_b2, mlp_w3, mlp_b3, log_dec);
    k_fft_h<<<DMOD / 2, 1024, smem_fft>>>();
    k_fftconv<<<BATCH * DMOD / 2, 1024, smem_fft>>>(sck_w, sck_b, scv_w, scv_b);
    k_gemm_tc<1><<<dim3(6, 128), 256>>>(nullptr, out_proj, out);
}

// round 7
// speedup vs baseline: 1.7725x; 1.1675x over previous
#include <cuda_runtime.h>
#include <cstdint>

// ---------------- problem constants ----------------
#define BATCH 2
#define LSEQ  8192
#define DMOD  768
#define NFFT  16384          // 2*LSEQ zero-padded FFT size
#define LOGN  14
#define EMB   64

// ---------------- scratch (static device globals; no runtime alloc) ----------------
__device__ float  g_qT[BATCH * DMOD * LSEQ];   // q transposed [b][d][l]
__device__ float  g_kT[BATCH * DMOD * LSEQ];   // k transposed
__device__ float  g_vT[BATCH * DMOD * LSEQ];   // v transposed
__device__ float  g_h [DMOD * LSEQ];           // hyena filter [d][l]
__device__ float2 g_Hf[DMOD * NFFT];           // filter spectrum, rev4-indexed: [d][p] = H_d(rev4(p))
__device__ float  g_yg[BATCH * LSEQ * DMOD];   // gated output [b][l][d]
__device__ float2 g_tw[NFFT / 2];              // twiddle table exp(-2*pi*i*t/N)

// ---------------- twiddle init ----------------
__global__ void k_twiddle() {
    int i = blockIdx.x * blockDim.x + threadIdx.x;
    if (i < NFFT / 2) {
        double ang = -2.0 * 3.14159265358979323846 * (double)i / (double)NFFT;
        g_tw[i] = make_float2((float)cos(ang), (float)sin(ang));
    }
}

// ---------------- complex helpers ----------------
__device__ __forceinline__ float2 cmul(float2 a, float2 b) {
    return make_float2(a.x * b.x - a.y * b.y, a.x * b.y + a.y * b.x);
}
__device__ __forceinline__ float2 cmulc(float2 a, float2 b) {   // a * conj(b)
    return make_float2(a.x * b.x + a.y * b.y, a.y * b.x - a.x * b.y);
}
__device__ __forceinline__ float2 cadd(float2 a, float2 b) { return make_float2(a.x + b.x, a.y + b.y); }
__device__ __forceinline__ float2 csub(float2 a, float2 b) { return make_float2(a.x - b.x, a.y - b.y); }

// base-4 digit reversal of a 14-bit index: rev4(x) = swap-adjacent-bits(bitrev(x))
__device__ __forceinline__ int rev4_14(int x) {
    unsigned y = __brev((unsigned)x) >> (32 - LOGN);
    return (int)(((y & 0x1555u) << 1) | ((y >> 1) & 0x1555u));
}

// ---------------- tf32 helpers ----------------
__device__ __forceinline__ uint32_t f2tf(float x) {
    uint32_t r;
    asm("cvt.rna.tf32.f32 %0, %1;" : "=r"(r) : "f"(x));
    return r;
}

#define MMA_TF32(c, a, b)                                                     \
    asm volatile(                                                             \
        "mma.sync.aligned.m16n8k8.row.col.f32.tf32.tf32.f32 "                 \
        "{%0,%1,%2,%3},{%4,%5,%6,%7},{%8,%9},{%0,%1,%2,%3};"                  \
        : "+f"(c[0]), "+f"(c[1]), "+f"(c[2]), "+f"(c[3])                      \
        : "r"(a[0]), "r"(a[1]), "r"(a[2]), "r"(a[3]), "r"(b[0]), "r"(b[1]))

// ---------------- tensor-core GEMM (tf32x3) with register-prefetch pipeline ---------
#define BKP 20
template <int EPI>
__global__ __launch_bounds__(256) void k_gemm_tc(const float* __restrict__ Aarg,
                                                 const float* __restrict__ B,
                                                 float* __restrict__ C) {
    __shared__ uint32_t Ah[128][BKP], Al[128][BKP];
    __shared__ uint32_t Bh[128][BKP], Bl[128][BKP];

    const float* A = (EPI == 1) ? (const float*)g_yg : Aarg;
    const int i0 = blockIdx.y * 128;
    const int j0 = blockIdx.x * 128;
    const int tid = threadIdx.x;
    const int wid = tid >> 5;
    const int lane = tid & 31;
    const int g  = lane >> 2;
    const int tg = lane & 3;
    const int wm = wid >> 2;
    const int wn = wid & 3;

    const int r0 = tid >> 2;
    const int kq0 = (tid & 3) * 4;
    const float* Ar0 = A + (size_t)(i0 + r0) * 768 + kq0;
    const float* Ar1 = A + (size_t)(i0 + r0 + 64) * 768 + kq0;
    const float* Br0 = B + (size_t)(j0 + r0) * 768 + kq0;
    const float* Br1 = B + (size_t)(j0 + r0 + 64) * 768 + kq0;

    float c[4][4][4];
#pragma unroll
    for (int mi = 0; mi < 4; mi++)
#pragma unroll
        for (int ni = 0; ni < 4; ni++)
#pragma unroll
            for (int r = 0; r < 4; r++) c[mi][ni][r] = 0.f;

    float4 va0 = *(const float4*)(Ar0);
    float4 va1 = *(const float4*)(Ar1);
    float4 vb0 = *(const float4*)(Br0);
    float4 vb1 = *(const float4*)(Br1);

    for (int kb = 0; kb < 768; kb += 16) {
        {
            uint32_t h0 = f2tf(va0.x), h1 = f2tf(va0.y), h2 = f2tf(va0.z), h3 = f2tf(va0.w);
            *(uint4*)&Ah[r0][kq0] = make_uint4(h0, h1, h2, h3);
            *(uint4*)&Al[r0][kq0] = make_uint4(f2tf(va0.x - __uint_as_float(h0)),
                                               f2tf(va0.y - __uint_as_float(h1)),
                                               f2tf(va0.z - __uint_as_float(h2)),
                                               f2tf(va0.w - __uint_as_float(h3)));
            uint32_t i0h = f2tf(va1.x), i1h = f2tf(va1.y), i2h = f2tf(va1.z), i3h = f2tf(va1.w);
            *(uint4*)&Ah[r0 + 64][kq0] = make_uint4(i0h, i1h, i2h, i3h);
            *(uint4*)&Al[r0 + 64][kq0] = make_uint4(f2tf(va1.x - __uint_as_float(i0h)),
                                                    f2tf(va1.y - __uint_as_float(i1h)),
                                                    f2tf(va1.z - __uint_as_float(i2h)),
                                                    f2tf(va1.w - __uint_as_float(i3h)));
            uint32_t g0 = f2tf(vb0.x), g1 = f2tf(vb0.y), g2 = f2tf(vb0.z), g3 = f2tf(vb0.w);
            *(uint4*)&Bh[r0][kq0] = make_uint4(g0, g1, g2, g3);
            *(uint4*)&Bl[r0][kq0] = make_uint4(f2tf(vb0.x - __uint_as_float(g0)),
                                               f2tf(vb0.y - __uint_as_float(g1)),
                                               f2tf(vb0.z - __uint_as_float(g2)),
                                               f2tf(vb0.w - __uint_as_float(g3)));
            uint32_t j0h = f2tf(vb1.x), j1h = f2tf(vb1.y), j2h = f2tf(vb1.z), j3h = f2tf(vb1.w);
            *(uint4*)&Bh[r0 + 64][kq0] = make_uint4(j0h, j1h, j2h, j3h);
            *(uint4*)&Bl[r0 + 64][kq0] = make_uint4(f2tf(vb1.x - __uint_as_float(j0h)),
                                                    f2tf(vb1.y - __uint_as_float(j1h)),
                                                    f2tf(vb1.z - __uint_as_float(j2h)),
                                                    f2tf(vb1.w - __uint_as_float(j3h)));
        }
        __syncthreads();

        if (kb + 16 < 768) {
            va0 = *(const float4*)(Ar0 + kb + 16);
            va1 = *(const float4*)(Ar1 + kb + 16);
            vb0 = *(const float4*)(Br0 + kb + 16);
            vb1 = *(const float4*)(Br1 + kb + 16);
        }

#pragma unroll
        for (int ks = 0; ks < 16; ks += 8) {
            uint32_t ah[4][4], al[4][4], bh[4][2], bl[4][2];
#pragma unroll
            for (int mi = 0; mi < 4; mi++) {
                int m = wm * 64 + mi * 16;
                ah[mi][0] = Ah[m + g][ks + tg];
                ah[mi][1] = Ah[m + g + 8][ks + tg];
                ah[mi][2] = Ah[m + g][ks + tg + 4];
                ah[mi][3] = Ah[m + g + 8][ks + tg + 4];
                al[mi][0] = Al[m + g][ks + tg];
                al[mi][1] = Al[m + g + 8][ks + tg];
                al[mi][2] = Al[m + g][ks + tg + 4];
                al[mi][3] = Al[m + g + 8][ks + tg + 4];
            }
#pragma unroll
            for (int ni = 0; ni < 4; ni++) {
                int n = wn * 32 + ni * 8;
                bh[ni][0] = Bh[n + g][ks + tg];
                bh[ni][1] = Bh[n + g][ks + tg + 4];
                bl[ni][0] = Bl[n + g][ks + tg];
                bl[ni][1] = Bl[n + g][ks + tg + 4];
            }
#pragma unroll
            for (int mi = 0; mi < 4; mi++)
#pragma unroll
                for (int ni = 0; ni < 4; ni++) {
                    MMA_TF32(c[mi][ni], ah[mi], bh[ni]);
                    MMA_TF32(c[mi][ni], al[mi], bh[ni]);
                    MMA_TF32(c[mi][ni], ah[mi], bl[ni]);
                }
        }
        __syncthreads();
    }

#pragma unroll
    for (int mi = 0; mi < 4; mi++) {
#pragma unroll
        for (int ni = 0; ni < 4; ni++) {
            int rm0 = i0 + wm * 64 + mi * 16 + g;
            int rm1 = rm0 + 8;
            int cn  = j0 + wn * 32 + ni * 8 + 2 * tg;
            if (EPI == 0) {
                int part0 = rm0 / DMOD, dch0 = rm0 - part0 * DMOD;
                int part1 = rm1 / DMOD, dch1 = rm1 - part1 * DMOD;
                float* t0 = (part0 == 0) ? g_qT : (part0 == 1 ? g_kT : g_vT);
                float* t1 = (part1 == 0) ? g_qT : (part1 == 1 ? g_kT : g_vT);
                int bb = cn >> 13;
                int l  = cn & (LSEQ - 1);
                *(float2*)(t0 + ((size_t)bb * DMOD + dch0) * LSEQ + l) =
                    make_float2(c[mi][ni][0], c[mi][ni][1]);
                *(float2*)(t1 + ((size_t)bb * DMOD + dch1) * LSEQ + l) =
                    make_float2(c[mi][ni][2], c[mi][ni][3]);
            } else {
                *(float2*)(C + (size_t)rm0 * DMOD + cn) =
                    make_float2(c[mi][ni][0], c[mi][ni][1]);
                *(float2*)(C + (size_t)rm1 * DMOD + cn) =
                    make_float2(c[mi][ni][2], c[mi][ni][3]);
            }
        }
    }
}

// ---------------- hyena filter MLP + decay ----------------
#define FTL 32
__global__ __launch_bounds__(256) void k_filter(const float* __restrict__ w1, const float* __restrict__ b1,
                                                const float* __restrict__ w2, const float* __restrict__ b2,
                                                const float* __restrict__ w3, const float* __restrict__ b3,
                                                const float* __restrict__ ld) {
    __shared__ float ws [EMB][EMB + 1];
    __shared__ float pe [FTL][EMB + 1];
    __shared__ float h1s[FTL][EMB + 1];
    __shared__ float h2s[FTL][EMB + 1];
    const int l0 = blockIdx.x * FTL;
    const int tid = threadIdx.x;
    const float TWO_PI = 6.2831853071795864769f;
    const float inv = 1.0f / (float)(LSEQ - 1);

    for (int idx = tid; idx < EMB * EMB; idx += 256)
        ws[idx >> 6][idx & 63] = w1[idx];
    for (int idx = tid; idx < FTL * EMB; idx += 256) {
        int li = idx >> 6, e = idx & 63;
        float t = (float)(l0 + li) * inv;
        pe[li][e] = (e < 32) ? sinf(t * TWO_PI * (float)(e + 1))
                             : cosf(t * TWO_PI * (float)(e - 31));
    }
    __syncthreads();
    for (int idx = tid; idx < FTL * EMB; idx += 256) {
        int li = idx >> 6, e = idx & 63;
        float s = b1[e];
#pragma unroll 16
        for (int cc = 0; cc < EMB; cc++) s += pe[li][cc] * ws[e][cc];
        h1s[li][e] = s / (1.f + __expf(-s));
    }
    __syncthreads();
    for (int idx = tid; idx < EMB * EMB; idx += 256)
        ws[idx >> 6][idx & 63] = w2[idx];
    __syncthreads();
    for (int idx = tid; idx < FTL * EMB; idx += 256) {
        int li = idx >> 6, e = idx & 63;
        float s = b2[e];
#pragma unroll 16
        for (int cc = 0; cc < EMB; cc++) s += h1s[li][cc] * ws[e][cc];
        h2s[li][e] = s / (1.f + __expf(-s));
    }
    __syncthreads();
    for (int d = tid; d < DMOD; d += 256) {
        float acc[FTL];
#pragma unroll
        for (int li = 0; li < FTL; li++) acc[li] = 0.f;
        const float* w3r = w3 + d * EMB;
#pragma unroll 8
        for (int e = 0; e < EMB; e++) {
            float wv = w3r[e];
#pragma unroll
            for (int li = 0; li < FTL; li++) acc[li] += h2s[li][e] * wv;
        }
        float b3d = b3[d];
        float a = fabsf(ld[d]);
        float dec  = __expf(-a * (float)l0);
        float step = __expf(-a);
        float* outp = g_h + (size_t)d * LSEQ + l0;
#pragma unroll
        for (int li = 0; li < FTL; li++) {
            outp[li] = (acc[li] + b3d) * dec;
            dec *= step;
        }
    }
}

// ---------------- radix-4 FFT stage helpers (shared memory) ----------------
// Forward DIF stages s = 1..6 (stage 0 folded into load). natural -> base-4 digit-reversed.
__device__ __forceinline__ void fft4_fwd_stages(float2* sm, int tid, int nthr) {
#pragma unroll
    for (int s = 1; s < 7; s++) {
        const int e = 2 * (6 - s);
        const int m = 1 << e;
#pragma unroll 4
        for (int idx = tid; idx < NFFT / 4; idx += nthr) {
            int j = idx & (m - 1);
            int base = ((idx >> e) << (e + 2)) + j;
            float2 a0 = sm[base], a1 = sm[base + m], a2 = sm[base + 2 * m], a3 = sm[base + 3 * m];
            float2 w  = g_tw[j << (2 * s)];
            float2 w2 = g_tw[j << (2 * s + 1)];
            float2 w3 = cmul(w, w2);
            float2 t0 = cadd(a0, a2);
            float2 t1 = csub(a0, a2);
            float2 t2 = cadd(a1, a3);
            float2 t3 = make_float2(a1.y - a3.y, a3.x - a1.x);   // -i*(a1-a3)
            sm[base]         = cadd(t0, t2);
            sm[base + m]     = cmul(cadd(t1, t3), w);
            sm[base + 2 * m] = cmul(csub(t0, t2), w2);
            sm[base + 3 * m] = cmul(csub(t1, t3), w3);
        }
        __syncthreads();
    }
}

// Inverse DIT stages s = 0..5 (final stage s=6 fused by caller). digit-reversed -> natural.
__device__ __forceinline__ void fft4_inv_stages(float2* sm, int tid, int nthr) {
#pragma unroll
    for (int s = 0; s < 6; s++) {
        const int e = 2 * s;
        const int m = 1 << e;
#pragma unroll 4
        for (int idx = tid; idx < NFFT / 4; idx += nthr) {
            int j = idx & (m - 1);
            int base = ((idx >> e) << (e + 2)) + j;
            float2 b0 = sm[base], b1 = sm[base + m], b2 = sm[base + 2 * m], b3 = sm[base + 3 * m];
            float2 w  = g_tw[j << (2 * (6 - s))];
            float2 w2 = g_tw[j << (2 * (6 - s) + 1)];
            float2 w3 = cmul(w, w2);
            float2 c1 = cmulc(b1, w);
            float2 c2 = cmulc(b2, w2);
            float2 c3 = cmulc(b3, w3);
            float2 v0 = cadd(b0, c2);     // 2*(a0+a2)
            float2 v1 = cadd(c1, c3);     // 2*(a0-a2)
            float2 v2 = csub(b0, c2);     // 2*(a1+a3)
            float2 v3 = csub(c1, c3);     // 2*t3 = -2i*(a1-a3)
            sm[base]         = cadd(v0, v1);                               // 4*a0
            sm[base + m]     = make_float2(v2.x - v3.y, v2.y + v3.x);      // 4*a1 = v2 + i*v3
            sm[base + 2 * m] = csub(v0, v1);                               // 4*a2
            sm[base + 3 * m] = make_float2(v2.x + v3.y, v2.y - v3.x);      // 4*a3 = v2 - i*v3
        }
        __syncthreads();
    }
}

// map pp (0..NFFT/2) to digit-reversed position p covering each conjugate pair once:
// p & 2 == 0  <=>  k = rev4(p) < N/2 ; pp == N/2 handles the self-conjugate k = N/2 (p = 2).
__device__ __forceinline__ int pair_pos(int pp) {
    return (pp == NFFT / 2) ? 2 : (((pp & ~1) << 1) | (pp & 1));
}

// ---------------- filter spectrum: two-for-one radix-4 (channels 2c, 2c+1) ------------
// g_Hf[d][p] = H_d(rev4(p)).
__global__ void k_fft_h() {
    extern __shared__ float2 sm[];
    const int c = blockIdx.x;
    const int d0 = 2 * c, d1 = 2 * c + 1;
    const int tid = threadIdx.x, nthr = blockDim.x;
    const float* s0 = g_h + (size_t)d0 * LSEQ;
    const float* s1 = g_h + (size_t)d1 * LSEQ;
    // load pair + fold radix-4 DIF stage 0 (a2 = a3 = 0 from zero padding)
    for (int j = tid; j < NFFT / 4; j += nthr) {
        float2 a0 = make_float2(s0[j], s1[j]);
        float2 a1 = make_float2(s0[j + 4096], s1[j + 4096]);
        float2 w  = g_tw[j];
        float2 w2 = g_tw[2 * j];
        float2 w3 = cmul(w, w2);
        float2 t3 = make_float2(a1.y, -a1.x);          // -i*a1
        sm[j]         = cadd(a0, a1);
        sm[j + 4096]  = cmul(cadd(a0, t3), w);
        sm[j + 8192]  = cmul(csub(a0, a1), w2);
        sm[j + 12288] = cmul(csub(a0, t3), w3);
    }
    __syncthreads();
    fft4_fwd_stages(sm, tid, nthr);
    // unpack Ha/Hb, store rev4-indexed
    float2* Ha = g_Hf + (size_t)d0 * NFFT;
    float2* Hb = g_Hf + (size_t)d1 * NFFT;
    for (int pp = tid; pp <= NFFT / 2; pp += nthr) {
        int p = pair_pos(pp);
        int k = rev4_14(p);
        int q = rev4_14((NFFT - k) & (NFFT - 1));
        float2 z1 = sm[p];
        float2 z2 = sm[q];
        float2 ha = make_float2(0.5f * (z1.x + z2.x), 0.5f * (z1.y - z2.y));
        float2 hb = make_float2(0.5f * (z1.y + z2.y), 0.5f * (z2.x - z1.x));
        Ha[p] = ha;
        Hb[p] = hb;
        Ha[q] = make_float2(ha.x, -ha.y);
        Hb[q] = make_float2(hb.x, -hb.y);
    }
}

// ---- fused: dwconv(k)*dwconv(v) -> radix-4 FFT pair -> xH -> IFFT -> gate -> yg ------
__global__ void k_fftconv(const float* __restrict__ skw, const float* __restrict__ skb,
                          const float* __restrict__ svw, const float* __restrict__ svb) {
    extern __shared__ float2 sm[];
    const int bc = blockIdx.x;
    const int b = bc / (DMOD / 2);
    const int c = bc - b * (DMOD / 2);
    const int d0 = 2 * c, d1 = 2 * c + 1;
    const int tid = threadIdx.x, nthr = blockDim.x;

    const float* k0 = g_kT + ((size_t)b * DMOD + d0) * LSEQ;
    const float* k1 = g_kT + ((size_t)b * DMOD + d1) * LSEQ;
    const float* v0 = g_vT + ((size_t)b * DMOD + d0) * LSEQ;
    const float* v1 = g_vT + ((size_t)b * DMOD + d1) * LSEQ;

    float kw00 = skw[d0 * 3], kw01 = skw[d0 * 3 + 1], kw02 = skw[d0 * 3 + 2], kb0 = skb[d0];
    float vw00 = svw[d0 * 3], vw01 = svw[d0 * 3 + 1], vw02 = svw[d0 * 3 + 2], vb0 = svb[d0];
    float kw10 = skw[d1 * 3], kw11 = skw[d1 * 3 + 1], kw12 = skw[d1 * 3 + 2], kb1 = skb[d1];
    float vw10 = svw[d1 * 3], vw11 = svw[d1 * 3 + 1], vw12 = svw[d1 * 3 + 2], vb1 = svb[d1];

    // depthwise conv at position l for both channels, packed as float2
#define UPAIR(l, out)                                                                   \
    {                                                                                   \
        int _l = (l);                                                                   \
        float ka2 = k0[_l];                                                             \
        float ka1 = (_l >= 1) ? k0[_l - 1] : 0.f;                                       \
        float ka0 = (_l >= 2) ? k0[_l - 2] : 0.f;                                       \
        float va2 = v0[_l];                                                             \
        float va1 = (_l >= 1) ? v0[_l - 1] : 0.f;                                       \
        float va0 = (_l >= 2) ? v0[_l - 2] : 0.f;                                       \
        float u0 = (kw00 * ka0 + kw01 * ka1 + kw02 * ka2 + kb0) *                       \
                   (vw00 * va0 + vw01 * va1 + vw02 * va2 + vb0);                        \
        float kb2_ = k1[_l];                                                            \
        float kb1_ = (_l >= 1) ? k1[_l - 1] : 0.f;                                      \
        float kb0_ = (_l >= 2) ? k1[_l - 2] : 0.f;                                      \
        float vb2_ = v1[_l];                                                            \
        float vb1_ = (_l >= 1) ? v1[_l - 1] : 0.f;                                      \
        float vb0_ = (_l >= 2) ? v1[_l - 2] : 0.f;                                      \
        float u1 = (kw10 * kb0_ + kw11 * kb1_ + kw12 * kb2_ + kb1) *                    \
                   (vw10 * vb0_ + vw11 * vb1_ + vw12 * vb2_ + vb1);                     \
        out = make_float2(u0, u1);                                                      \
    }

    // load + conv + fold radix-4 DIF stage 0 (a2 = a3 = 0)
    for (int j = tid; j < NFFT / 4; j += nthr) {
        float2 a0, a1;
        UPAIR(j, a0);
        UPAIR(j + 4096, a1);
        float2 w  = g_tw[j];
        float2 w2 = g_tw[2 * j];
        float2 w3 = cmul(w, w2);
        float2 t3 = make_float2(a1.y, -a1.x);          // -i*a1
        sm[j]         = cadd(a0, a1);
        sm[j + 4096]  = cmul(cadd(a0, t3), w);
        sm[j + 8192]  = cmul(csub(a0, a1), w2);
        sm[j + 12288] = cmul(csub(a0, t3), w3);
    }
#undef UPAIR
    __syncthreads();
    fft4_fwd_stages(sm, tid, nthr);

    // spectral: unpack pair, multiply by H (rev4-indexed, coalesced), repack
    const float2* Ha = g_Hf + (size_t)d0 * NFFT;
    const float2* Hb = g_Hf + (size_t)d1 * NFFT;
    const float hscale = 0.5f / (float)NFFT;
    for (int pp = tid; pp <= NFFT / 2; pp += nthr) {
        int p = pair_pos(pp);
        int k = rev4_14(p);
        int q = rev4_14((NFFT - k) & (NFFT - 1));
        float2 z1 = sm[p];
        float2 z2 = sm[q];
        float2 za = make_float2(hscale * (z1.x + z2.x), hscale * (z1.y - z2.y));
        float2 zb = make_float2(hscale * (z1.y + z2.y), hscale * (z2.x - z1.x));
        float2 ha = Ha[p];
        float2 hb = Hb[p];
        float2 ya = cmul(za, ha);
        float2 yb = cmul(zb, hb);
        sm[p] = make_float2(ya.x - yb.y, ya.y + yb.x);   // W(k) = Ya + i*Yb
        sm[q] = make_float2(ya.x + yb.y, yb.x - ya.y);   // W(N-k) = conj(Ya)+i*conj(Yb)
    }
    __syncthreads();
    fft4_inv_stages(sm, tid, nthr);

    // final inverse stage (s=6, m=4096) fused with silu(q) gate + store [b][l][d]
    const float* q0 = g_qT + ((size_t)b * DMOD + d0) * LSEQ;
    const float* q1 = g_qT + ((size_t)b * DMOD + d1) * LSEQ;
    for (int j = tid; j < NFFT / 4; j += nthr) {
        float2 b0 = sm[j], b1 = sm[j + 4096], b2 = sm[j + 8192], b3 = sm[j + 12288];
        float2 w  = g_tw[j];
        float2 w2 = g_tw[2 * j];
        float2 w3 = cmul(w, w2);
        float2 c1 = cmulc(b1, w);
        float2 c2 = cmulc(b2, w2);
        float2 c3 = cmulc(b3, w3);
        float2 v0 = cadd(b0, c2);
        float2 v1 = cadd(c1, c3);
        float2 v2 = csub(b0, c2);
        float2 v3 = csub(c1, c3);
        float2 y0 = cadd(v0, v1);                              // packed output at l = j
        float2 y1 = make_float2(v2.x - v3.y, v2.y + v3.x);     // packed output at l = j+4096
        // gate + store l = j
        {
            float qa = q0[j], qb = q1[j];
            float ga = qa / (1.f + __expf(-qa));
            float gb = qb / (1.f + __expf(-qb));
            *(float2*)&g_yg[((size_t)b * LSEQ + j) * DMOD + d0] = make_float2(ga * y0.x, gb * y0.y);
        }
        // gate + store l = j + 4096
        {
            int l = j + 4096;
            float qa = q0[l], qb = q1[l];
            float ga = qa / (1.f + __expf(-qa));
            float gb = qb / (1.f + __expf(-qb));
            *(float2*)&g_yg[((size_t)b * LSEQ + l) * DMOD + d0] = make_float2(ga * y1.x, gb * y1.y);
        }
    }
}

// ---------------- launch ----------------
extern "C" void kernel_launch(void* const* d_in, const int* in_sizes, int n_in,
                              void* d_out, int out_size) {
    const float* x        = (const float*)d_in[0];
    const float* in_proj  = (const float*)d_in[1];
    const float* sck_w    = (const float*)d_in[2];
    const float* sck_b    = (const float*)d_in[3];
    const float* scv_w    = (const float*)d_in[4];
    const float* scv_b    = (const float*)d_in[5];
    const float* mlp_w1   = (const float*)d_in[6];
    const float* mlp_b1   = (const float*)d_in[7];
    const float* mlp_w2   = (const float*)d_in[8];
    const float* mlp_b2   = (const float*)d_in[9];
    const float* mlp_w3   = (const float*)d_in[10];
    const float* mlp_b3   = (const float*)d_in[11];
    const float* log_dec  = (const float*)d_in[12];
    const float* out_proj = (const float*)d_in[13];
    float* out = (float*)d_out;

    const int smem_fft = NFFT * sizeof(float2);   // 128 KB
    cudaFuncSetAttribute(k_fft_h,   cudaFuncAttributeMaxDynamicSharedMemorySize, smem_fft);
    cudaFuncSetAttribute(k_fftconv, cudaFuncAttributeMaxDynamicSharedMemorySize, smem_fft);

    k_twiddle<<<16, 512>>>();
    k_gemm_tc<0><<<dim3(128, 18), 256>>>(in_proj, x, nullptr);
    k_filter<<<LSEQ / FTL, 256>>>(mlp_w1, mlp_b1, mlp_w2, mlp_b2, mlp_w3, mlp_b3, log_dec);
    k_fft_h<<<DMOD / 2, 1024, smem_fft>>>();
    k_fftconv<<<BATCH * DMOD / 2, 1024, smem_fft>>>(sck_w, sck_b, scv_w, scv_b);
    k_gemm_tc<1><<<dim3(6, 128), 256>>>(nullptr, out_proj, out);
}

// round 8
// speedup vs baseline: 2.6880x; 1.5165x over previous
#include <cuda_runtime.h>
#include <cuda_bf16.h>
#include <cstdint>

// ---------------- problem constants ----------------
#define BATCH 2
#define LSEQ  8192
#define DMOD  768
#define NFFT  16384          // 2*LSEQ zero-padded FFT size
#define LOGN  14
#define EMB   64

// ---------------- scratch (static device globals; no runtime alloc) ----------------
__device__ float  g_qT[BATCH * DMOD * LSEQ];   // q transposed [b][d][l]
__device__ float  g_kT[BATCH * DMOD * LSEQ];   // k transposed
__device__ float  g_vT[BATCH * DMOD * LSEQ];   // v transposed
__device__ float  g_h [DMOD * LSEQ];           // hyena filter [d][l]
__device__ float2 g_Hf[DMOD * NFFT];           // filter spectrum, rev4-indexed
__device__ float  g_yg[BATCH * LSEQ * DMOD];   // gated output [b][l][d]
__device__ float2 g_tw[NFFT / 2];              // twiddle table exp(-2*pi*i*t/N)

// ---------------- twiddle init ----------------
__global__ void k_twiddle() {
    int i = blockIdx.x * blockDim.x + threadIdx.x;
    if (i < NFFT / 2) {
        double ang = -2.0 * 3.14159265358979323846 * (double)i / (double)NFFT;
        g_tw[i] = make_float2((float)cos(ang), (float)sin(ang));
    }
}

// ---------------- complex helpers ----------------
__device__ __forceinline__ float2 cmul(float2 a, float2 b) {
    return make_float2(a.x * b.x - a.y * b.y, a.x * b.y + a.y * b.x);
}
__device__ __forceinline__ float2 cmulc(float2 a, float2 b) {   // a * conj(b)
    return make_float2(a.x * b.x + a.y * b.y, a.y * b.x - a.x * b.y);
}
__device__ __forceinline__ float2 cadd(float2 a, float2 b) { return make_float2(a.x + b.x, a.y + b.y); }
__device__ __forceinline__ float2 csub(float2 a, float2 b) { return make_float2(a.x - b.x, a.y - b.y); }

__device__ __forceinline__ int rev4_14(int x) {
    unsigned y = __brev((unsigned)x) >> (32 - LOGN);
    return (int)(((y & 0x1555u) << 1) | ((y >> 1) & 0x1555u));
}

// ---------------- bf16 split helpers ----------------
// split two floats into packed bf16x2 (hi) + packed bf16x2 (lo); low half = x, high = y
__device__ __forceinline__ void split_pack(float x, float y, uint32_t& hi, uint32_t& lo) {
    __nv_bfloat16 xh = __float2bfloat16(x);
    __nv_bfloat16 yh = __float2bfloat16(y);
    __nv_bfloat16 xl = __float2bfloat16(x - __bfloat162float(xh));
    __nv_bfloat16 yl = __float2bfloat16(y - __bfloat162float(yh));
    hi = ((uint32_t)__bfloat16_as_ushort(yh) << 16) | (uint32_t)__bfloat16_as_ushort(xh);
    lo = ((uint32_t)__bfloat16_as_ushort(yl) << 16) | (uint32_t)__bfloat16_as_ushort(xl);
}

#define MMA_BF16(c, a, b)                                                     \
    asm volatile(                                                             \
        "mma.sync.aligned.m16n8k16.row.col.f32.bf16.bf16.f32 "                \
        "{%0,%1,%2,%3},{%4,%5,%6,%7},{%8,%9},{%0,%1,%2,%3};"                  \
        : "+f"(c[0]), "+f"(c[1]), "+f"(c[2]), "+f"(c[3])                      \
        : "r"(a[0]), "r"(a[1]), "r"(a[2]), "r"(a[3]), "r"(b[0]), "r"(b[1]))

// ---------------- tensor-core GEMM (bf16x3, m16n8k16): C[i][j]=sum_k A[i,k]*B[j,k] ----
// Block tile 128x128, BK=16, 8 warps (2Mx4N), warp tile 64x32.
// smem: packed bf16 pairs along K; column c holds k=2c,2c+1. Stride 12 -> conflict-free.
#define BKP2 12
template <int EPI>
__global__ __launch_bounds__(256) void k_gemm_tc(const float* __restrict__ Aarg,
                                                 const float* __restrict__ B,
                                                 float* __restrict__ C) {
    __shared__ uint32_t Ah[128][BKP2], Al[128][BKP2];
    __shared__ uint32_t Bh[128][BKP2], Bl[128][BKP2];

    const float* A = (EPI == 1) ? (const float*)g_yg : Aarg;
    const int i0 = blockIdx.y * 128;
    const int j0 = blockIdx.x * 128;
    const int tid = threadIdx.x;
    const int wid = tid >> 5;
    const int lane = tid & 31;
    const int g  = lane >> 2;
    const int tg = lane & 3;
    const int wm = wid >> 2;
    const int wn = wid & 3;

    const int r0  = tid >> 2;
    const int kq0 = (tid & 3) * 4;      // k offset {0,4,8,12}
    const int cc0 = kq0 >> 1;           // packed column {0,2,4,6}
    const float* Ar0 = A + (size_t)(i0 + r0) * 768 + kq0;
    const float* Ar1 = A + (size_t)(i0 + r0 + 64) * 768 + kq0;
    const float* Br0 = B + (size_t)(j0 + r0) * 768 + kq0;
    const float* Br1 = B + (size_t)(j0 + r0 + 64) * 768 + kq0;

    float c[4][4][4];
#pragma unroll
    for (int mi = 0; mi < 4; mi++)
#pragma unroll
        for (int ni = 0; ni < 4; ni++)
#pragma unroll
            for (int r = 0; r < 4; r++) c[mi][ni][r] = 0.f;

    float4 va0 = *(const float4*)(Ar0);
    float4 va1 = *(const float4*)(Ar1);
    float4 vb0 = *(const float4*)(Br0);
    float4 vb1 = *(const float4*)(Br1);

    for (int kb = 0; kb < 768; kb += 16) {
        // split + pack + store current tile
        {
            uint32_t h0, l0, h1, l1;
            split_pack(va0.x, va0.y, h0, l0);
            split_pack(va0.z, va0.w, h1, l1);
            Ah[r0][cc0] = h0; Ah[r0][cc0 + 1] = h1;
            Al[r0][cc0] = l0; Al[r0][cc0 + 1] = l1;
            split_pack(va1.x, va1.y, h0, l0);
            split_pack(va1.z, va1.w, h1, l1);
            Ah[r0 + 64][cc0] = h0; Ah[r0 + 64][cc0 + 1] = h1;
            Al[r0 + 64][cc0] = l0; Al[r0 + 64][cc0 + 1] = l1;
            split_pack(vb0.x, vb0.y, h0, l0);
            split_pack(vb0.z, vb0.w, h1, l1);
            Bh[r0][cc0] = h0; Bh[r0][cc0 + 1] = h1;
            Bl[r0][cc0] = l0; Bl[r0][cc0 + 1] = l1;
            split_pack(vb1.x, vb1.y, h0, l0);
            split_pack(vb1.z, vb1.w, h1, l1);
            Bh[r0 + 64][cc0] = h0; Bh[r0 + 64][cc0 + 1] = h1;
            Bl[r0 + 64][cc0] = l0; Bl[r0 + 64][cc0 + 1] = l1;
        }
        __syncthreads();

        // prefetch next tile (overlaps with MMA below)
        if (kb + 16 < 768) {
            va0 = *(const float4*)(Ar0 + kb + 16);
            va1 = *(const float4*)(Ar1 + kb + 16);
            vb0 = *(const float4*)(Br0 + kb + 16);
            vb1 = *(const float4*)(Br1 + kb + 16);
        }

        // one k16 pass covers the whole 16-wide tile
        uint32_t ah[4][4], al[4][4], bh[4][2], bl[4][2];
#pragma unroll
        for (int mi = 0; mi < 4; mi++) {
            int m = wm * 64 + mi * 16;
            ah[mi][0] = Ah[m + g][tg];
            ah[mi][1] = Ah[m + g + 8][tg];
            ah[mi][2] = Ah[m + g][tg + 4];
            ah[mi][3] = Ah[m + g + 8][tg + 4];
            al[mi][0] = Al[m + g][tg];
            al[mi][1] = Al[m + g + 8][tg];
            al[mi][2] = Al[m + g][tg + 4];
            al[mi][3] = Al[m + g + 8][tg + 4];
        }
#pragma unroll
        for (int ni = 0; ni < 4; ni++) {
            int n = wn * 32 + ni * 8;
            bh[ni][0] = Bh[n + g][tg];
            bh[ni][1] = Bh[n + g][tg + 4];
            bl[ni][0] = Bl[n + g][tg];
            bl[ni][1] = Bl[n + g][tg + 4];
        }
#pragma unroll
        for (int mi = 0; mi < 4; mi++)
#pragma unroll
            for (int ni = 0; ni < 4; ni++) {
                MMA_BF16(c[mi][ni], ah[mi], bh[ni]);
                MMA_BF16(c[mi][ni], al[mi], bh[ni]);
                MMA_BF16(c[mi][ni], ah[mi], bl[ni]);
            }
        __syncthreads();
    }

    // epilogue (C fragment layout identical to tf32 path)
#pragma unroll
    for (int mi = 0; mi < 4; mi++) {
#pragma unroll
        for (int ni = 0; ni < 4; ni++) {
            int rm0 = i0 + wm * 64 + mi * 16 + g;
            int rm1 = rm0 + 8;
            int cn  = j0 + wn * 32 + ni * 8 + 2 * tg;
            if (EPI == 0) {
                int part0 = rm0 / DMOD, dch0 = rm0 - part0 * DMOD;
                int part1 = rm1 / DMOD, dch1 = rm1 - part1 * DMOD;
                float* t0 = (part0 == 0) ? g_qT : (part0 == 1 ? g_kT : g_vT);
                float* t1 = (part1 == 0) ? g_qT : (part1 == 1 ? g_kT : g_vT);
                int bb = cn >> 13;
                int l  = cn & (LSEQ - 1);
                *(float2*)(t0 + ((size_t)bb * DMOD + dch0) * LSEQ + l) =
                    make_float2(c[mi][ni][0], c[mi][ni][1]);
                *(float2*)(t1 + ((size_t)bb * DMOD + dch1) * LSEQ + l) =
                    make_float2(c[mi][ni][2], c[mi][ni][3]);
            } else {
                *(float2*)(C + (size_t)rm0 * DMOD + cn) =
                    make_float2(c[mi][ni][0], c[mi][ni][1]);
                *(float2*)(C + (size_t)rm1 * DMOD + cn) =
                    make_float2(c[mi][ni][2], c[mi][ni][3]);
            }
        }
    }
}

// ---------------- hyena filter MLP + decay ----------------
#define FTL 32
__global__ __launch_bounds__(256) void k_filter(const float* __restrict__ w1, const float* __restrict__ b1,
                                                const float* __restrict__ w2, const float* __restrict__ b2,
                                                const float* __restrict__ w3, const float* __restrict__ b3,
                                                const float* __restrict__ ld) {
    __shared__ float ws [EMB][EMB + 1];
    __shared__ float pe [FTL][EMB + 1];
    __shared__ float h1s[FTL][EMB + 1];
    __shared__ float h2s[FTL][EMB + 1];
    const int l0 = blockIdx.x * FTL;
    const int tid = threadIdx.x;
    const float TWO_PI = 6.2831853071795864769f;
    const float inv = 1.0f / (float)(LSEQ - 1);

    for (int idx = tid; idx < EMB * EMB; idx += 256)
        ws[idx >> 6][idx & 63] = w1[idx];
    for (int idx = tid; idx < FTL * EMB; idx += 256) {
        int li = idx >> 6, e = idx & 63;
        float t = (float)(l0 + li) * inv;
        pe[li][e] = (e < 32) ? sinf(t * TWO_PI * (float)(e + 1))
                             : cosf(t * TWO_PI * (float)(e - 31));
    }
    __syncthreads();
    for (int idx = tid; idx < FTL * EMB; idx += 256) {
        int li = idx >> 6, e = idx & 63;
        float s = b1[e];
#pragma unroll 16
        for (int cc = 0; cc < EMB; cc++) s += pe[li][cc] * ws[e][cc];
        h1s[li][e] = s / (1.f + __expf(-s));
    }
    __syncthreads();
    for (int idx = tid; idx < EMB * EMB; idx += 256)
        ws[idx >> 6][idx & 63] = w2[idx];
    __syncthreads();
    for (int idx = tid; idx < FTL * EMB; idx += 256) {
        int li = idx >> 6, e = idx & 63;
        float s = b2[e];
#pragma unroll 16
        for (int cc = 0; cc < EMB; cc++) s += h1s[li][cc] * ws[e][cc];
        h2s[li][e] = s / (1.f + __expf(-s));
    }
    __syncthreads();
    for (int d = tid; d < DMOD; d += 256) {
        float acc[FTL];
#pragma unroll
        for (int li = 0; li < FTL; li++) acc[li] = 0.f;
        const float* w3r = w3 + d * EMB;
#pragma unroll 8
        for (int e = 0; e < EMB; e++) {
            float wv = w3r[e];
#pragma unroll
            for (int li = 0; li < FTL; li++) acc[li] += h2s[li][e] * wv;
        }
        float b3d = b3[d];
        float a = fabsf(ld[d]);
        float dec  = __expf(-a * (float)l0);
        float step = __expf(-a);
        float* outp = g_h + (size_t)d * LSEQ + l0;
#pragma unroll
        for (int li = 0; li < FTL; li++) {
            outp[li] = (acc[li] + b3d) * dec;
            dec *= step;
        }
    }
}

// ---------------- radix-4 FFT stage helpers (shared memory) ----------------
__device__ __forceinline__ void fft4_fwd_stages(float2* sm, int tid, int nthr) {
#pragma unroll
    for (int s = 1; s < 7; s++) {
        const int e = 2 * (6 - s);
        const int m = 1 << e;
#pragma unroll 4
        for (int idx = tid; idx < NFFT / 4; idx += nthr) {
            int j = idx & (m - 1);
            int base = ((idx >> e) << (e + 2)) + j;
            float2 a0 = sm[base], a1 = sm[base + m], a2 = sm[base + 2 * m], a3 = sm[base + 3 * m];
            float2 w  = g_tw[j << (2 * s)];
            float2 w2 = g_tw[j << (2 * s + 1)];
            float2 w3 = cmul(w, w2);
            float2 t0 = cadd(a0, a2);
            float2 t1 = csub(a0, a2);
            float2 t2 = cadd(a1, a3);
            float2 t3 = make_float2(a1.y - a3.y, a3.x - a1.x);   // -i*(a1-a3)
            sm[base]         = cadd(t0, t2);
            sm[base + m]     = cmul(cadd(t1, t3), w);
            sm[base + 2 * m] = cmul(csub(t0, t2), w2);
            sm[base + 3 * m] = cmul(csub(t1, t3), w3);
        }
        __syncthreads();
    }
}

__device__ __forceinline__ void fft4_inv_stages(float2* sm, int tid, int nthr) {
#pragma unroll
    for (int s = 0; s < 6; s++) {
        const int e = 2 * s;
        const int m = 1 << e;
#pragma unroll 4
        for (int idx = tid; idx < NFFT / 4; idx += nthr) {
            int j = idx & (m - 1);
            int base = ((idx >> e) << (e + 2)) + j;
            float2 b0 = sm[base], b1 = sm[base + m], b2 = sm[base + 2 * m], b3 = sm[base + 3 * m];
            float2 w  = g_tw[j << (2 * (6 - s))];
            float2 w2 = g_tw[j << (2 * (6 - s) + 1)];
            float2 w3 = cmul(w, w2);
            float2 c1 = cmulc(b1, w);
            float2 c2 = cmulc(b2, w2);
            float2 c3 = cmulc(b3, w3);
            float2 v0 = cadd(b0, c2);
            float2 v1 = cadd(c1, c3);
            float2 v2 = csub(b0, c2);
            float2 v3 = csub(c1, c3);
            sm[base]         = cadd(v0, v1);
            sm[base + m]     = make_float2(v2.x - v3.y, v2.y + v3.x);
            sm[base + 2 * m] = csub(v0, v1);
            sm[base + 3 * m] = make_float2(v2.x + v3.y, v2.y - v3.x);
        }
        __syncthreads();
    }
}

__device__ __forceinline__ int pair_pos(int pp) {
    return (pp == NFFT / 2) ? 2 : (((pp & ~1) << 1) | (pp & 1));
}

// ---------------- filter spectrum: two-for-one radix-4 ----------------
__global__ void k_fft_h() {
    extern __shared__ float2 sm[];
    const int c = blockIdx.x;
    const int d0 = 2 * c, d1 = 2 * c + 1;
    const int tid = threadIdx.x, nthr = blockDim.x;
    const float* s0 = g_h + (size_t)d0 * LSEQ;
    const float* s1 = g_h + (size_t)d1 * LSEQ;
    for (int j = tid; j < NFFT / 4; j += nthr) {
        float2 a0 = make_float2(s0[j], s1[j]);
        float2 a1 = make_float2(s0[j + 4096], s1[j + 4096]);
        float2 w  = g_tw[j];
        float2 w2 = g_tw[2 * j];
        float2 w3 = cmul(w, w2);
        float2 t3 = make_float2(a1.y, -a1.x);
        sm[j]         = cadd(a0, a1);
        sm[j + 4096]  = cmul(cadd(a0, t3), w);
        sm[j + 8192]  = cmul(csub(a0, a1), w2);
        sm[j + 12288] = cmul(csub(a0, t3), w3);
    }
    __syncthreads();
    fft4_fwd_stages(sm, tid, nthr);
    float2* Ha = g_Hf + (size_t)d0 * NFFT;
    float2* Hb = g_Hf + (size_t)d1 * NFFT;
    for (int pp = tid; pp <= NFFT / 2; pp += nthr) {
        int p = pair_pos(pp);
        int k = rev4_14(p);
        int q = rev4_14((NFFT - k) & (NFFT - 1));
        float2 z1 = sm[p];
        float2 z2 = sm[q];
        float2 ha = make_float2(0.5f * (z1.x + z2.x), 0.5f * (z1.y - z2.y));
        float2 hb = make_float2(0.5f * (z1.y + z2.y), 0.5f * (z2.x - z1.x));
        Ha[p] = ha;
        Hb[p] = hb;
        Ha[q] = make_float2(ha.x, -ha.y);
        Hb[q] = make_float2(hb.x, -hb.y);
    }
}

// ---- fused: dwconv(k)*dwconv(v) -> radix-4 FFT pair -> xH -> IFFT -> gate -> yg ------
__global__ void k_fftconv(const float* __restrict__ skw, const float* __restrict__ skb,
                          const float* __restrict__ svw, const float* __restrict__ svb) {
    extern __shared__ float2 sm[];
    const int bc = blockIdx.x;
    const int b = bc / (DMOD / 2);
    const int c = bc - b * (DMOD / 2);
    const int d0 = 2 * c, d1 = 2 * c + 1;
    const int tid = threadIdx.x, nthr = blockDim.x;

    const float* k0 = g_kT + ((size_t)b * DMOD + d0) * LSEQ;
    const float* k1 = g_kT + ((size_t)b * DMOD + d1) * LSEQ;
    const float* v0 = g_vT + ((size_t)b * DMOD + d0) * LSEQ;
    const float* v1 = g_vT + ((size_t)b * DMOD + d1) * LSEQ;

    float kw00 = skw[d0 * 3], kw01 = skw[d0 * 3 + 1], kw02 = skw[d0 * 3 + 2], kb0 = skb[d0];
    float vw00 = svw[d0 * 3], vw01 = svw[d0 * 3 + 1], vw02 = svw[d0 * 3 + 2], vb0 = svb[d0];
    float kw10 = skw[d1 * 3], kw11 = skw[d1 * 3 + 1], kw12 = skw[d1 * 3 + 2], kb1 = skb[d1];
    float vw10 = svw[d1 * 3], vw11 = svw[d1 * 3 + 1], vw12 = svw[d1 * 3 + 2], vb1 = svb[d1];

#define UPAIR(l, out)                                                                   \
    {                                                                                   \
        int _l = (l);                                                                   \
        float ka2 = k0[_l];                                                             \
        float ka1 = (_l >= 1) ? k0[_l - 1] : 0.f;                                       \
        float ka0 = (_l >= 2) ? k0[_l - 2] : 0.f;                                       \
        float va2 = v0[_l];                                                             \
        float va1 = (_l >= 1) ? v0[_l - 1] : 0.f;                                       \
        float va0 = (_l >= 2) ? v0[_l - 2] : 0.f;                                       \
        float u0 = (kw00 * ka0 + kw01 * ka1 + kw02 * ka2 + kb0) *                       \
                   (vw00 * va0 + vw01 * va1 + vw02 * va2 + vb0);                        \
        float kb2_ = k1[_l];                                                            \
        float kb1_ = (_l >= 1) ? k1[_l - 1] : 0.f;                                      \
        float kb0_ = (_l >= 2) ? k1[_l - 2] : 0.f;                                      \
        float vb2_ = v1[_l];                                                            \
        float vb1_ = (_l >= 1) ? v1[_l - 1] : 0.f;                                      \
        float vb0_ = (_l >= 2) ? v1[_l - 2] : 0.f;                                      \
        float u1 = (kw10 * kb0_ + kw11 * kb1_ + kw12 * kb2_ + kb1) *                    \
                   (vw10 * vb0_ + vw11 * vb1_ + vw12 * vb2_ + vb1);                     \
        out = make_float2(u0, u1);                                                      \
    }

    for (int j = tid; j < NFFT / 4; j += nthr) {
        float2 a0, a1;
        UPAIR(j, a0);
        UPAIR(j + 4096, a1);
        float2 w  = g_tw[j];
        float2 w2 = g_tw[2 * j];
        float2 w3 = cmul(w, w2);
        float2 t3 = make_float2(a1.y, -a1.x);
        sm[j]         = cadd(a0, a1);
        sm[j + 4096]  = cmul(cadd(a0, t3), w);
        sm[j + 8192]  = cmul(csub(a0, a1), w2);
        sm[j + 12288] = cmul(csub(a0, t3), w3);
    }
#undef UPAIR
    __syncthreads();
    fft4_fwd_stages(sm, tid, nthr);

    const float2* Ha = g_Hf + (size_t)d0 * NFFT;
    const float2* Hb = g_Hf + (size_t)d1 * NFFT;
    const float hscale = 0.5f / (float)NFFT;
    for (int pp = tid; pp <= NFFT / 2; pp += nthr) {
        int p = pair_pos(pp);
        int k = rev4_14(p);
        int q = rev4_14((NFFT - k) & (NFFT - 1));
        float2 z1 = sm[p];
        float2 z2 = sm[q];
        float2 za = make_float2(hscale * (z1.x + z2.x), hscale * (z1.y - z2.y));
        float2 zb = make_float2(hscale * (z1.y + z2.y), hscale * (z2.x - z1.x));
        float2 ya = cmul(za, Ha[p]);
        float2 yb = cmul(zb, Hb[p]);
        sm[p] = make_float2(ya.x - yb.y, ya.y + yb.x);
        sm[q] = make_float2(ya.x + yb.y, yb.x - ya.y);
    }
    __syncthreads();
    fft4_inv_stages(sm, tid, nthr);

    const float* q0 = g_qT + ((size_t)b * DMOD + d0) * LSEQ;
    const float* q1 = g_qT + ((size_t)b * DMOD + d1) * LSEQ;
    for (int j = tid; j < NFFT / 4; j += nthr) {
        float2 b0 = sm[j], b1 = sm[j + 4096], b2 = sm[j + 8192], b3 = sm[j + 12288];
        float2 w  = g_tw[j];
        float2 w2 = g_tw[2 * j];
        float2 w3 = cmul(w, w2);
        float2 c1 = cmulc(b1, w);
        float2 c2 = cmulc(b2, w2);
        float2 c3 = cmulc(b3, w3);
        float2 v0 = cadd(b0, c2);
        float2 v1 = cadd(c1, c3);
        float2 v2 = csub(b0, c2);
        float2 v3 = csub(c1, c3);
        float2 y0 = cadd(v0, v1);
        float2 y1 = make_float2(v2.x - v3.y, v2.y + v3.x);
        {
            float qa = q0[j], qb = q1[j];
            float ga = qa / (1.f + __expf(-qa));
            float gb = qb / (1.f + __expf(-qb));
            *(float2*)&g_yg[((size_t)b * LSEQ + j) * DMOD + d0] = make_float2(ga * y0.x, gb * y0.y);
        }
        {
            int l = j + 4096;
            float qa = q0[l], qb = q1[l];
            float ga = qa / (1.f + __expf(-qa));
            float gb = qb / (1.f + __expf(-qb));
            *(float2*)&g_yg[((size_t)b * LSEQ + l) * DMOD + d0] = make_float2(ga * y1.x, gb * y1.y);
        }
    }
}

// ---------------- launch ----------------
extern "C" void kernel_launch(void* const* d_in, const int* in_sizes, int n_in,
                              void* d_out, int out_size) {
    const float* x        = (const float*)d_in[0];
    const float* in_proj  = (const float*)d_in[1];
    const float* sck_w    = (const float*)d_in[2];
    const float* sck_b    = (const float*)d_in[3];
    const float* scv_w    = (const float*)d_in[4];
    const float* scv_b    = (const float*)d_in[5];
    const float* mlp_w1   = (const float*)d_in[6];
    const float* mlp_b1   = (const float*)d_in[7];
    const float* mlp_w2   = (const float*)d_in[8];
    const float* mlp_b2   = (const float*)d_in[9];
    const float* mlp_w3   = (const float*)d_in[10];
    const float* mlp_b3   = (const float*)d_in[11];
    const float* log_dec  = (const float*)d_in[12];
    const float* out_proj = (const float*)d_in[13];
    float* out = (float*)d_out;

    const int smem_fft = NFFT * sizeof(float2);   // 128 KB
    cudaFuncSetAttribute(k_fft_h,   cudaFuncAttributeMaxDynamicSharedMemorySize, smem_fft);
    cudaFuncSetAttribute(k_fftconv, cudaFuncAttributeMaxDynamicSharedMemorySize, smem_fft);

    k_twiddle<<<16, 512>>>();
    k_gemm_tc<0><<<dim3(128, 18), 256>>>(in_proj, x, nullptr);
    k_filter<<<LSEQ / FTL, 256>>>(mlp_w1, mlp_b1, mlp_w2, mlp_b2, mlp_w3, mlp_b3, log_dec);
    k_fft_h<<<DMOD / 2, 1024, smem_fft>>>();
    k_fftconv<<<BATCH * DMOD / 2, 1024, smem_fft>>>(sck_w, sck_b, scv_w, scv_b);
    k_gemm_tc<1><<<dim3(6, 128), 256>>>(nullptr, out_proj, out);
}

// round 9
// speedup vs baseline: 2.9002x; 1.0789x over previous
#include <cuda_runtime.h>
#include <cuda_bf16.h>
#include <cstdint>

// ---------------- problem constants ----------------
#define BATCH 2
#define LSEQ  8192
#define DMOD  768
#define NFFT  16384          // 2*LSEQ zero-padded FFT size
#define LOGN  14
#define EMB   64

// ---------------- scratch (static device globals; no runtime alloc) ----------------
__device__ float  g_qT[BATCH * DMOD * LSEQ];   // q transposed [b][d][l]
__device__ float  g_kT[BATCH * DMOD * LSEQ];   // k transposed
__device__ float  g_vT[BATCH * DMOD * LSEQ];   // v transposed
__device__ float  g_h [DMOD * LSEQ];           // hyena filter [d][l]
__device__ float2 g_Hf[DMOD * NFFT];           // filter spectrum, rev4-indexed
__device__ float  g_yg[BATCH * LSEQ * DMOD];   // gated output [b][l][d]
__device__ float2 g_tw[NFFT / 2];              // twiddle table exp(-2*pi*i*t/N)

// ---------------- twiddle init ----------------
__global__ void k_twiddle() {
    int i = blockIdx.x * blockDim.x + threadIdx.x;
    if (i < NFFT / 2) {
        double ang = -2.0 * 3.14159265358979323846 * (double)i / (double)NFFT;
        g_tw[i] = make_float2((float)cos(ang), (float)sin(ang));
    }
}

// ---------------- complex helpers ----------------
__device__ __forceinline__ float2 cmul(float2 a, float2 b) {
    return make_float2(a.x * b.x - a.y * b.y, a.x * b.y + a.y * b.x);
}
__device__ __forceinline__ float2 cmulc(float2 a, float2 b) {   // a * conj(b)
    return make_float2(a.x * b.x + a.y * b.y, a.y * b.x - a.x * b.y);
}
__device__ __forceinline__ float2 cadd(float2 a, float2 b) { return make_float2(a.x + b.x, a.y + b.y); }
__device__ __forceinline__ float2 csub(float2 a, float2 b) { return make_float2(a.x - b.x, a.y - b.y); }

__device__ __forceinline__ int rev4_14(int x) {
    unsigned y = __brev((unsigned)x) >> (32 - LOGN);
    return (int)(((y & 0x1555u) << 1) | ((y >> 1) & 0x1555u));
}

// bank-conflict-killing swizzle: low nibble XOR 5*(next nibble) (5 coprime 16)
__device__ __forceinline__ int SWZ(int e) {
    int h = (e >> 4) & 15;
    return (e & ~15) | ((e ^ (5 * h)) & 15);
}

// ---------------- bf16 split helpers ----------------
__device__ __forceinline__ void split_pack(float x, float y, uint32_t& hi, uint32_t& lo) {
    __nv_bfloat16 xh = __float2bfloat16(x);
    __nv_bfloat16 yh = __float2bfloat16(y);
    __nv_bfloat16 xl = __float2bfloat16(x - __bfloat162float(xh));
    __nv_bfloat16 yl = __float2bfloat16(y - __bfloat162float(yh));
    hi = ((uint32_t)__bfloat16_as_ushort(yh) << 16) | (uint32_t)__bfloat16_as_ushort(xh);
    lo = ((uint32_t)__bfloat16_as_ushort(yl) << 16) | (uint32_t)__bfloat16_as_ushort(xl);
}

#define MMA_BF16(c, a, b)                                                     \
    asm volatile(                                                             \
        "mma.sync.aligned.m16n8k16.row.col.f32.bf16.bf16.f32 "                \
        "{%0,%1,%2,%3},{%4,%5,%6,%7},{%8,%9},{%0,%1,%2,%3};"                  \
        : "+f"(c[0]), "+f"(c[1]), "+f"(c[2]), "+f"(c[3])                      \
        : "r"(a[0]), "r"(a[1]), "r"(a[2]), "r"(a[3]), "r"(b[0]), "r"(b[1]))

// ---------------- tensor-core GEMM (bf16x3, m16n8k16) ----------------
#define BKP2 12
template <int EPI>
__global__ __launch_bounds__(256) void k_gemm_tc(const float* __restrict__ Aarg,
                                                 const float* __restrict__ B,
                                                 float* __restrict__ C) {
    __shared__ uint32_t Ah[128][BKP2], Al[128][BKP2];
    __shared__ uint32_t Bh[128][BKP2], Bl[128][BKP2];

    const float* A = (EPI == 1) ? (const float*)g_yg : Aarg;
    const int i0 = blockIdx.y * 128;
    const int j0 = blockIdx.x * 128;
    const int tid = threadIdx.x;
    const int wid = tid >> 5;
    const int lane = tid & 31;
    const int g  = lane >> 2;
    const int tg = lane & 3;
    const int wm = wid >> 2;
    const int wn = wid & 3;

    const int r0  = tid >> 2;
    const int kq0 = (tid & 3) * 4;
    const int cc0 = kq0 >> 1;
    const float* Ar0 = A + (size_t)(i0 + r0) * 768 + kq0;
    const float* Ar1 = A + (size_t)(i0 + r0 + 64) * 768 + kq0;
    const float* Br0 = B + (size_t)(j0 + r0) * 768 + kq0;
    const float* Br1 = B + (size_t)(j0 + r0 + 64) * 768 + kq0;

    float c[4][4][4];
#pragma unroll
    for (int mi = 0; mi < 4; mi++)
#pragma unroll
        for (int ni = 0; ni < 4; ni++)
#pragma unroll
            for (int r = 0; r < 4; r++) c[mi][ni][r] = 0.f;

    float4 va0 = *(const float4*)(Ar0);
    float4 va1 = *(const float4*)(Ar1);
    float4 vb0 = *(const float4*)(Br0);
    float4 vb1 = *(const float4*)(Br1);

    for (int kb = 0; kb < 768; kb += 16) {
        {
            uint32_t h0, l0, h1, l1;
            split_pack(va0.x, va0.y, h0, l0);
            split_pack(va0.z, va0.w, h1, l1);
            Ah[r0][cc0] = h0; Ah[r0][cc0 + 1] = h1;
            Al[r0][cc0] = l0; Al[r0][cc0 + 1] = l1;
            split_pack(va1.x, va1.y, h0, l0);
            split_pack(va1.z, va1.w, h1, l1);
            Ah[r0 + 64][cc0] = h0; Ah[r0 + 64][cc0 + 1] = h1;
            Al[r0 + 64][cc0] = l0; Al[r0 + 64][cc0 + 1] = l1;
            split_pack(vb0.x, vb0.y, h0, l0);
            split_pack(vb0.z, vb0.w, h1, l1);
            Bh[r0][cc0] = h0; Bh[r0][cc0 + 1] = h1;
            Bl[r0][cc0] = l0; Bl[r0][cc0 + 1] = l1;
            split_pack(vb1.x, vb1.y, h0, l0);
            split_pack(vb1.z, vb1.w, h1, l1);
            Bh[r0 + 64][cc0] = h0; Bh[r0 + 64][cc0 + 1] = h1;
            Bl[r0 + 64][cc0] = l0; Bl[r0 + 64][cc0 + 1] = l1;
        }
        __syncthreads();

        if (kb + 16 < 768) {
            va0 = *(const float4*)(Ar0 + kb + 16);
            va1 = *(const float4*)(Ar1 + kb + 16);
            vb0 = *(const float4*)(Br0 + kb + 16);
            vb1 = *(const float4*)(Br1 + kb + 16);
        }

        uint32_t ah[4][4], al[4][4], bh[4][2], bl[4][2];
#pragma unroll
        for (int mi = 0; mi < 4; mi++) {
            int m = wm * 64 + mi * 16;
            ah[mi][0] = Ah[m + g][tg];
            ah[mi][1] = Ah[m + g + 8][tg];
            ah[mi][2] = Ah[m + g][tg + 4];
            ah[mi][3] = Ah[m + g + 8][tg + 4];
            al[mi][0] = Al[m + g][tg];
            al[mi][1] = Al[m + g + 8][tg];
            al[mi][2] = Al[m + g][tg + 4];
            al[mi][3] = Al[m + g + 8][tg + 4];
        }
#pragma unroll
        for (int ni = 0; ni < 4; ni++) {
            int n = wn * 32 + ni * 8;
            bh[ni][0] = Bh[n + g][tg];
            bh[ni][1] = Bh[n + g][tg + 4];
            bl[ni][0] = Bl[n + g][tg];
            bl[ni][1] = Bl[n + g][tg + 4];
        }
#pragma unroll
        for (int mi = 0; mi < 4; mi++)
#pragma unroll
            for (int ni = 0; ni < 4; ni++) {
                MMA_BF16(c[mi][ni], ah[mi], bh[ni]);
                MMA_BF16(c[mi][ni], al[mi], bh[ni]);
                MMA_BF16(c[mi][ni], ah[mi], bl[ni]);
            }
        __syncthreads();
    }

#pragma unroll
    for (int mi = 0; mi < 4; mi++) {
#pragma unroll
        for (int ni = 0; ni < 4; ni++) {
            int rm0 = i0 + wm * 64 + mi * 16 + g;
            int rm1 = rm0 + 8;
            int cn  = j0 + wn * 32 + ni * 8 + 2 * tg;
            if (EPI == 0) {
                int part0 = rm0 / DMOD, dch0 = rm0 - part0 * DMOD;
                int part1 = rm1 / DMOD, dch1 = rm1 - part1 * DMOD;
                float* t0 = (part0 == 0) ? g_qT : (part0 == 1 ? g_kT : g_vT);
                float* t1 = (part1 == 0) ? g_qT : (part1 == 1 ? g_kT : g_vT);
                int bb = cn >> 13;
                int l  = cn & (LSEQ - 1);
                *(float2*)(t0 + ((size_t)bb * DMOD + dch0) * LSEQ + l) =
                    make_float2(c[mi][ni][0], c[mi][ni][1]);
                *(float2*)(t1 + ((size_t)bb * DMOD + dch1) * LSEQ + l) =
                    make_float2(c[mi][ni][2], c[mi][ni][3]);
            } else {
                *(float2*)(C + (size_t)rm0 * DMOD + cn) =
                    make_float2(c[mi][ni][0], c[mi][ni][1]);
                *(float2*)(C + (size_t)rm1 * DMOD + cn) =
                    make_float2(c[mi][ni][2], c[mi][ni][3]);
            }
        }
    }
}

// ---------------- hyena filter MLP + decay (with decay cutoff) ----------------
#define FTL 32
__global__ __launch_bounds__(256) void k_filter(const float* __restrict__ w1, const float* __restrict__ b1,
                                                const float* __restrict__ w2, const float* __restrict__ b2,
                                                const float* __restrict__ w3, const float* __restrict__ b3,
                                                const float* __restrict__ ld) {
    __shared__ float ws [EMB][EMB + 1];
    __shared__ float pe [FTL][EMB + 1];
    __shared__ float h1s[FTL][EMB + 1];
    __shared__ float h2s[FTL][EMB + 1];
    const int l0 = blockIdx.x * FTL;
    const int tid = threadIdx.x;
    const float TWO_PI = 6.2831853071795864769f;
    const float inv = 1.0f / (float)(LSEQ - 1);

    for (int idx = tid; idx < EMB * EMB; idx += 256)
        ws[idx >> 6][idx & 63] = w1[idx];
    for (int idx = tid; idx < FTL * EMB; idx += 256) {
        int li = idx >> 6, e = idx & 63;
        float t = (float)(l0 + li) * inv;
        pe[li][e] = (e < 32) ? sinf(t * TWO_PI * (float)(e + 1))
                             : cosf(t * TWO_PI * (float)(e - 31));
    }
    __syncthreads();
    for (int idx = tid; idx < FTL * EMB; idx += 256) {
        int li = idx >> 6, e = idx & 63;
        float s = b1[e];
#pragma unroll 16
        for (int cc = 0; cc < EMB; cc++) s += pe[li][cc] * ws[e][cc];
        h1s[li][e] = s / (1.f + __expf(-s));
    }
    __syncthreads();
    for (int idx = tid; idx < EMB * EMB; idx += 256)
        ws[idx >> 6][idx & 63] = w2[idx];
    __syncthreads();
    for (int idx = tid; idx < FTL * EMB; idx += 256) {
        int li = idx >> 6, e = idx & 63;
        float s = b2[e];
#pragma unroll 16
        for (int cc = 0; cc < EMB; cc++) s += h1s[li][cc] * ws[e][cc];
        h2s[li][e] = s / (1.f + __expf(-s));
    }
    __syncthreads();
    for (int d = tid; d < DMOD; d += 256) {
        float a = fabsf(ld[d]);
        float* outp = g_h + (size_t)d * LSEQ + l0;
        // exp(-a*l0) < e^-100 ~ 3.7e-44: below fp32 subnormal scale vs O(1) outputs
        if (a * (float)l0 > 100.f) {
#pragma unroll
            for (int li = 0; li < FTL; li++) outp[li] = 0.f;
            continue;
        }
        float acc[FTL];
#pragma unroll
        for (int li = 0; li < FTL; li++) acc[li] = 0.f;
        const float* w3r = w3 + d * EMB;
#pragma unroll 8
        for (int e = 0; e < EMB; e++) {
            float wv = w3r[e];
#pragma unroll
            for (int li = 0; li < FTL; li++) acc[li] += h2s[li][e] * wv;
        }
        float b3d = b3[d];
        float dec  = __expf(-a * (float)l0);
        float step = __expf(-a);
#pragma unroll
        for (int li = 0; li < FTL; li++) {
            outp[li] = (acc[li] + b3d) * dec;
            dec *= step;
        }
    }
}

// ---------------- radix-4 FFT stage helpers (swizzled shared memory) ----------------
__device__ __forceinline__ void fft4_fwd_stages(float2* sm, int tid, int nthr) {
#pragma unroll
    for (int s = 1; s < 7; s++) {
        const int e = 2 * (6 - s);
        const int m = 1 << e;
#pragma unroll 4
        for (int idx = tid; idx < NFFT / 4; idx += nthr) {
            int j = idx & (m - 1);
            int base = ((idx >> e) << (e + 2)) + j;
            float2 a0 = sm[SWZ(base)], a1 = sm[SWZ(base + m)];
            float2 a2 = sm[SWZ(base + 2 * m)], a3 = sm[SWZ(base + 3 * m)];
            float2 w  = g_tw[j << (2 * s)];
            float2 w2 = g_tw[j << (2 * s + 1)];
            float2 w3 = cmul(w, w2);
            float2 t0 = cadd(a0, a2);
            float2 t1 = csub(a0, a2);
            float2 t2 = cadd(a1, a3);
            float2 t3 = make_float2(a1.y - a3.y, a3.x - a1.x);   // -i*(a1-a3)
            sm[SWZ(base)]         = cadd(t0, t2);
            sm[SWZ(base + m)]     = cmul(cadd(t1, t3), w);
            sm[SWZ(base + 2 * m)] = cmul(csub(t0, t2), w2);
            sm[SWZ(base + 3 * m)] = cmul(csub(t1, t3), w3);
        }
        __syncthreads();
    }
}

__device__ __forceinline__ void fft4_inv_stages(float2* sm, int tid, int nthr) {
#pragma unroll
    for (int s = 0; s < 6; s++) {
        const int e = 2 * s;
        const int m = 1 << e;
#pragma unroll 4
        for (int idx = tid; idx < NFFT / 4; idx += nthr) {
            int j = idx & (m - 1);
            int base = ((idx >> e) << (e + 2)) + j;
            float2 b0 = sm[SWZ(base)], b1 = sm[SWZ(base + m)];
            float2 b2 = sm[SWZ(base + 2 * m)], b3 = sm[SWZ(base + 3 * m)];
            float2 w  = g_tw[j << (2 * (6 - s))];
            float2 w2 = g_tw[j << (2 * (6 - s) + 1)];
            float2 w3 = cmul(w, w2);
            float2 c1 = cmulc(b1, w);
            float2 c2 = cmulc(b2, w2);
            float2 c3 = cmulc(b3, w3);
            float2 v0 = cadd(b0, c2);
            float2 v1 = cadd(c1, c3);
            float2 v2 = csub(b0, c2);
            float2 v3 = csub(c1, c3);
            sm[SWZ(base)]         = cadd(v0, v1);
            sm[SWZ(base + m)]     = make_float2(v2.x - v3.y, v2.y + v3.x);
            sm[SWZ(base + 2 * m)] = csub(v0, v1);
            sm[SWZ(base + 3 * m)] = make_float2(v2.x + v3.y, v2.y - v3.x);
        }
        __syncthreads();
    }
}

__device__ __forceinline__ int pair_pos(int pp) {
    return (pp == NFFT / 2) ? 2 : (((pp & ~1) << 1) | (pp & 1));
}

// ---------------- filter spectrum: two-for-one radix-4 ----------------
__global__ void k_fft_h() {
    extern __shared__ float2 sm[];
    const int c = blockIdx.x;
    const int d0 = 2 * c, d1 = 2 * c + 1;
    const int tid = threadIdx.x, nthr = blockDim.x;
    const float* s0 = g_h + (size_t)d0 * LSEQ;
    const float* s1 = g_h + (size_t)d1 * LSEQ;
    for (int j = tid; j < NFFT / 4; j += nthr) {
        float2 a0 = make_float2(s0[j], s1[j]);
        float2 a1 = make_float2(s0[j + 4096], s1[j + 4096]);
        float2 w  = g_tw[j];
        float2 w2 = g_tw[2 * j];
        float2 w3 = cmul(w, w2);
        float2 t3 = make_float2(a1.y, -a1.x);
        sm[SWZ(j)]         = cadd(a0, a1);
        sm[SWZ(j + 4096)]  = cmul(cadd(a0, t3), w);
        sm[SWZ(j + 8192)]  = cmul(csub(a0, a1), w2);
        sm[SWZ(j + 12288)] = cmul(csub(a0, t3), w3);
    }
    __syncthreads();
    fft4_fwd_stages(sm, tid, nthr);
    float2* Ha = g_Hf + (size_t)d0 * NFFT;
    float2* Hb = g_Hf + (size_t)d1 * NFFT;
    for (int pp = tid; pp <= NFFT / 2; pp += nthr) {
        int p = pair_pos(pp);
        int k = rev4_14(p);
        int q = rev4_14((NFFT - k) & (NFFT - 1));
        float2 z1 = sm[SWZ(p)];
        float2 z2 = sm[SWZ(q)];
        float2 ha = make_float2(0.5f * (z1.x + z2.x), 0.5f * (z1.y - z2.y));
        float2 hb = make_float2(0.5f * (z1.y + z2.y), 0.5f * (z2.x - z1.x));
        Ha[p] = ha;
        Hb[p] = hb;
        Ha[q] = make_float2(ha.x, -ha.y);
        Hb[q] = make_float2(hb.x, -hb.y);
    }
}

// ---- fused: dwconv(k)*dwconv(v) -> radix-4 FFT pair -> xH -> IFFT -> gate -> yg ------
__global__ void k_fftconv(const float* __restrict__ skw, const float* __restrict__ skb,
                          const float* __restrict__ svw, const float* __restrict__ svb) {
    extern __shared__ float2 sm[];
    const int bc = blockIdx.x;
    const int b = bc / (DMOD / 2);
    const int c = bc - b * (DMOD / 2);
    const int d0 = 2 * c, d1 = 2 * c + 1;
    const int tid = threadIdx.x, nthr = blockDim.x;

    const float* k0 = g_kT + ((size_t)b * DMOD + d0) * LSEQ;
    const float* k1 = g_kT + ((size_t)b * DMOD + d1) * LSEQ;
    const float* v0 = g_vT + ((size_t)b * DMOD + d0) * LSEQ;
    const float* v1 = g_vT + ((size_t)b * DMOD + d1) * LSEQ;

    float kw00 = skw[d0 * 3], kw01 = skw[d0 * 3 + 1], kw02 = skw[d0 * 3 + 2], kb0 = skb[d0];
    float vw00 = svw[d0 * 3], vw01 = svw[d0 * 3 + 1], vw02 = svw[d0 * 3 + 2], vb0 = svb[d0];
    float kw10 = skw[d1 * 3], kw11 = skw[d1 * 3 + 1], kw12 = skw[d1 * 3 + 2], kb1 = skb[d1];
    float vw10 = svw[d1 * 3], vw11 = svw[d1 * 3 + 1], vw12 = svw[d1 * 3 + 2], vb1 = svb[d1];

#define UPAIR(l, out)                                                                   \
    {                                                                                   \
        int _l = (l);                                                                   \
        float ka2 = k0[_l];                                                             \
        float ka1 = (_l >= 1) ? k0[_l - 1] : 0.f;                                       \
        float ka0 = (_l >= 2) ? k0[_l - 2] : 0.f;                                       \
        float va2 = v0[_l];                                                             \
        float va1 = (_l >= 1) ? v0[_l - 1] : 0.f;                                       \
        float va0 = (_l >= 2) ? v0[_l - 2] : 0.f;                                       \
        float u0 = (kw00 * ka0 + kw01 * ka1 + kw02 * ka2 + kb0) *                       \
                   (vw00 * va0 + vw01 * va1 + vw02 * va2 + vb0);                        \
        float kb2_ = k1[_l];                                                            \
        float kb1_ = (_l >= 1) ? k1[_l - 1] : 0.f;                                      \
        float kb0_ = (_l >= 2) ? k1[_l - 2] : 0.f;                                      \
        float vb2_ = v1[_l];                                                            \
        float vb1_ = (_l >= 1) ? v1[_l - 1] : 0.f;                                      \
        float vb0_ = (_l >= 2) ? v1[_l - 2] : 0.f;                                      \
        float u1 = (kw10 * kb0_ + kw11 * kb1_ + kw12 * kb2_ + kb1) *                    \
                   (vw10 * vb0_ + vw11 * vb1_ + vw12 * vb2_ + vb1);                     \
        out = make_float2(u0, u1);                                                      \
    }

    for (int j = tid; j < NFFT / 4; j += nthr) {
        float2 a0, a1;
        UPAIR(j, a0);
        UPAIR(j + 4096, a1);
        float2 w  = g_tw[j];
        float2 w2 = g_tw[2 * j];
        float2 w3 = cmul(w, w2);
        float2 t3 = make_float2(a1.y, -a1.x);
        sm[SWZ(j)]         = cadd(a0, a1);
        sm[SWZ(j + 4096)]  = cmul(cadd(a0, t3), w);
        sm[SWZ(j + 8192)]  = cmul(csub(a0, a1), w2);
        sm[SWZ(j + 12288)] = cmul(csub(a0, t3), w3);
    }
#undef UPAIR
    __syncthreads();
    fft4_fwd_stages(sm, tid, nthr);

    const float2* Ha = g_Hf + (size_t)d0 * NFFT;
    const float2* Hb = g_Hf + (size_t)d1 * NFFT;
    const float hscale = 0.5f / (float)NFFT;
    for (int pp = tid; pp <= NFFT / 2; pp += nthr) {
        int p = pair_pos(pp);
        int k = rev4_14(p);
        int q = rev4_14((NFFT - k) & (NFFT - 1));
        float2 z1 = sm[SWZ(p)];
        float2 z2 = sm[SWZ(q)];
        float2 za = make_float2(hscale * (z1.x + z2.x), hscale * (z1.y - z2.y));
        float2 zb = make_float2(hscale * (z1.y + z2.y), hscale * (z2.x - z1.x));
        float2 ya = cmul(za, Ha[p]);
        float2 yb = cmul(zb, Hb[p]);
        sm[SWZ(p)] = make_float2(ya.x - yb.y, ya.y + yb.x);
        sm[SWZ(q)] = make_float2(ya.x + yb.y, yb.x - ya.y);
    }
    __syncthreads();
    fft4_inv_stages(sm, tid, nthr);

    const float* q0 = g_qT + ((size_t)b * DMOD + d0) * LSEQ;
    const float* q1 = g_qT + ((size_t)b * DMOD + d1) * LSEQ;
    for (int j = tid; j < NFFT / 4; j += nthr) {
        float2 b0 = sm[SWZ(j)], b1 = sm[SWZ(j + 4096)];
        float2 b2 = sm[SWZ(j + 8192)], b3 = sm[SWZ(j + 12288)];
        float2 w  = g_tw[j];
        float2 w2 = g_tw[2 * j];
        float2 w3 = cmul(w, w2);
        float2 c1 = cmulc(b1, w);
        float2 c2 = cmulc(b2, w2);
        float2 c3 = cmulc(b3, w3);
        float2 v0 = cadd(b0, c2);
        float2 v1 = cadd(c1, c3);
        float2 v2 = csub(b0, c2);
        float2 v3 = csub(c1, c3);
        float2 y0 = cadd(v0, v1);
        float2 y1 = make_float2(v2.x - v3.y, v2.y + v3.x);
        {
            float qa = q0[j], qb = q1[j];
            float ga = qa / (1.f + __expf(-qa));
            float gb = qb / (1.f + __expf(-qb));
            *(float2*)&g_yg[((size_t)b * LSEQ + j) * DMOD + d0] = make_float2(ga * y0.x, gb * y0.y);
        }
        {
            int l = j + 4096;
            float qa = q0[l], qb = q1[l];
            float ga = qa / (1.f + __expf(-qa));
            float gb = qb / (1.f + __expf(-qb));
            *(float2*)&g_yg[((size_t)b * LSEQ + l) * DMOD + d0] = make_float2(ga * y1.x, gb * y1.y);
        }
    }
}

// ---------------- launch ----------------
extern "C" void kernel_launch(void* const* d_in, const int* in_sizes, int n_in,
                              void* d_out, int out_size) {
    const float* x        = (const float*)d_in[0];
    const float* in_proj  = (const float*)d_in[1];
    const float* sck_w    = (const float*)d_in[2];
    const float* sck_b    = (const float*)d_in[3];
    const float* scv_w    = (const float*)d_in[4];
    const float* scv_b    = (const float*)d_in[5];
    const float* mlp_w1   = (const float*)d_in[6];
    const float* mlp_b1   = (const float*)d_in[7];
    const float* mlp_w2   = (const float*)d_in[8];
    const float* mlp_b2   = (const float*)d_in[9];
    const float* mlp_w3   = (const float*)d_in[10];
    const float* mlp_b3   = (const float*)d_in[11];
    const float* log_dec  = (const float*)d_in[12];
    const float* out_proj = (const float*)d_in[13];
    float* out = (float*)d_out;

    const int smem_fft = NFFT * sizeof(float2);   // 128 KB
    cudaFuncSetAttribute(k_fft_h,   cudaFuncAttributeMaxDynamicSharedMemorySize, smem_fft);
    cudaFuncSetAttribute(k_fftconv, cudaFuncAttributeMaxDynamicSharedMemorySize, smem_fft);

    k_twiddle<<<16, 512>>>();
    k_gemm_tc<0><<<dim3(128, 18), 256>>>(in_proj, x, nullptr);
    k_filter<<<LSEQ / FTL, 256>>>(mlp_w1, mlp_b1, mlp_w2, mlp_b2, mlp_w3, mlp_b3, log_dec);
    k_fft_h<<<DMOD / 2, 1024, smem_fft>>>();
    k_fftconv<<<BATCH * DMOD / 2, 1024, smem_fft>>>(sck_w, sck_b, scv_w, scv_b);
    k_gemm_tc<1><<<dim3(6, 128), 256>>>(nullptr, out_proj, out);
}

// round 10
// speedup vs baseline: 3.2207x; 1.1105x over previous
#include <cuda_runtime.h>
#include <cuda_bf16.h>
#include <cstdint>

// ---------------- problem constants ----------------
#define BATCH 2
#define LSEQ  8192
#define DMOD  768
#define NFFT  16384
#define LOGN  14
#define EMB   64

// ---------------- scratch ----------------
__device__ float  g_qT[BATCH * DMOD * LSEQ];
__device__ float  g_kT[BATCH * DMOD * LSEQ];
__device__ float  g_vT[BATCH * DMOD * LSEQ];
__device__ float  g_h [DMOD * LSEQ];
__device__ float2 g_Hf[DMOD * NFFT];           // filter spectrum, rev4-indexed
__device__ float  g_yg[BATCH * LSEQ * DMOD];
__device__ float2 g_tw[NFFT / 2];

__global__ void k_twiddle() {
    int i = blockIdx.x * blockDim.x + threadIdx.x;
    if (i < NFFT / 2) {
        double ang = -2.0 * 3.14159265358979323846 * (double)i / (double)NFFT;
        g_tw[i] = make_float2((float)cos(ang), (float)sin(ang));
    }
}

// ---------------- complex helpers ----------------
__device__ __forceinline__ float2 cmul(float2 a, float2 b) {
    return make_float2(a.x * b.x - a.y * b.y, a.x * b.y + a.y * b.x);
}
__device__ __forceinline__ float2 cmulc(float2 a, float2 b) {
    return make_float2(a.x * b.x + a.y * b.y, a.y * b.x - a.x * b.y);
}
__device__ __forceinline__ float2 cadd(float2 a, float2 b) { return make_float2(a.x + b.x, a.y + b.y); }
__device__ __forceinline__ float2 csub(float2 a, float2 b) { return make_float2(a.x - b.x, a.y - b.y); }

__device__ __forceinline__ int rev4_14(int x) {
    unsigned y = __brev((unsigned)x) >> (32 - 14);
    return (int)(((y & 0x1555u) << 1) | ((y >> 1) & 0x1555u));
}
// 6-digit base-4 reversal (12 bits)
__device__ __forceinline__ int rev4_6(int x) {
    unsigned y = __brev((unsigned)x) >> 20;
    return (int)(((y & 0x555u) << 1) | ((y >> 1) & 0x555u));
}

__device__ __forceinline__ int SWZ(int e) {
    int h = (e >> 4) & 15;
    return (e & ~15) | ((e ^ (5 * h)) & 15);
}

// radix-4 butterflies with precomputed twiddles
__device__ __forceinline__ void bfly_fwd_w(float2& x0, float2& x1, float2& x2, float2& x3,
                                           float2 w, float2 w2, float2 w3) {
    float2 t0 = cadd(x0, x2), t1 = csub(x0, x2), t2 = cadd(x1, x3);
    float2 t3 = make_float2(x1.y - x3.y, x3.x - x1.x);
    x0 = cadd(t0, t2);
    x1 = cmul(cadd(t1, t3), w);
    x2 = cmul(csub(t0, t2), w2);
    x3 = cmul(csub(t1, t3), w3);
}
__device__ __forceinline__ void bfly_inv_w(float2& x0, float2& x1, float2& x2, float2& x3,
                                           float2 w, float2 w2, float2 w3) {
    float2 c1 = cmulc(x1, w), c2 = cmulc(x2, w2), c3 = cmulc(x3, w3);
    float2 v0 = cadd(x0, c2), v1 = cadd(c1, c3), v2 = csub(x0, c2), v3 = csub(c1, c3);
    x0 = cadd(v0, v1);
    x1 = make_float2(v2.x - v3.y, v2.y + v3.x);
    x2 = csub(v0, v1);
    x3 = make_float2(v2.x + v3.y, v2.y - v3.x);
}
// twiddle-free variants (stage 6 fwd / stage 0 inv)
__device__ __forceinline__ void r4_fwd_nw(float2* z) {
    float2 t0 = cadd(z[0], z[2]), t1 = csub(z[0], z[2]), t2 = cadd(z[1], z[3]);
    float2 t3 = make_float2(z[1].y - z[3].y, z[3].x - z[1].x);
    z[0] = cadd(t0, t2); z[1] = cadd(t1, t3); z[2] = csub(t0, t2); z[3] = csub(t1, t3);
}
__device__ __forceinline__ void r4_inv_nw(float2* z) {
    float2 v0 = cadd(z[0], z[2]), v1 = cadd(z[1], z[3]), v2 = csub(z[0], z[2]), v3 = csub(z[1], z[3]);
    z[0] = cadd(v0, v1);
    z[1] = make_float2(v2.x - v3.y, v2.y + v3.x);
    z[2] = csub(v0, v1);
    z[3] = make_float2(v2.x + v3.y, v2.y - v3.x);
}

// ---- register-resident double-stage passes (16 elements / group, 1024 groups) ----
// forward stages (S, S+1); m = 4*M4; elements base + t*M4, t = 4a+b
template <int M4, int S>
__device__ __forceinline__ void fwd_pass2(float2* sm, int tid, int nthr) {
    for (int g = tid; g < 1024; g += nthr) {
        int j = g & (M4 - 1);
        int base = (g / M4) * (16 * M4) + j;
        float2 x[16];
#pragma unroll
        for (int t = 0; t < 16; t++) x[t] = sm[SWZ(base + t * M4)];
#pragma unroll
        for (int b = 0; b < 4; b++) {
            int e1 = (j + b * M4) << (2 * S);
            float2 w = g_tw[e1], w2 = g_tw[2 * e1], w3 = cmul(w, w2);
            bfly_fwd_w(x[b], x[4 + b], x[8 + b], x[12 + b], w, w2, w3);
        }
        {
            int e1 = j << (2 * (S + 1));
            float2 w = g_tw[e1], w2 = g_tw[2 * e1], w3 = cmul(w, w2);
#pragma unroll
            for (int a = 0; a < 4; a++)
                bfly_fwd_w(x[4 * a], x[4 * a + 1], x[4 * a + 2], x[4 * a + 3], w, w2, w3);
        }
#pragma unroll
        for (int t = 0; t < 16; t++) sm[SWZ(base + t * M4)] = x[t];
    }
    __syncthreads();
}

// inverse stages (S, S+1); M = 4^S; elements base + t*M, t = 4b+a
template <int M, int S>
__device__ __forceinline__ void inv_pass2(float2* sm, int tid, int nthr) {
    for (int g = tid; g < 1024; g += nthr) {
        int j = g & (M - 1);
        int base = (g / M) * (16 * M) + j;
        float2 x[16];
#pragma unroll
        for (int t = 0; t < 16; t++) x[t] = sm[SWZ(base + t * M)];
        {
            int e1 = j << (2 * (6 - S));
            float2 w = g_tw[e1], w2 = g_tw[2 * e1], w3 = cmul(w, w2);
#pragma unroll
            for (int b = 0; b < 4; b++)
                bfly_inv_w(x[4 * b], x[4 * b + 1], x[4 * b + 2], x[4 * b + 3], w, w2, w3);
        }
#pragma unroll
        for (int a = 0; a < 4; a++) {
            int e1 = (a * M + j) << (2 * (5 - S));
            float2 w = g_tw[e1], w2 = g_tw[2 * e1], w3 = cmul(w, w2);
            bfly_inv_w(x[a], x[4 + a], x[8 + a], x[12 + a], w, w2, w3);
        }
#pragma unroll
        for (int t = 0; t < 16; t++) sm[SWZ(base + t * M)] = x[t];
    }
    __syncthreads();
}

// ---------------- bf16 split helpers + tensor-core GEMM (unchanged from R8) ---------
__device__ __forceinline__ void split_pack(float x, float y, uint32_t& hi, uint32_t& lo) {
    __nv_bfloat16 xh = __float2bfloat16(x);
    __nv_bfloat16 yh = __float2bfloat16(y);
    __nv_bfloat16 xl = __float2bfloat16(x - __bfloat162float(xh));
    __nv_bfloat16 yl = __float2bfloat16(y - __bfloat162float(yh));
    hi = ((uint32_t)__bfloat16_as_ushort(yh) << 16) | (uint32_t)__bfloat16_as_ushort(xh);
    lo = ((uint32_t)__bfloat16_as_ushort(yl) << 16) | (uint32_t)__bfloat16_as_ushort(xl);
}

#define MMA_BF16(c, a, b)                                                     \
    asm volatile(                                                             \
        "mma.sync.aligned.m16n8k16.row.col.f32.bf16.bf16.f32 "                \
        "{%0,%1,%2,%3},{%4,%5,%6,%7},{%8,%9},{%0,%1,%2,%3};"                  \
        : "+f"(c[0]), "+f"(c[1]), "+f"(c[2]), "+f"(c[3])                      \
        : "r"(a[0]), "r"(a[1]), "r"(a[2]), "r"(a[3]), "r"(b[0]), "r"(b[1]))

#define BKP2 12
template <int EPI>
__global__ __launch_bounds__(256) void k_gemm_tc(const float* __restrict__ Aarg,
                                                 const float* __restrict__ B,
                                                 float* __restrict__ C) {
    __shared__ uint32_t Ah[128][BKP2], Al[128][BKP2];
    __shared__ uint32_t Bh[128][BKP2], Bl[128][BKP2];

    const float* A = (EPI == 1) ? (const float*)g_yg : Aarg;
    const int i0 = blockIdx.y * 128;
    const int j0 = blockIdx.x * 128;
    const int tid = threadIdx.x;
    const int wid = tid >> 5;
    const int lane = tid & 31;
    const int g  = lane >> 2;
    const int tg = lane & 3;
    const int wm = wid >> 2;
    const int wn = wid & 3;

    const int r0  = tid >> 2;
    const int kq0 = (tid & 3) * 4;
    const int cc0 = kq0 >> 1;
    const float* Ar0 = A + (size_t)(i0 + r0) * 768 + kq0;
    const float* Ar1 = A + (size_t)(i0 + r0 + 64) * 768 + kq0;
    const float* Br0 = B + (size_t)(j0 + r0) * 768 + kq0;
    const float* Br1 = B + (size_t)(j0 + r0 + 64) * 768 + kq0;

    float c[4][4][4];
#pragma unroll
    for (int mi = 0; mi < 4; mi++)
#pragma unroll
        for (int ni = 0; ni < 4; ni++)
#pragma unroll
            for (int r = 0; r < 4; r++) c[mi][ni][r] = 0.f;

    float4 va0 = *(const float4*)(Ar0);
    float4 va1 = *(const float4*)(Ar1);
    float4 vb0 = *(const float4*)(Br0);
    float4 vb1 = *(const float4*)(Br1);

    for (int kb = 0; kb < 768; kb += 16) {
        {
            uint32_t h0, l0, h1, l1;
            split_pack(va0.x, va0.y, h0, l0);
            split_pack(va0.z, va0.w, h1, l1);
            Ah[r0][cc0] = h0; Ah[r0][cc0 + 1] = h1;
            Al[r0][cc0] = l0; Al[r0][cc0 + 1] = l1;
            split_pack(va1.x, va1.y, h0, l0);
            split_pack(va1.z, va1.w, h1, l1);
            Ah[r0 + 64][cc0] = h0; Ah[r0 + 64][cc0 + 1] = h1;
            Al[r0 + 64][cc0] = l0; Al[r0 + 64][cc0 + 1] = l1;
            split_pack(vb0.x, vb0.y, h0, l0);
            split_pack(vb0.z, vb0.w, h1, l1);
            Bh[r0][cc0] = h0; Bh[r0][cc0 + 1] = h1;
            Bl[r0][cc0] = l0; Bl[r0][cc0 + 1] = l1;
            split_pack(vb1.x, vb1.y, h0, l0);
            split_pack(vb1.z, vb1.w, h1, l1);
            Bh[r0 + 64][cc0] = h0; Bh[r0 + 64][cc0 + 1] = h1;
            Bl[r0 + 64][cc0] = l0; Bl[r0 + 64][cc0 + 1] = l1;
        }
        __syncthreads();

        if (kb + 16 < 768) {
            va0 = *(const float4*)(Ar0 + kb + 16);
            va1 = *(const float4*)(Ar1 + kb + 16);
            vb0 = *(const float4*)(Br0 + kb + 16);
            vb1 = *(const float4*)(Br1 + kb + 16);
        }

        uint32_t ah[4][4], al[4][4], bh[4][2], bl[4][2];
#pragma unroll
        for (int mi = 0; mi < 4; mi++) {
            int m = wm * 64 + mi * 16;
            ah[mi][0] = Ah[m + g][tg];
            ah[mi][1] = Ah[m + g + 8][tg];
            ah[mi][2] = Ah[m + g][tg + 4];
            ah[mi][3] = Ah[m + g + 8][tg + 4];
            al[mi][0] = Al[m + g][tg];
            al[mi][1] = Al[m + g + 8][tg];
            al[mi][2] = Al[m + g][tg + 4];
            al[mi][3] = Al[m + g + 8][tg + 4];
        }
#pragma unroll
        for (int ni = 0; ni < 4; ni++) {
            int n = wn * 32 + ni * 8;
            bh[ni][0] = Bh[n + g][tg];
            bh[ni][1] = Bh[n + g][tg + 4];
            bl[ni][0] = Bl[n + g][tg];
            bl[ni][1] = Bl[n + g][tg + 4];
        }
#pragma unroll
        for (int mi = 0; mi < 4; mi++)
#pragma unroll
            for (int ni = 0; ni < 4; ni++) {
                MMA_BF16(c[mi][ni], ah[mi], bh[ni]);
                MMA_BF16(c[mi][ni], al[mi], bh[ni]);
                MMA_BF16(c[mi][ni], ah[mi], bl[ni]);
            }
        __syncthreads();
    }

#pragma unroll
    for (int mi = 0; mi < 4; mi++) {
#pragma unroll
        for (int ni = 0; ni < 4; ni++) {
            int rm0 = i0 + wm * 64 + mi * 16 + g;
            int rm1 = rm0 + 8;
            int cn  = j0 + wn * 32 + ni * 8 + 2 * tg;
            if (EPI == 0) {
                int part0 = rm0 / DMOD, dch0 = rm0 - part0 * DMOD;
                int part1 = rm1 / DMOD, dch1 = rm1 - part1 * DMOD;
                float* t0 = (part0 == 0) ? g_qT : (part0 == 1 ? g_kT : g_vT);
                float* t1 = (part1 == 0) ? g_qT : (part1 == 1 ? g_kT : g_vT);
                int bb = cn >> 13;
                int l  = cn & (LSEQ - 1);
                *(float2*)(t0 + ((size_t)bb * DMOD + dch0) * LSEQ + l) =
                    make_float2(c[mi][ni][0], c[mi][ni][1]);
                *(float2*)(t1 + ((size_t)bb * DMOD + dch1) * LSEQ + l) =
                    make_float2(c[mi][ni][2], c[mi][ni][3]);
            } else {
                *(float2*)(C + (size_t)rm0 * DMOD + cn) =
                    make_float2(c[mi][ni][0], c[mi][ni][1]);
                *(float2*)(C + (size_t)rm1 * DMOD + cn) =
                    make_float2(c[mi][ni][2], c[mi][ni][3]);
            }
        }
    }
}

// ---------------- hyena filter MLP + decay (unchanged) ----------------
#define FTL 32
__global__ __launch_bounds__(256) void k_filter(const float* __restrict__ w1, const float* __restrict__ b1,
                                                const float* __restrict__ w2, const float* __restrict__ b2,
                                                const float* __restrict__ w3, const float* __restrict__ b3,
                                                const float* __restrict__ ld) {
    __shared__ float ws [EMB][EMB + 1];
    __shared__ float pe [FTL][EMB + 1];
    __shared__ float h1s[FTL][EMB + 1];
    __shared__ float h2s[FTL][EMB + 1];
    const int l0 = blockIdx.x * FTL;
    const int tid = threadIdx.x;
    const float TWO_PI = 6.2831853071795864769f;
    const float inv = 1.0f / (float)(LSEQ - 1);

    for (int idx = tid; idx < EMB * EMB; idx += 256)
        ws[idx >> 6][idx & 63] = w1[idx];
    for (int idx = tid; idx < FTL * EMB; idx += 256) {
        int li = idx >> 6, e = idx & 63;
        float t = (float)(l0 + li) * inv;
        pe[li][e] = (e < 32) ? sinf(t * TWO_PI * (float)(e + 1))
                             : cosf(t * TWO_PI * (float)(e - 31));
    }
    __syncthreads();
    for (int idx = tid; idx < FTL * EMB; idx += 256) {
        int li = idx >> 6, e = idx & 63;
        float s = b1[e];
#pragma unroll 16
        for (int cc = 0; cc < EMB; cc++) s += pe[li][cc] * ws[e][cc];
        h1s[li][e] = s / (1.f + __expf(-s));
    }
    __syncthreads();
    for (int idx = tid; idx < EMB * EMB; idx += 256)
        ws[idx >> 6][idx & 63] = w2[idx];
    __syncthreads();
    for (int idx = tid; idx < FTL * EMB; idx += 256) {
        int li = idx >> 6, e = idx & 63;
        float s = b2[e];
#pragma unroll 16
        for (int cc = 0; cc < EMB; cc++) s += h1s[li][cc] * ws[e][cc];
        h2s[li][e] = s / (1.f + __expf(-s));
    }
    __syncthreads();
    for (int d = tid; d < DMOD; d += 256) {
        float a = fabsf(ld[d]);
        float* outp = g_h + (size_t)d * LSEQ + l0;
        if (a * (float)l0 > 100.f) {
#pragma unroll
            for (int li = 0; li < FTL; li++) outp[li] = 0.f;
            continue;
        }
        float acc[FTL];
#pragma unroll
        for (int li = 0; li < FTL; li++) acc[li] = 0.f;
        const float* w3r = w3 + d * EMB;
#pragma unroll 8
        for (int e = 0; e < EMB; e++) {
            float wv = w3r[e];
#pragma unroll
            for (int li = 0; li < FTL; li++) acc[li] += h2s[li][e] * wv;
        }
        float b3d = b3[d];
        float dec  = __expf(-a * (float)l0);
        float step = __expf(-a);
#pragma unroll
        for (int li = 0; li < FTL; li++) {
            outp[li] = (acc[li] + b3d) * dec;
            dec *= step;
        }
    }
}

// ---------------- filter spectrum: radix-16 passes + fused stage6/unpack -------------
__global__ __launch_bounds__(512) void k_fft_h() {
    extern __shared__ float2 sm[];
    const int c = blockIdx.x;
    const int d0 = 2 * c, d1 = 2 * c + 1;
    const int tid = threadIdx.x, nthr = blockDim.x;
    const float* s0 = g_h + (size_t)d0 * LSEQ;
    const float* s1 = g_h + (size_t)d1 * LSEQ;

    // pass A: load pair + fwd stages 0,1 in regs
    for (int j = tid; j < 1024; j += nthr) {
        float2 x[16];
#pragma unroll
        for (int t = 0; t < 8; t++) {
            int l = j + t * 1024;
            x[t] = make_float2(s0[l], s1[l]);
        }
#pragma unroll
        for (int b = 0; b < 4; b++) {
            int e1 = j + b * 1024;
            float2 w = g_tw[e1], w2 = g_tw[2 * e1], w3 = cmul(w, w2);
            float2 a0 = x[b], a1 = x[4 + b];
            x[b]      = cadd(a0, a1);
            x[4 + b]  = cmul(make_float2(a0.x + a1.y, a0.y - a1.x), w);
            x[8 + b]  = cmul(csub(a0, a1), w2);
            x[12 + b] = cmul(make_float2(a0.x - a1.y, a0.y + a1.x), w3);
        }
        {
            int e1 = j << 2;
            float2 w = g_tw[e1], w2 = g_tw[2 * e1], w3 = cmul(w, w2);
#pragma unroll
            for (int a = 0; a < 4; a++)
                bfly_fwd_w(x[4 * a], x[4 * a + 1], x[4 * a + 2], x[4 * a + 3], w, w2, w3);
        }
#pragma unroll
        for (int t = 0; t < 16; t++) sm[SWZ(j + t * 1024)] = x[t];
    }
    __syncthreads();

    fwd_pass2<64, 2>(sm, tid, nthr);
    fwd_pass2<4, 4>(sm, tid, nthr);

    // fused: fwd stage 6 (twiddle-free) + unpack + store (group-paired)
    float2* Ha = g_Hf + (size_t)d0 * NFFT;
    float2* Hb = g_Hf + (size_t)d1 * NFFT;
    for (int i = tid; i < 4096; i += nthr) {
        int r = rev4_6(i);
        int i2 = (r == 0) ? 0 : rev4_6(4096 - r);
        if (i2 < i) continue;
        float2 z[4], zz[4];
#pragma unroll
        for (int t = 0; t < 4; t++) z[t] = sm[SWZ(4 * i + t)];
        r4_fwd_nw(z);
        bool self = (i2 == i);
        if (!self) {
#pragma unroll
            for (int t = 0; t < 4; t++) zz[t] = sm[SWZ(4 * i2 + t)];
            r4_fwd_nw(zz);
        }
#pragma unroll
        for (int t = 0; t < 4; t++) {
            int tp = (i == 0) ? ((4 - t) & 3) : (3 - t);
            float2 z1 = z[t];
            float2 z2 = self ? z[tp] : zz[tp];
            float2 ha = make_float2(0.5f * (z1.x + z2.x), 0.5f * (z1.y - z2.y));
            float2 hb = make_float2(0.5f * (z1.y + z2.y), 0.5f * (z2.x - z1.x));
            int p = 4 * i + t;
            int q = 4 * i2 + tp;
            Ha[p] = ha;
            Hb[p] = hb;
            Ha[q] = make_float2(ha.x, -ha.y);
            Hb[q] = make_float2(hb.x, -hb.y);
        }
    }
}

// ---- fused fftconv: conv -> FFT (reg radix-16) -> xH -> IFFT -> gate -> yg ----------
__global__ __launch_bounds__(512) void k_fftconv(const float* __restrict__ skw, const float* __restrict__ skb,
                                                 const float* __restrict__ svw, const float* __restrict__ svb) {
    extern __shared__ float2 sm[];
    const int bc = blockIdx.x;
    const int b = bc / (DMOD / 2);
    const int c = bc - b * (DMOD / 2);
    const int d0 = 2 * c, d1 = 2 * c + 1;
    const int tid = threadIdx.x, nthr = blockDim.x;

    const float* k0 = g_kT + ((size_t)b * DMOD + d0) * LSEQ;
    const float* k1 = g_kT + ((size_t)b * DMOD + d1) * LSEQ;
    const float* v0 = g_vT + ((size_t)b * DMOD + d0) * LSEQ;
    const float* v1 = g_vT + ((size_t)b * DMOD + d1) * LSEQ;

    float kw00 = skw[d0 * 3], kw01 = skw[d0 * 3 + 1], kw02 = skw[d0 * 3 + 2], kb0 = skb[d0];
    float vw00 = svw[d0 * 3], vw01 = svw[d0 * 3 + 1], vw02 = svw[d0 * 3 + 2], vb0 = svb[d0];
    float kw10 = skw[d1 * 3], kw11 = skw[d1 * 3 + 1], kw12 = skw[d1 * 3 + 2], kb1 = skb[d1];
    float vw10 = svw[d1 * 3], vw11 = svw[d1 * 3 + 1], vw12 = svw[d1 * 3 + 2], vb1 = svb[d1];

#define UPAIR(l, out)                                                                   \
    {                                                                                   \
        int _l = (l);                                                                   \
        float ka2 = k0[_l];                                                             \
        float ka1 = (_l >= 1) ? k0[_l - 1] : 0.f;                                       \
        float ka0 = (_l >= 2) ? k0[_l - 2] : 0.f;                                       \
        float va2 = v0[_l];                                                             \
        float va1 = (_l >= 1) ? v0[_l - 1] : 0.f;                                       \
        float va0 = (_l >= 2) ? v0[_l - 2] : 0.f;                                       \
        float u0 = (kw00 * ka0 + kw01 * ka1 + kw02 * ka2 + kb0) *                       \
                   (vw00 * va0 + vw01 * va1 + vw02 * va2 + vb0);                        \
        float kb2_ = k1[_l];                                                            \
        float kb1_ = (_l >= 1) ? k1[_l - 1] : 0.f;                                      \
        float kb0_ = (_l >= 2) ? k1[_l - 2] : 0.f;                                      \
        float vb2_ = v1[_l];                                                            \
        float vb1_ = (_l >= 1) ? v1[_l - 1] : 0.f;                                      \
        float vb0_ = (_l >= 2) ? v1[_l - 2] : 0.f;                                      \
        float u1 = (kw10 * kb0_ + kw11 * kb1_ + kw12 * kb2_ + kb1) *                    \
                   (vw10 * vb0_ + vw11 * vb1_ + vw12 * vb2_ + vb1);                     \
        out = make_float2(u0, u1);                                                      \
    }

    // pass A: conv + fwd stages 0,1
    for (int j = tid; j < 1024; j += nthr) {
        float2 x[16];
#pragma unroll
        for (int t = 0; t < 8; t++) { UPAIR(j + t * 1024, x[t]); }
#pragma unroll
        for (int bb2 = 0; bb2 < 4; bb2++) {
            int e1 = j + bb2 * 1024;
            float2 w = g_tw[e1], w2 = g_tw[2 * e1], w3 = cmul(w, w2);
            float2 a0 = x[bb2], a1 = x[4 + bb2];
            x[bb2]      = cadd(a0, a1);
            x[4 + bb2]  = cmul(make_float2(a0.x + a1.y, a0.y - a1.x), w);
            x[8 + bb2]  = cmul(csub(a0, a1), w2);
            x[12 + bb2] = cmul(make_float2(a0.x - a1.y, a0.y + a1.x), w3);
        }
        {
            int e1 = j << 2;
            float2 w = g_tw[e1], w2 = g_tw[2 * e1], w3 = cmul(w, w2);
#pragma unroll
            for (int a = 0; a < 4; a++)
                bfly_fwd_w(x[4 * a], x[4 * a + 1], x[4 * a + 2], x[4 * a + 3], w, w2, w3);
        }
#pragma unroll
        for (int t = 0; t < 16; t++) sm[SWZ(j + t * 1024)] = x[t];
    }
#undef UPAIR
    __syncthreads();

    fwd_pass2<64, 2>(sm, tid, nthr);
    fwd_pass2<4, 4>(sm, tid, nthr);

    // merged middle: fwd stage 6 + spectral multiply + inv stage 0 (group-paired)
    {
        const float2* Ha = g_Hf + (size_t)d0 * NFFT;
        const float2* Hb = g_Hf + (size_t)d1 * NFFT;
        const float hscale = 0.5f / (float)NFFT;
        for (int i = tid; i < 4096; i += nthr) {
            int r = rev4_6(i);
            int i2 = (r == 0) ? 0 : rev4_6(4096 - r);
            if (i2 < i) continue;
            float2 z[4], zz[4];
#pragma unroll
            for (int t = 0; t < 4; t++) z[t] = sm[SWZ(4 * i + t)];
            r4_fwd_nw(z);
            bool self = (i2 == i);
            if (!self) {
#pragma unroll
                for (int t = 0; t < 4; t++) zz[t] = sm[SWZ(4 * i2 + t)];
                r4_fwd_nw(zz);
            }
            float2 o1[4], o2[4];
#pragma unroll
            for (int t = 0; t < 4; t++) {
                int tp = (i == 0) ? ((4 - t) & 3) : (3 - t);
                float2 z1 = z[t];
                float2 z2 = self ? z[tp] : zz[tp];
                float2 za = make_float2(hscale * (z1.x + z2.x), hscale * (z1.y - z2.y));
                float2 zb = make_float2(hscale * (z1.y + z2.y), hscale * (z2.x - z1.x));
                int p = 4 * i + t;
                float2 ya = cmul(za, Ha[p]);
                float2 yb = cmul(zb, Hb[p]);
                o1[t]  = make_float2(ya.x - yb.y, ya.y + yb.x);
                o2[tp] = make_float2(ya.x + yb.y, yb.x - ya.y);
            }
            r4_inv_nw(o1);
#pragma unroll
            for (int t = 0; t < 4; t++) sm[SWZ(4 * i + t)] = o1[t];
            if (!self) {
                r4_inv_nw(o2);
#pragma unroll
                for (int t = 0; t < 4; t++) sm[SWZ(4 * i2 + t)] = o2[t];
            }
        }
    }
    __syncthreads();

    inv_pass2<4, 1>(sm, tid, nthr);
    inv_pass2<64, 3>(sm, tid, nthr);

    // pass G: inv stages 5,6 + gate + store (only l < 8192 outputs)
    const float* q0 = g_qT + ((size_t)b * DMOD + d0) * LSEQ;
    const float* q1 = g_qT + ((size_t)b * DMOD + d1) * LSEQ;
    for (int j = tid; j < 1024; j += nthr) {
        float2 x[16];
#pragma unroll
        for (int t = 0; t < 16; t++) x[t] = sm[SWZ(j + t * 1024)];
        {
            int e1 = j << 2;
            float2 w = g_tw[e1], w2 = g_tw[2 * e1], w3 = cmul(w, w2);
#pragma unroll
            for (int bb2 = 0; bb2 < 4; bb2++)
                bfly_inv_w(x[4 * bb2], x[4 * bb2 + 1], x[4 * bb2 + 2], x[4 * bb2 + 3], w, w2, w3);
        }
#pragma unroll
        for (int a = 0; a < 4; a++) {
            int e1 = a * 1024 + j;
            float2 w = g_tw[e1], w2 = g_tw[2 * e1], w3 = cmul(w, w2);
            float2 c1 = cmulc(x[4 + a], w);
            float2 c2 = cmulc(x[8 + a], w2);
            float2 c3 = cmulc(x[12 + a], w3);
            float2 v0 = cadd(x[a], c2);
            float2 v1 = cadd(c1, c3);
            float2 v2 = csub(x[a], c2);
            float2 v3 = csub(c1, c3);
            float2 y0 = cadd(v0, v1);                           // l = j + a*1024
            float2 y1 = make_float2(v2.x - v3.y, v2.y + v3.x);  // l = j + a*1024 + 4096
            {
                int l = j + a * 1024;
                float qa = q0[l], qb = q1[l];
                float ga = qa / (1.f + __expf(-qa));
                float gb = qb / (1.f + __expf(-qb));
                *(float2*)&g_yg[((size_t)b * LSEQ + l) * DMOD + d0] = make_float2(ga * y0.x, gb * y0.y);
            }
            {
                int l = j + a * 1024 + 4096;
                float qa = q0[l], qb = q1[l];
                float ga = qa / (1.f + __expf(-qa));
                float gb = qb / (1.f + __expf(-qb));
                *(float2*)&g_yg[((size_t)b * LSEQ + l) * DMOD + d0] = make_float2(ga * y1.x, gb * y1.y);
            }
        }
    }
}

// ---------------- launch ----------------
extern "C" void kernel_launch(void* const* d_in, const int* in_sizes, int n_in,
                              void* d_out, int out_size) {
    const float* x        = (const float*)d_in[0];
    const float* in_proj  = (const float*)d_in[1];
    const float* sck_w    = (const float*)d_in[2];
    const float* sck_b    = (const float*)d_in[3];
    const float* scv_w    = (const float*)d_in[4];
    const float* scv_b    = (const float*)d_in[5];
    const float* mlp_w1   = (const float*)d_in[6];
    const float* mlp_b1   = (const float*)d_in[7];
    const float* mlp_w2   = (const float*)d_in[8];
    const float* mlp_b2   = (const float*)d_in[9];
    const float* mlp_w3   = (const float*)d_in[10];
    const float* mlp_b3   = (const float*)d_in[11];
    const float* log_dec  = (const float*)d_in[12];
    const float* out_proj = (const float*)d_in[13];
    float* out = (float*)d_out;

    const int smem_fft = NFFT * sizeof(float2);   // 128 KB
    cudaFuncSetAttribute(k_fft_h,   cudaFuncAttributeMaxDynamicSharedMemorySize, smem_fft);
    cudaFuncSetAttribute(k_fftconv, cudaFuncAttributeMaxDynamicSharedMemorySize, smem_fft);

    k_twiddle<<<16, 512>>>();
    k_gemm_tc<0><<<dim3(128, 18), 256>>>(in_proj, x, nullptr);
    k_filter<<<LSEQ / FTL, 256>>>(mlp_w1, mlp_b1, mlp_w2, mlp_b2, mlp_w3, mlp_b3, log_dec);
    k_fft_h<<<DMOD / 2, 512, smem_fft>>>();
    k_fftconv<<<BATCH * DMOD / 2, 512, smem_fft>>>(sck_w, sck_b, scv_w, scv_b);
    k_gemm_tc<1><<<dim3(6, 128), 256>>>(nullptr, out_proj, out);
}

// round 11
// speedup vs baseline: 3.3120x; 1.0283x over previous
#include <cuda_runtime.h>
#include <cuda_bf16.h>
#include <cstdint>

// ---------------- problem constants ----------------
#define BATCH 2
#define LSEQ  8192
#define DMOD  768
#define NFFT  16384
#define LOGN  14
#define EMB   64

// ---------------- scratch ----------------
__device__ float  g_qT[BATCH * DMOD * LSEQ];
__device__ float  g_kT[BATCH * DMOD * LSEQ];
__device__ float  g_vT[BATCH * DMOD * LSEQ];
__device__ float  g_h [DMOD * LSEQ];
__device__ float2 g_Hf[DMOD * NFFT];           // filter spectrum, rev4-indexed
__device__ float  g_yg[BATCH * LSEQ * DMOD];
__device__ float2 g_tw[NFFT / 2];

__global__ void k_twiddle() {
    int i = blockIdx.x * blockDim.x + threadIdx.x;
    if (i < NFFT / 2) {
        double ang = -2.0 * 3.14159265358979323846 * (double)i / (double)NFFT;
        g_tw[i] = make_float2((float)cos(ang), (float)sin(ang));
    }
}

// ---------------- complex helpers ----------------
__device__ __forceinline__ float2 cmul(float2 a, float2 b) {
    return make_float2(a.x * b.x - a.y * b.y, a.x * b.y + a.y * b.x);
}
__device__ __forceinline__ float2 cmulc(float2 a, float2 b) {
    return make_float2(a.x * b.x + a.y * b.y, a.y * b.x - a.x * b.y);
}
__device__ __forceinline__ float2 cadd(float2 a, float2 b) { return make_float2(a.x + b.x, a.y + b.y); }
__device__ __forceinline__ float2 csub(float2 a, float2 b) { return make_float2(a.x - b.x, a.y - b.y); }

__device__ __forceinline__ int rev4_6(int x) {
    unsigned y = __brev((unsigned)x) >> 20;
    return (int)(((y & 0x555u) << 1) | ((y >> 1) & 0x555u));
}

__device__ __forceinline__ int SWZ(int e) {
    int h = (e >> 4) & 15;
    return (e & ~15) | ((e ^ (5 * h)) & 15);
}

__device__ __forceinline__ void bfly_fwd_w(float2& x0, float2& x1, float2& x2, float2& x3,
                                           float2 w, float2 w2, float2 w3) {
    float2 t0 = cadd(x0, x2), t1 = csub(x0, x2), t2 = cadd(x1, x3);
    float2 t3 = make_float2(x1.y - x3.y, x3.x - x1.x);
    x0 = cadd(t0, t2);
    x1 = cmul(cadd(t1, t3), w);
    x2 = cmul(csub(t0, t2), w2);
    x3 = cmul(csub(t1, t3), w3);
}
__device__ __forceinline__ void bfly_inv_w(float2& x0, float2& x1, float2& x2, float2& x3,
                                           float2 w, float2 w2, float2 w3) {
    float2 c1 = cmulc(x1, w), c2 = cmulc(x2, w2), c3 = cmulc(x3, w3);
    float2 v0 = cadd(x0, c2), v1 = cadd(c1, c3), v2 = csub(x0, c2), v3 = csub(c1, c3);
    x0 = cadd(v0, v1);
    x1 = make_float2(v2.x - v3.y, v2.y + v3.x);
    x2 = csub(v0, v1);
    x3 = make_float2(v2.x + v3.y, v2.y - v3.x);
}
__device__ __forceinline__ void r4_fwd_nw(float2* z) {
    float2 t0 = cadd(z[0], z[2]), t1 = csub(z[0], z[2]), t2 = cadd(z[1], z[3]);
    float2 t3 = make_float2(z[1].y - z[3].y, z[3].x - z[1].x);
    z[0] = cadd(t0, t2); z[1] = cadd(t1, t3); z[2] = csub(t0, t2); z[3] = csub(t1, t3);
}
__device__ __forceinline__ void r4_inv_nw(float2* z) {
    float2 v0 = cadd(z[0], z[2]), v1 = cadd(z[1], z[3]), v2 = csub(z[0], z[2]), v3 = csub(z[1], z[3]);
    z[0] = cadd(v0, v1);
    z[1] = make_float2(v2.x - v3.y, v2.y + v3.x);
    z[2] = csub(v0, v1);
    z[3] = make_float2(v2.x + v3.y, v2.y - v3.x);
}

template <int M4, int S>
__device__ __forceinline__ void fwd_pass2(float2* sm, int tid, int nthr) {
    for (int g = tid; g < 1024; g += nthr) {
        int j = g & (M4 - 1);
        int base = (g / M4) * (16 * M4) + j;
        float2 x[16];
#pragma unroll
        for (int t = 0; t < 16; t++) x[t] = sm[SWZ(base + t * M4)];
#pragma unroll
        for (int b = 0; b < 4; b++) {
            int e1 = (j + b * M4) << (2 * S);
            float2 w = g_tw[e1], w2 = g_tw[2 * e1], w3 = cmul(w, w2);
            bfly_fwd_w(x[b], x[4 + b], x[8 + b], x[12 + b], w, w2, w3);
        }
        {
            int e1 = j << (2 * (S + 1));
            float2 w = g_tw[e1], w2 = g_tw[2 * e1], w3 = cmul(w, w2);
#pragma unroll
            for (int a = 0; a < 4; a++)
                bfly_fwd_w(x[4 * a], x[4 * a + 1], x[4 * a + 2], x[4 * a + 3], w, w2, w3);
        }
#pragma unroll
        for (int t = 0; t < 16; t++) sm[SWZ(base + t * M4)] = x[t];
    }
    __syncthreads();
}

template <int M, int S>
__device__ __forceinline__ void inv_pass2(float2* sm, int tid, int nthr) {
    for (int g = tid; g < 1024; g += nthr) {
        int j = g & (M - 1);
        int base = (g / M) * (16 * M) + j;
        float2 x[16];
#pragma unroll
        for (int t = 0; t < 16; t++) x[t] = sm[SWZ(base + t * M)];
        {
            int e1 = j << (2 * (6 - S));
            float2 w = g_tw[e1], w2 = g_tw[2 * e1], w3 = cmul(w, w2);
#pragma unroll
            for (int b = 0; b < 4; b++)
                bfly_inv_w(x[4 * b], x[4 * b + 1], x[4 * b + 2], x[4 * b + 3], w, w2, w3);
        }
#pragma unroll
        for (int a = 0; a < 4; a++) {
            int e1 = (a * M + j) << (2 * (5 - S));
            float2 w = g_tw[e1], w2 = g_tw[2 * e1], w3 = cmul(w, w2);
            bfly_inv_w(x[a], x[4 + a], x[8 + a], x[12 + a], w, w2, w3);
        }
#pragma unroll
        for (int t = 0; t < 16; t++) sm[SWZ(base + t * M)] = x[t];
    }
    __syncthreads();
}

// ---------------- bf16 split helpers + tensor-core GEMM ----------------
__device__ __forceinline__ void split_pack(float x, float y, uint32_t& hi, uint32_t& lo) {
    __nv_bfloat16 xh = __float2bfloat16(x);
    __nv_bfloat16 yh = __float2bfloat16(y);
    __nv_bfloat16 xl = __float2bfloat16(x - __bfloat162float(xh));
    __nv_bfloat16 yl = __float2bfloat16(y - __bfloat162float(yh));
    hi = ((uint32_t)__bfloat16_as_ushort(yh) << 16) | (uint32_t)__bfloat16_as_ushort(xh);
    lo = ((uint32_t)__bfloat16_as_ushort(yl) << 16) | (uint32_t)__bfloat16_as_ushort(xl);
}

#define MMA_BF16(c, a, b)                                                     \
    asm volatile(                                                             \
        "mma.sync.aligned.m16n8k16.row.col.f32.bf16.bf16.f32 "                \
        "{%0,%1,%2,%3},{%4,%5,%6,%7},{%8,%9},{%0,%1,%2,%3};"                  \
        : "+f"(c[0]), "+f"(c[1]), "+f"(c[2]), "+f"(c[3])                      \
        : "r"(a[0]), "r"(a[1]), "r"(a[2]), "r"(a[3]), "r"(b[0]), "r"(b[1]))

#define BKP2 12
template <int EPI>
__global__ __launch_bounds__(256) void k_gemm_tc(const float* __restrict__ Aarg,
                                                 const float* __restrict__ B,
                                                 float* __restrict__ C) {
    __shared__ uint32_t Ah[128][BKP2], Al[128][BKP2];
    __shared__ uint32_t Bh[128][BKP2], Bl[128][BKP2];

    const float* A = (EPI == 1) ? (const float*)g_yg : Aarg;
    const int i0 = blockIdx.y * 128;
    const int j0 = blockIdx.x * 128;
    const int tid = threadIdx.x;
    const int wid = tid >> 5;
    const int lane = tid & 31;
    const int g  = lane >> 2;
    const int tg = lane & 3;
    const int wm = wid >> 2;
    const int wn = wid & 3;

    const int r0  = tid >> 2;
    const int kq0 = (tid & 3) * 4;
    const int cc0 = kq0 >> 1;
    const float* Ar0 = A + (size_t)(i0 + r0) * 768 + kq0;
    const float* Ar1 = A + (size_t)(i0 + r0 + 64) * 768 + kq0;
    const float* Br0 = B + (size_t)(j0 + r0) * 768 + kq0;
    const float* Br1 = B + (size_t)(j0 + r0 + 64) * 768 + kq0;

    float c[4][4][4];
#pragma unroll
    for (int mi = 0; mi < 4; mi++)
#pragma unroll
        for (int ni = 0; ni < 4; ni++)
#pragma unroll
            for (int r = 0; r < 4; r++) c[mi][ni][r] = 0.f;

    float4 va0 = *(const float4*)(Ar0);
    float4 va1 = *(const float4*)(Ar1);
    float4 vb0 = *(const float4*)(Br0);
    float4 vb1 = *(const float4*)(Br1);

    for (int kb = 0; kb < 768; kb += 16) {
        {
            uint32_t h0, l0, h1, l1;
            split_pack(va0.x, va0.y, h0, l0);
            split_pack(va0.z, va0.w, h1, l1);
            Ah[r0][cc0] = h0; Ah[r0][cc0 + 1] = h1;
            Al[r0][cc0] = l0; Al[r0][cc0 + 1] = l1;
            split_pack(va1.x, va1.y, h0, l0);
            split_pack(va1.z, va1.w, h1, l1);
            Ah[r0 + 64][cc0] = h0; Ah[r0 + 64][cc0 + 1] = h1;
            Al[r0 + 64][cc0] = l0; Al[r0 + 64][cc0 + 1] = l1;
            split_pack(vb0.x, vb0.y, h0, l0);
            split_pack(vb0.z, vb0.w, h1, l1);
            Bh[r0][cc0] = h0; Bh[r0][cc0 + 1] = h1;
            Bl[r0][cc0] = l0; Bl[r0][cc0 + 1] = l1;
            split_pack(vb1.x, vb1.y, h0, l0);
            split_pack(vb1.z, vb1.w, h1, l1);
            Bh[r0 + 64][cc0] = h0; Bh[r0 + 64][cc0 + 1] = h1;
            Bl[r0 + 64][cc0] = l0; Bl[r0 + 64][cc0 + 1] = l1;
        }
        __syncthreads();

        if (kb + 16 < 768) {
            va0 = *(const float4*)(Ar0 + kb + 16);
            va1 = *(const float4*)(Ar1 + kb + 16);
            vb0 = *(const float4*)(Br0 + kb + 16);
            vb1 = *(const float4*)(Br1 + kb + 16);
        }

        uint32_t ah[4][4], al[4][4], bh[4][2], bl[4][2];
#pragma unroll
        for (int mi = 0; mi < 4; mi++) {
            int m = wm * 64 + mi * 16;
            ah[mi][0] = Ah[m + g][tg];
            ah[mi][1] = Ah[m + g + 8][tg];
            ah[mi][2] = Ah[m + g][tg + 4];
            ah[mi][3] = Ah[m + g + 8][tg + 4];
            al[mi][0] = Al[m + g][tg];
            al[mi][1] = Al[m + g + 8][tg];
            al[mi][2] = Al[m + g][tg + 4];
            al[mi][3] = Al[m + g + 8][tg + 4];
        }
#pragma unroll
        for (int ni = 0; ni < 4; ni++) {
            int n = wn * 32 + ni * 8;
            bh[ni][0] = Bh[n + g][tg];
            bh[ni][1] = Bh[n + g][tg + 4];
            bl[ni][0] = Bl[n + g][tg];
            bl[ni][1] = Bl[n + g][tg + 4];
        }
#pragma unroll
        for (int mi = 0; mi < 4; mi++)
#pragma unroll
            for (int ni = 0; ni < 4; ni++) {
                MMA_BF16(c[mi][ni], ah[mi], bh[ni]);
                MMA_BF16(c[mi][ni], al[mi], bh[ni]);
                MMA_BF16(c[mi][ni], ah[mi], bl[ni]);
            }
        __syncthreads();
    }

#pragma unroll
    for (int mi = 0; mi < 4; mi++) {
#pragma unroll
        for (int ni = 0; ni < 4; ni++) {
            int rm0 = i0 + wm * 64 + mi * 16 + g;
            int rm1 = rm0 + 8;
            int cn  = j0 + wn * 32 + ni * 8 + 2 * tg;
            if (EPI == 0) {
                int part0 = rm0 / DMOD, dch0 = rm0 - part0 * DMOD;
                int part1 = rm1 / DMOD, dch1 = rm1 - part1 * DMOD;
                float* t0 = (part0 == 0) ? g_qT : (part0 == 1 ? g_kT : g_vT);
                float* t1 = (part1 == 0) ? g_qT : (part1 == 1 ? g_kT : g_vT);
                int bb = cn >> 13;
                int l  = cn & (LSEQ - 1);
                *(float2*)(t0 + ((size_t)bb * DMOD + dch0) * LSEQ + l) =
                    make_float2(c[mi][ni][0], c[mi][ni][1]);
                *(float2*)(t1 + ((size_t)bb * DMOD + dch1) * LSEQ + l) =
                    make_float2(c[mi][ni][2], c[mi][ni][3]);
            } else {
                *(float2*)(C + (size_t)rm0 * DMOD + cn) =
                    make_float2(c[mi][ni][0], c[mi][ni][1]);
                *(float2*)(C + (size_t)rm1 * DMOD + cn) =
                    make_float2(c[mi][ni][2], c[mi][ni][3]);
            }
        }
    }
}

// ---------------- hyena filter MLP + decay ----------------
#define FTL 32
__global__ __launch_bounds__(256) void k_filter(const float* __restrict__ w1, const float* __restrict__ b1,
                                                const float* __restrict__ w2, const float* __restrict__ b2,
                                                const float* __restrict__ w3, const float* __restrict__ b3,
                                                const float* __restrict__ ld) {
    __shared__ float ws [EMB][EMB + 1];
    __shared__ float pe [FTL][EMB + 1];
    __shared__ float h1s[FTL][EMB + 1];
    __shared__ float h2s[FTL][EMB + 1];
    const int l0 = blockIdx.x * FTL;
    const int tid = threadIdx.x;
    const float TWO_PI = 6.2831853071795864769f;
    const float inv = 1.0f / (float)(LSEQ - 1);

    for (int idx = tid; idx < EMB * EMB; idx += 256)
        ws[idx >> 6][idx & 63] = w1[idx];
    for (int idx = tid; idx < FTL * EMB; idx += 256) {
        int li = idx >> 6, e = idx & 63;
        float t = (float)(l0 + li) * inv;
        pe[li][e] = (e < 32) ? sinf(t * TWO_PI * (float)(e + 1))
                             : cosf(t * TWO_PI * (float)(e - 31));
    }
    __syncthreads();
    for (int idx = tid; idx < FTL * EMB; idx += 256) {
        int li = idx >> 6, e = idx & 63;
        float s = b1[e];
#pragma unroll 16
        for (int cc = 0; cc < EMB; cc++) s += pe[li][cc] * ws[e][cc];
        h1s[li][e] = s / (1.f + __expf(-s));
    }
    __syncthreads();
    for (int idx = tid; idx < EMB * EMB; idx += 256)
        ws[idx >> 6][idx & 63] = w2[idx];
    __syncthreads();
    for (int idx = tid; idx < FTL * EMB; idx += 256) {
        int li = idx >> 6, e = idx & 63;
        float s = b2[e];
#pragma unroll 16
        for (int cc = 0; cc < EMB; cc++) s += h1s[li][cc] * ws[e][cc];
        h2s[li][e] = s / (1.f + __expf(-s));
    }
    __syncthreads();
    for (int d = tid; d < DMOD; d += 256) {
        float a = fabsf(ld[d]);
        float* outp = g_h + (size_t)d * LSEQ + l0;
        if (a * (float)l0 > 100.f) {
#pragma unroll
            for (int li = 0; li < FTL; li++) outp[li] = 0.f;
            continue;
        }
        float acc[FTL];
#pragma unroll
        for (int li = 0; li < FTL; li++) acc[li] = 0.f;
        const float* w3r = w3 + d * EMB;
#pragma unroll 8
        for (int e = 0; e < EMB; e++) {
            float wv = w3r[e];
#pragma unroll
            for (int li = 0; li < FTL; li++) acc[li] += h2s[li][e] * wv;
        }
        float b3d = b3[d];
        float dec  = __expf(-a * (float)l0);
        float step = __expf(-a);
#pragma unroll
        for (int li = 0; li < FTL; li++) {
            outp[li] = (acc[li] + b3d) * dec;
            dec *= step;
        }
    }
}

// ---------------- filter spectrum ----------------
__global__ __launch_bounds__(512) void k_fft_h() {
    extern __shared__ float2 sm[];
    const int c = blockIdx.x;
    const int d0 = 2 * c, d1 = 2 * c + 1;
    const int tid = threadIdx.x, nthr = blockDim.x;
    const float* s0 = g_h + (size_t)d0 * LSEQ;
    const float* s1 = g_h + (size_t)d1 * LSEQ;

    for (int j = tid; j < 1024; j += nthr) {
        float2 x[16];
#pragma unroll
        for (int t = 0; t < 8; t++) {
            int l = j + t * 1024;
            x[t] = make_float2(s0[l], s1[l]);
        }
#pragma unroll
        for (int b = 0; b < 4; b++) {
            int e1 = j + b * 1024;
            float2 w = g_tw[e1], w2 = g_tw[2 * e1], w3 = cmul(w, w2);
            float2 a0 = x[b], a1 = x[4 + b];
            x[b]      = cadd(a0, a1);
            x[4 + b]  = cmul(make_float2(a0.x + a1.y, a0.y - a1.x), w);
            x[8 + b]  = cmul(csub(a0, a1), w2);
            x[12 + b] = cmul(make_float2(a0.x - a1.y, a0.y + a1.x), w3);
        }
        {
            int e1 = j << 2;
            float2 w = g_tw[e1], w2 = g_tw[2 * e1], w3 = cmul(w, w2);
#pragma unroll
            for (int a = 0; a < 4; a++)
                bfly_fwd_w(x[4 * a], x[4 * a + 1], x[4 * a + 2], x[4 * a + 3], w, w2, w3);
        }
#pragma unroll
        for (int t = 0; t < 16; t++) sm[SWZ(j + t * 1024)] = x[t];
    }
    __syncthreads();

    fwd_pass2<64, 2>(sm, tid, nthr);
    fwd_pass2<4, 4>(sm, tid, nthr);

    float2* Ha = g_Hf + (size_t)d0 * NFFT;
    float2* Hb = g_Hf + (size_t)d1 * NFFT;
    for (int i = tid; i < 4096; i += nthr) {
        int r = rev4_6(i);
        int i2 = (r == 0) ? 0 : rev4_6(4096 - r);
        if (i2 < i) continue;
        float2 z[4], zz[4];
#pragma unroll
        for (int t = 0; t < 4; t++) z[t] = sm[SWZ(4 * i + t)];
        r4_fwd_nw(z);
        bool self = (i2 == i);
        if (!self) {
#pragma unroll
            for (int t = 0; t < 4; t++) zz[t] = sm[SWZ(4 * i2 + t)];
            r4_fwd_nw(zz);
        }
#pragma unroll
        for (int t = 0; t < 4; t++) {
            int tp = (i == 0) ? ((4 - t) & 3) : (3 - t);
            float2 z1 = z[t];
            float2 z2 = self ? z[tp] : zz[tp];
            float2 ha = make_float2(0.5f * (z1.x + z2.x), 0.5f * (z1.y - z2.y));
            float2 hb = make_float2(0.5f * (z1.y + z2.y), 0.5f * (z2.x - z1.x));
            int p = 4 * i + t;
            int q = 4 * i2 + tp;
            Ha[p] = ha;
            Hb[p] = hb;
            Ha[q] = make_float2(ha.x, -ha.y);
            Hb[q] = make_float2(hb.x, -hb.y);
        }
    }
}

// ---- fused fftconv ----
__global__ __launch_bounds__(512) void k_fftconv(const float* __restrict__ skw, const float* __restrict__ skb,
                                                 const float* __restrict__ svw, const float* __restrict__ svb) {
    extern __shared__ float2 sm[];
    const int bc = blockIdx.x;
    const int b = bc / (DMOD / 2);
    const int c = bc - b * (DMOD / 2);
    const int d0 = 2 * c, d1 = 2 * c + 1;
    const int tid = threadIdx.x, nthr = blockDim.x;

    const float* k0 = g_kT + ((size_t)b * DMOD + d0) * LSEQ;
    const float* k1 = g_kT + ((size_t)b * DMOD + d1) * LSEQ;
    const float* v0 = g_vT + ((size_t)b * DMOD + d0) * LSEQ;
    const float* v1 = g_vT + ((size_t)b * DMOD + d1) * LSEQ;

    float kw00 = skw[d0 * 3], kw01 = skw[d0 * 3 + 1], kw02 = skw[d0 * 3 + 2], kb0 = skb[d0];
    float vw00 = svw[d0 * 3], vw01 = svw[d0 * 3 + 1], vw02 = svw[d0 * 3 + 2], vb0 = svb[d0];
    float kw10 = skw[d1 * 3], kw11 = skw[d1 * 3 + 1], kw12 = skw[d1 * 3 + 2], kb1 = skb[d1];
    float vw10 = svw[d1 * 3], vw11 = svw[d1 * 3 + 1], vw12 = svw[d1 * 3 + 2], vb1 = svb[d1];

#define UPAIR(l, out)                                                                   \
    {                                                                                   \
        int _l = (l);                                                                   \
        float ka2 = k0[_l];                                                             \
        float ka1 = (_l >= 1) ? k0[_l - 1] : 0.f;                                       \
        float ka0 = (_l >= 2) ? k0[_l - 2] : 0.f;                                       \
        float va2 = v0[_l];                                                             \
        float va1 = (_l >= 1) ? v0[_l - 1] : 0.f;                                       \
        float va0 = (_l >= 2) ? v0[_l - 2] : 0.f;                                       \
        float u0 = (kw00 * ka0 + kw01 * ka1 + kw02 * ka2 + kb0) *                       \
                   (vw00 * va0 + vw01 * va1 + vw02 * va2 + vb0);                        \
        float kb2_ = k1[_l];                                                            \
        float kb1_ = (_l >= 1) ? k1[_l - 1] : 0.f;                                      \
        float kb0_ = (_l >= 2) ? k1[_l - 2] : 0.f;                                      \
        float vb2_ = v1[_l];                                                            \
        float vb1_ = (_l >= 1) ? v1[_l - 1] : 0.f;                                      \
        float vb0_ = (_l >= 2) ? v1[_l - 2] : 0.f;                                      \
        float u1 = (kw10 * kb0_ + kw11 * kb1_ + kw12 * kb2_ + kb1) *                    \
                   (vw10 * vb0_ + vw11 * vb1_ + vw12 * vb2_ + vb1);                     \
        out = make_float2(u0, u1);                                                      \
    }

    for (int j = tid; j < 1024; j += nthr) {
        float2 x[16];
#pragma unroll
        for (int t = 0; t < 8; t++) { UPAIR(j + t * 1024, x[t]); }
#pragma unroll
        for (int bb2 = 0; bb2 < 4; bb2++) {
            int e1 = j + bb2 * 1024;
            float2 w = g_tw[e1], w2 = g_tw[2 * e1], w3 = cmul(w, w2);
            float2 a0 = x[bb2], a1 = x[4 + bb2];
            x[bb2]      = cadd(a0, a1);
            x[4 + bb2]  = cmul(make_float2(a0.x + a1.y, a0.y - a1.x), w);
            x[8 + bb2]  = cmul(csub(a0, a1), w2);
            x[12 + bb2] = cmul(make_float2(a0.x - a1.y, a0.y + a1.x), w3);
        }
        {
            int e1 = j << 2;
            float2 w = g_tw[e1], w2 = g_tw[2 * e1], w3 = cmul(w, w2);
#pragma unroll
            for (int a = 0; a < 4; a++)
                bfly_fwd_w(x[4 * a], x[4 * a + 1], x[4 * a + 2], x[4 * a + 3], w, w2, w3);
        }
#pragma unroll
        for (int t = 0; t < 16; t++) sm[SWZ(j + t * 1024)] = x[t];
    }
#undef UPAIR
    __syncthreads();

    fwd_pass2<64, 2>(sm, tid, nthr);
    fwd_pass2<4, 4>(sm, tid, nthr);

    {
        const float2* Ha = g_Hf + (size_t)d0 * NFFT;
        const float2* Hb = g_Hf + (size_t)d1 * NFFT;
        const float hscale = 0.5f / (float)NFFT;
        for (int i = tid; i < 4096; i += nthr) {
            int r = rev4_6(i);
            int i2 = (r == 0) ? 0 : rev4_6(4096 - r);
            if (i2 < i) continue;
            float2 z[4], zz[4];
#pragma unroll
            for (int t = 0; t < 4; t++) z[t] = sm[SWZ(4 * i + t)];
            r4_fwd_nw(z);
            bool self = (i2 == i);
            if (!self) {
#pragma unroll
                for (int t = 0; t < 4; t++) zz[t] = sm[SWZ(4 * i2 + t)];
                r4_fwd_nw(zz);
            }
            float2 o1[4], o2[4];
#pragma unroll
            for (int t = 0; t < 4; t++) {
                int tp = (i == 0) ? ((4 - t) & 3) : (3 - t);
                float2 z1 = z[t];
                float2 z2 = self ? z[tp] : zz[tp];
                float2 za = make_float2(hscale * (z1.x + z2.x), hscale * (z1.y - z2.y));
                float2 zb = make_float2(hscale * (z1.y + z2.y), hscale * (z2.x - z1.x));
                int p = 4 * i + t;
                float2 ya = cmul(za, Ha[p]);
                float2 yb = cmul(zb, Hb[p]);
                o1[t]  = make_float2(ya.x - yb.y, ya.y + yb.x);
                o2[tp] = make_float2(ya.x + yb.y, yb.x - ya.y);
            }
            r4_inv_nw(o1);
#pragma unroll
            for (int t = 0; t < 4; t++) sm[SWZ(4 * i + t)] = o1[t];
            if (!self) {
                r4_inv_nw(o2);
#pragma unroll
                for (int t = 0; t < 4; t++) sm[SWZ(4 * i2 + t)] = o2[t];
            }
        }
    }
    __syncthreads();

    inv_pass2<4, 1>(sm, tid, nthr);
    inv_pass2<64, 3>(sm, tid, nthr);

    const float* q0 = g_qT + ((size_t)b * DMOD + d0) * LSEQ;
    const float* q1 = g_qT + ((size_t)b * DMOD + d1) * LSEQ;
    for (int j = tid; j < 1024; j += nthr) {
        float2 x[16];
#pragma unroll
        for (int t = 0; t < 16; t++) x[t] = sm[SWZ(j + t * 1024)];
        {
            int e1 = j << 2;
            float2 w = g_tw[e1], w2 = g_tw[2 * e1], w3 = cmul(w, w2);
#pragma unroll
            for (int bb2 = 0; bb2 < 4; bb2++)
                bfly_inv_w(x[4 * bb2], x[4 * bb2 + 1], x[4 * bb2 + 2], x[4 * bb2 + 3], w, w2, w3);
        }
#pragma unroll
        for (int a = 0; a < 4; a++) {
            int e1 = a * 1024 + j;
            float2 w = g_tw[e1], w2 = g_tw[2 * e1], w3 = cmul(w, w2);
            float2 c1 = cmulc(x[4 + a], w);
            float2 c2 = cmulc(x[8 + a], w2);
            float2 c3 = cmulc(x[12 + a], w3);
            float2 v0 = cadd(x[a], c2);
            float2 v1 = cadd(c1, c3);
            float2 v2 = csub(x[a], c2);
            float2 v3 = csub(c1, c3);
            float2 y0 = cadd(v0, v1);
            float2 y1 = make_float2(v2.x - v3.y, v2.y + v3.x);
            {
                int l = j + a * 1024;
                float qa = q0[l], qb = q1[l];
                float ga = qa / (1.f + __expf(-qa));
                float gb = qb / (1.f + __expf(-qb));
                *(float2*)&g_yg[((size_t)b * LSEQ + l) * DMOD + d0] = make_float2(ga * y0.x, gb * y0.y);
            }
            {
                int l = j + a * 1024 + 4096;
                float qa = q0[l], qb = q1[l];
                float ga = qa / (1.f + __expf(-qa));
                float gb = qb / (1.f + __expf(-qb));
                *(float2*)&g_yg[((size_t)b * LSEQ + l) * DMOD + d0] = make_float2(ga * y1.x, gb * y1.y);
            }
        }
    }
}

// ---------------- launch: fork filter chain onto side stream, overlap with qkv GEMM --
extern "C" void kernel_launch(void* const* d_in, const int* in_sizes, int n_in,
                              void* d_out, int out_size) {
    const float* x        = (const float*)d_in[0];
    const float* in_proj  = (const float*)d_in[1];
    const float* sck_w    = (const float*)d_in[2];
    const float* sck_b    = (const float*)d_in[3];
    const float* scv_w    = (const float*)d_in[4];
    const float* scv_b    = (const float*)d_in[5];
    const float* mlp_w1   = (const float*)d_in[6];
    const float* mlp_b1   = (const float*)d_in[7];
    const float* mlp_w2   = (const float*)d_in[8];
    const float* mlp_b2   = (const float*)d_in[9];
    const float* mlp_w3   = (const float*)d_in[10];
    const float* mlp_b3   = (const float*)d_in[11];
    const float* log_dec  = (const float*)d_in[12];
    const float* out_proj = (const float*)d_in[13];
    float* out = (float*)d_out;

    // lazy one-time stream/event setup (runs during the uncaptured correctness call)
    static cudaStream_t s2 = nullptr;
    static cudaEvent_t eFork = nullptr, eJoin = nullptr;
    static int smem_set = 0;
    const int smem_fft = NFFT * sizeof(float2);   // 128 KB
    if (!s2) {
        cudaStreamCreateWithFlags(&s2, cudaStreamNonBlocking);
        cudaEventCreateWithFlags(&eFork, cudaEventDisableTiming);
        cudaEventCreateWithFlags(&eJoin, cudaEventDisableTiming);
    }
    if (!smem_set) {
        cudaFuncSetAttribute(k_fft_h,   cudaFuncAttributeMaxDynamicSharedMemorySize, smem_fft);
        cudaFuncSetAttribute(k_fftconv, cudaFuncAttributeMaxDynamicSharedMemorySize, smem_fft);
        smem_set = 1;
    }

    // fork: side stream runs twiddle -> filter -> fft_h while main runs qkv GEMM
    cudaEventRecord(eFork, 0);
    cudaStreamWaitEvent(s2, eFork, 0);

    k_twiddle<<<16, 512, 0, s2>>>();
    k_filter<<<LSEQ / FTL, 256, 0, s2>>>(mlp_w1, mlp_b1, mlp_w2, mlp_b2, mlp_w3, mlp_b3, log_dec);
    k_fft_h<<<DMOD / 2, 512, smem_fft, s2>>>();
    cudaEventRecord(eJoin, s2);

    k_gemm_tc<0><<<dim3(128, 18), 256>>>(in_proj, x, nullptr);

    // join: fftconv needs qkv outputs (main) + Hf + twiddles (side)
    cudaStreamWaitEvent(0, eJoin, 0);
    k_fftconv<<<BATCH * DMOD / 2, 512, smem_fft>>>(sck_w, sck_b, scv_w, scv_b);
    k_gemm_tc<1><<<dim3(6, 128), 256>>>(nullptr, out_proj, out);
}

// round 13
// speedup vs baseline: 3.4424x; 1.0394x over previous
#include <cuda_runtime.h>
#include <cuda_bf16.h>
#include <cstdint>

// ---------------- problem constants ----------------
#define BATCH 2
#define LSEQ  8192
#define DMOD  768
#define NFFT  16384
#define LOGN  14
#define EMB   64

// ---------------- scratch ----------------
__device__ float  g_qT[BATCH * DMOD * LSEQ];
__device__ float  g_kT[BATCH * DMOD * LSEQ];
__device__ float  g_vT[BATCH * DMOD * LSEQ];
__device__ float  g_h [DMOD * LSEQ];
__device__ float2 g_Hf[DMOD * NFFT];           // filter spectrum, rev4-indexed
__device__ float  g_yg[BATCH * LSEQ * DMOD];
__device__ float2 g_tw[NFFT / 2];

__global__ void k_twiddle() {
    int i = blockIdx.x * blockDim.x + threadIdx.x;
    if (i < NFFT / 2) {
        double ang = -2.0 * 3.14159265358979323846 * (double)i / (double)NFFT;
        g_tw[i] = make_float2((float)cos(ang), (float)sin(ang));
    }
}

// ---------------- complex helpers ----------------
__device__ __forceinline__ float2 cmul(float2 a, float2 b) {
    return make_float2(a.x * b.x - a.y * b.y, a.x * b.y + a.y * b.x);
}
__device__ __forceinline__ float2 cmulc(float2 a, float2 b) {
    return make_float2(a.x * b.x + a.y * b.y, a.y * b.x - a.x * b.y);
}
__device__ __forceinline__ float2 cadd(float2 a, float2 b) { return make_float2(a.x + b.x, a.y + b.y); }
__device__ __forceinline__ float2 csub(float2 a, float2 b) { return make_float2(a.x - b.x, a.y - b.y); }

__device__ __forceinline__ int rev4_6(int x) {
    unsigned y = __brev((unsigned)x) >> 20;
    return (int)(((y & 0x555u) << 1) | ((y >> 1) & 0x555u));
}

__device__ __forceinline__ int SWZ(int e) {
    int h = (e >> 4) & 15;
    return (e & ~15) | ((e ^ (5 * h)) & 15);
}

__device__ __forceinline__ void bfly_fwd_w(float2& x0, float2& x1, float2& x2, float2& x3,
                                           float2 w, float2 w2, float2 w3) {
    float2 t0 = cadd(x0, x2), t1 = csub(x0, x2), t2 = cadd(x1, x3);
    float2 t3 = make_float2(x1.y - x3.y, x3.x - x1.x);
    x0 = cadd(t0, t2);
    x1 = cmul(cadd(t1, t3), w);
    x2 = cmul(csub(t0, t2), w2);
    x3 = cmul(csub(t1, t3), w3);
}
__device__ __forceinline__ void bfly_inv_w(float2& x0, float2& x1, float2& x2, float2& x3,
                                           float2 w, float2 w2, float2 w3) {
    float2 c1 = cmulc(x1, w), c2 = cmulc(x2, w2), c3 = cmulc(x3, w3);
    float2 v0 = cadd(x0, c2), v1 = cadd(c1, c3), v2 = csub(x0, c2), v3 = csub(c1, c3);
    x0 = cadd(v0, v1);
    x1 = make_float2(v2.x - v3.y, v2.y + v3.x);
    x2 = csub(v0, v1);
    x3 = make_float2(v2.x + v3.y, v2.y - v3.x);
}
__device__ __forceinline__ void r4_fwd_nw(float2* z) {
    float2 t0 = cadd(z[0], z[2]), t1 = csub(z[0], z[2]), t2 = cadd(z[1], z[3]);
    float2 t3 = make_float2(z[1].y - z[3].y, z[3].x - z[1].x);
    z[0] = cadd(t0, t2); z[1] = cadd(t1, t3); z[2] = csub(t0, t2); z[3] = csub(t1, t3);
}
__device__ __forceinline__ void r4_inv_nw(float2* z) {
    float2 v0 = cadd(z[0], z[2]), v1 = cadd(z[1], z[3]), v2 = csub(z[0], z[2]), v3 = csub(z[1], z[3]);
    z[0] = cadd(v0, v1);
    z[1] = make_float2(v2.x - v3.y, v2.y + v3.x);
    z[2] = csub(v0, v1);
    z[3] = make_float2(v2.x + v3.y, v2.y - v3.x);
}

template <int M4, int S>
__device__ __forceinline__ void fwd_pass2(float2* sm, int tid, int nthr) {
    for (int g = tid; g < 1024; g += nthr) {
        int j = g & (M4 - 1);
        int base = (g / M4) * (16 * M4) + j;
        float2 x[16];
#pragma unroll
        for (int t = 0; t < 16; t++) x[t] = sm[SWZ(base + t * M4)];
#pragma unroll
        for (int b = 0; b < 4; b++) {
            int e1 = (j + b * M4) << (2 * S);
            float2 w = g_tw[e1], w2 = g_tw[2 * e1], w3 = cmul(w, w2);
            bfly_fwd_w(x[b], x[4 + b], x[8 + b], x[12 + b], w, w2, w3);
        }
        {
            int e1 = j << (2 * (S + 1));
            float2 w = g_tw[e1], w2 = g_tw[2 * e1], w3 = cmul(w, w2);
#pragma unroll
            for (int a = 0; a < 4; a++)
                bfly_fwd_w(x[4 * a], x[4 * a + 1], x[4 * a + 2], x[4 * a + 3], w, w2, w3);
        }
#pragma unroll
        for (int t = 0; t < 16; t++) sm[SWZ(base + t * M4)] = x[t];
    }
    __syncthreads();
}

template <int M, int S>
__device__ __forceinline__ void inv_pass2(float2* sm, int tid, int nthr) {
    for (int g = tid; g < 1024; g += nthr) {
        int j = g & (M - 1);
        int base = (g / M) * (16 * M) + j;
        float2 x[16];
#pragma unroll
        for (int t = 0; t < 16; t++) x[t] = sm[SWZ(base + t * M)];
        {
            int e1 = j << (2 * (6 - S));
            float2 w = g_tw[e1], w2 = g_tw[2 * e1], w3 = cmul(w, w2);
#pragma unroll
            for (int b = 0; b < 4; b++)
                bfly_inv_w(x[4 * b], x[4 * b + 1], x[4 * b + 2], x[4 * b + 3], w, w2, w3);
        }
#pragma unroll
        for (int a = 0; a < 4; a++) {
            int e1 = (a * M + j) << (2 * (5 - S));
            float2 w = g_tw[e1], w2 = g_tw[2 * e1], w3 = cmul(w, w2);
            bfly_inv_w(x[a], x[4 + a], x[8 + a], x[12 + a], w, w2, w3);
        }
#pragma unroll
        for (int t = 0; t < 16; t++) sm[SWZ(base + t * M)] = x[t];
    }
    __syncthreads();
}

// ---------------- bf16 split helpers + tensor-core GEMM ----------------
__device__ __forceinline__ void split_pack(float x, float y, uint32_t& hi, uint32_t& lo) {
    __nv_bfloat16 xh = __float2bfloat16(x);
    __nv_bfloat16 yh = __float2bfloat16(y);
    __nv_bfloat16 xl = __float2bfloat16(x - __bfloat162float(xh));
    __nv_bfloat16 yl = __float2bfloat16(y - __bfloat162float(yh));
    hi = ((uint32_t)__bfloat16_as_ushort(yh) << 16) | (uint32_t)__bfloat16_as_ushort(xh);
    lo = ((uint32_t)__bfloat16_as_ushort(yl) << 16) | (uint32_t)__bfloat16_as_ushort(xl);
}

#define MMA_BF16(c, a, b)                                                     \
    asm volatile(                                                             \
        "mma.sync.aligned.m16n8k16.row.col.f32.bf16.bf16.f32 "                \
        "{%0,%1,%2,%3},{%4,%5,%6,%7},{%8,%9},{%0,%1,%2,%3};"                  \
        : "+f"(c[0]), "+f"(c[1]), "+f"(c[2]), "+f"(c[3])                      \
        : "r"(a[0]), "r"(a[1]), "r"(a[2]), "r"(a[3]), "r"(b[0]), "r"(b[1]))

#define LDSM4(r0, r1, r2, r3, addr)                                           \
    asm volatile("ldmatrix.sync.aligned.m8n8.x4.shared.b16 {%0,%1,%2,%3}, [%4];" \
                 : "=r"(r0), "=r"(r1), "=r"(r2), "=r"(r3) : "r"(addr))

#define BKP2 12
#define ROWB (BKP2 * 4)   // smem row stride in bytes (48)
template <int EPI>
__global__ __launch_bounds__(256) void k_gemm_tc(const float* __restrict__ Aarg,
                                                 const float* __restrict__ B,
                                                 float* __restrict__ C) {
    __shared__ uint32_t Ah[128][BKP2], Al[128][BKP2];
    __shared__ uint32_t Bh[128][BKP2], Bl[128][BKP2];

    const float* A = (EPI == 1) ? (const float*)g_yg : Aarg;
    const int i0 = blockIdx.y * 128;
    const int j0 = blockIdx.x * 128;
    const int tid = threadIdx.x;
    const int wid = tid >> 5;
    const int lane = tid & 31;
    const int g  = lane >> 2;
    const int tg = lane & 3;
    const int wm = wid >> 2;
    const int wn = wid & 3;

    const int r0  = tid >> 2;
    const int kq0 = (tid & 3) * 4;
    const int cc0 = kq0 >> 1;
    const float* Ar0 = A + (size_t)(i0 + r0) * 768 + kq0;
    const float* Ar1 = A + (size_t)(i0 + r0 + 64) * 768 + kq0;
    const float* Br0 = B + (size_t)(j0 + r0) * 768 + kq0;
    const float* Br1 = B + (size_t)(j0 + r0 + 64) * 768 + kq0;

    // ldmatrix lane addresses (bytes) --------------------------------------
    const int arow = wm * 64 + (lane & 7) + ((lane >> 3) & 1) * 8;
    const int acol = ((lane >> 4) & 1) * 4;
    const uint32_t aOff = (uint32_t)(arow * ROWB + acol * 4);
    const uint32_t aHadr = (uint32_t)__cvta_generic_to_shared(&Ah[0][0]) + aOff;
    const uint32_t aLadr = (uint32_t)__cvta_generic_to_shared(&Al[0][0]) + aOff;
    const int brow = wn * 32 + (lane & 7) + ((lane >> 4) & 1) * 8;
    const int bcol = ((lane >> 3) & 1) * 4;
    const uint32_t bOff = (uint32_t)(brow * ROWB + bcol * 4);
    const uint32_t bHadr = (uint32_t)__cvta_generic_to_shared(&Bh[0][0]) + bOff;
    const uint32_t bLadr = (uint32_t)__cvta_generic_to_shared(&Bl[0][0]) + bOff;

    float c[4][4][4];
#pragma unroll
    for (int mi = 0; mi < 4; mi++)
#pragma unroll
        for (int ni = 0; ni < 4; ni++)
#pragma unroll
            for (int r = 0; r < 4; r++) c[mi][ni][r] = 0.f;

    float4 va0 = *(const float4*)(Ar0);
    float4 va1 = *(const float4*)(Ar1);
    float4 vb0 = *(const float4*)(Br0);
    float4 vb1 = *(const float4*)(Br1);

    for (int kb = 0; kb < 768; kb += 16) {
        {
            uint32_t h0, l0, h1, l1;
            split_pack(va0.x, va0.y, h0, l0);
            split_pack(va0.z, va0.w, h1, l1);
            Ah[r0][cc0] = h0; Ah[r0][cc0 + 1] = h1;
            Al[r0][cc0] = l0; Al[r0][cc0 + 1] = l1;
            split_pack(va1.x, va1.y, h0, l0);
            split_pack(va1.z, va1.w, h1, l1);
            Ah[r0 + 64][cc0] = h0; Ah[r0 + 64][cc0 + 1] = h1;
            Al[r0 + 64][cc0] = l0; Al[r0 + 64][cc0 + 1] = l1;
            split_pack(vb0.x, vb0.y, h0, l0);
            split_pack(vb0.z, vb0.w, h1, l1);
            Bh[r0][cc0] = h0; Bh[r0][cc0 + 1] = h1;
            Bl[r0][cc0] = l0; Bl[r0][cc0 + 1] = l1;
            split_pack(vb1.x, vb1.y, h0, l0);
            split_pack(vb1.z, vb1.w, h1, l1);
            Bh[r0 + 64][cc0] = h0; Bh[r0 + 64][cc0 + 1] = h1;
            Bl[r0 + 64][cc0] = l0; Bl[r0 + 64][cc0 + 1] = l1;
        }
        __syncthreads();

        if (kb + 16 < 768) {
            va0 = *(const float4*)(Ar0 + kb + 16);
            va1 = *(const float4*)(Ar1 + kb + 16);
            vb0 = *(const float4*)(Br0 + kb + 16);
            vb1 = *(const float4*)(Br1 + kb + 16);
        }

        // fragment loads via ldmatrix (12 LDSM vs 48 scalar LDS)
        uint32_t ah[4][4], al[4][4], bh[4][2], bl[4][2];
#pragma unroll
        for (int mi = 0; mi < 4; mi++) {
            LDSM4(ah[mi][0], ah[mi][1], ah[mi][2], ah[mi][3], aHadr + mi * 16 * ROWB);
            LDSM4(al[mi][0], al[mi][1], al[mi][2], al[mi][3], aLadr + mi * 16 * ROWB);
        }
        LDSM4(bh[0][0], bh[0][1], bh[1][0], bh[1][1], bHadr);
        LDSM4(bh[2][0], bh[2][1], bh[3][0], bh[3][1], bHadr + 16 * ROWB);
        LDSM4(bl[0][0], bl[0][1], bl[1][0], bl[1][1], bLadr);
        LDSM4(bl[2][0], bl[2][1], bl[3][0], bl[3][1], bLadr + 16 * ROWB);

#pragma unroll
        for (int mi = 0; mi < 4; mi++)
#pragma unroll
            for (int ni = 0; ni < 4; ni++) {
                MMA_BF16(c[mi][ni], ah[mi], bh[ni]);
                MMA_BF16(c[mi][ni], al[mi], bh[ni]);
                MMA_BF16(c[mi][ni], ah[mi], bl[ni]);
            }
        __syncthreads();
    }

#pragma unroll
    for (int mi = 0; mi < 4; mi++) {
#pragma unroll
        for (int ni = 0; ni < 4; ni++) {
            int rm0 = i0 + wm * 64 + mi * 16 + g;
            int rm1 = rm0 + 8;
            int cn  = j0 + wn * 32 + ni * 8 + 2 * tg;
            if (EPI == 0) {
                int part0 = rm0 / DMOD, dch0 = rm0 - part0 * DMOD;
                int part1 = rm1 / DMOD, dch1 = rm1 - part1 * DMOD;
                float* t0 = (part0 == 0) ? g_qT : (part0 == 1 ? g_kT : g_vT);
                float* t1 = (part1 == 0) ? g_qT : (part1 == 1 ? g_kT : g_vT);
                int bb = cn >> 13;
                int l  = cn & (LSEQ - 1);
                *(float2*)(t0 + ((size_t)bb * DMOD + dch0) * LSEQ + l) =
                    make_float2(c[mi][ni][0], c[mi][ni][1]);
                *(float2*)(t1 + ((size_t)bb * DMOD + dch1) * LSEQ + l) =
                    make_float2(c[mi][ni][2], c[mi][ni][3]);
            } else {
                *(float2*)(C + (size_t)rm0 * DMOD + cn) =
                    make_float2(c[mi][ni][0], c[mi][ni][1]);
                *(float2*)(C + (size_t)rm1 * DMOD + cn) =
                    make_float2(c[mi][ni][2], c[mi][ni][3]);
            }
        }
    }
}

// ---------------- hyena filter MLP + decay ----------------
#define FTL 32
__global__ __launch_bounds__(256) void k_filter(const float* __restrict__ w1, const float* __restrict__ b1,
                                                const float* __restrict__ w2, const float* __restrict__ b2,
                                                const float* __restrict__ w3, const float* __restrict__ b3,
                                                const float* __restrict__ ld) {
    __shared__ float ws [EMB][EMB + 1];
    __shared__ float pe [FTL][EMB + 1];
    __shared__ float h1s[FTL][EMB + 1];
    __shared__ float h2s[FTL][EMB + 1];
    const int l0 = blockIdx.x * FTL;
    const int tid = threadIdx.x;
    const float TWO_PI = 6.2831853071795864769f;
    const float inv = 1.0f / (float)(LSEQ - 1);

    for (int idx = tid; idx < EMB * EMB; idx += 256)
        ws[idx >> 6][idx & 63] = w1[idx];
    for (int idx = tid; idx < FTL * EMB; idx += 256) {
        int li = idx >> 6, e = idx & 63;
        float t = (float)(l0 + li) * inv;
        pe[li][e] = (e < 32) ? sinf(t * TWO_PI * (float)(e + 1))
                             : cosf(t * TWO_PI * (float)(e - 31));
    }
    __syncthreads();
    for (int idx = tid; idx < FTL * EMB; idx += 256) {
        int li = idx >> 6, e = idx & 63;
        float s = b1[e];
#pragma unroll 16
        for (int cc = 0; cc < EMB; cc++) s += pe[li][cc] * ws[e][cc];
        h1s[li][e] = s / (1.f + __expf(-s));
    }
    __syncthreads();
    for (int idx = tid; idx < EMB * EMB; idx += 256)
        ws[idx >> 6][idx & 63] = w2[idx];
    __syncthreads();
    for (int idx = tid; idx < FTL * EMB; idx += 256) {
        int li = idx >> 6, e = idx & 63;
        float s = b2[e];
#pragma unroll 16
        for (int cc = 0; cc < EMB; cc++) s += h1s[li][cc] * ws[e][cc];
        h2s[li][e] = s / (1.f + __expf(-s));
    }
    __syncthreads();
    for (int d = tid; d < DMOD; d += 256) {
        float a = fabsf(ld[d]);
        float* outp = g_h + (size_t)d * LSEQ + l0;
        if (a * (float)l0 > 100.f) {
#pragma unroll
            for (int li = 0; li < FTL; li++) outp[li] = 0.f;
            continue;
        }
        float acc[FTL];
#pragma unroll
        for (int li = 0; li < FTL; li++) acc[li] = 0.f;
        const float* w3r = w3 + d * EMB;
#pragma unroll 8
        for (int e = 0; e < EMB; e++) {
            float wv = w3r[e];
#pragma unroll
            for (int li = 0; li < FTL; li++) acc[li] += h2s[li][e] * wv;
        }
        float b3d = b3[d];
        float dec  = __expf(-a * (float)l0);
        float step = __expf(-a);
#pragma unroll
        for (int li = 0; li < FTL; li++) {
            outp[li] = (acc[li] + b3d) * dec;
            dec *= step;
        }
    }
}

// ---------------- filter spectrum ----------------
__global__ __launch_bounds__(512) void k_fft_h() {
    extern __shared__ float2 sm[];
    const int c = blockIdx.x;
    const int d0 = 2 * c, d1 = 2 * c + 1;
    const int tid = threadIdx.x, nthr = blockDim.x;
    const float* s0 = g_h + (size_t)d0 * LSEQ;
    const float* s1 = g_h + (size_t)d1 * LSEQ;

    for (int j = tid; j < 1024; j += nthr) {
        float2 x[16];
#pragma unroll
        for (int t = 0; t < 8; t++) {
            int l = j + t * 1024;
            x[t] = make_float2(s0[l], s1[l]);
        }
#pragma unroll
        for (int b = 0; b < 4; b++) {
            int e1 = j + b * 1024;
            float2 w = g_tw[e1], w2 = g_tw[2 * e1], w3 = cmul(w, w2);
            float2 a0 = x[b], a1 = x[4 + b];
            x[b]      = cadd(a0, a1);
            x[4 + b]  = cmul(make_float2(a0.x + a1.y, a0.y - a1.x), w);
            x[8 + b]  = cmul(csub(a0, a1), w2);
            x[12 + b] = cmul(make_float2(a0.x - a1.y, a0.y + a1.x), w3);
        }
        {
            int e1 = j << 2;
            float2 w = g_tw[e1], w2 = g_tw[2 * e1], w3 = cmul(w, w2);
#pragma unroll
            for (int a = 0; a < 4; a++)
                bfly_fwd_w(x[4 * a], x[4 * a + 1], x[4 * a + 2], x[4 * a + 3], w, w2, w3);
        }
#pragma unroll
        for (int t = 0; t < 16; t++) sm[SWZ(j + t * 1024)] = x[t];
    }
    __syncthreads();

    fwd_pass2<64, 2>(sm, tid, nthr);
    fwd_pass2<4, 4>(sm, tid, nthr);

    float2* Ha = g_Hf + (size_t)d0 * NFFT;
    float2* Hb = g_Hf + (size_t)d1 * NFFT;
    for (int i = tid; i < 4096; i += nthr) {
        int r = rev4_6(i);
        int i2 = (r == 0) ? 0 : rev4_6(4096 - r);
        if (i2 < i) continue;
        float2 z[4], zz[4];
#pragma unroll
        for (int t = 0; t < 4; t++) z[t] = sm[SWZ(4 * i + t)];
        r4_fwd_nw(z);
        bool self = (i2 == i);
        if (!self) {
#pragma unroll
            for (int t = 0; t < 4; t++) zz[t] = sm[SWZ(4 * i2 + t)];
            r4_fwd_nw(zz);
        }
#pragma unroll
        for (int t = 0; t < 4; t++) {
            int tp = (i == 0) ? ((4 - t) & 3) : (3 - t);
            float2 z1 = z[t];
            float2 z2 = self ? z[tp] : zz[tp];
            float2 ha = make_float2(0.5f * (z1.x + z2.x), 0.5f * (z1.y - z2.y));
            float2 hb = make_float2(0.5f * (z1.y + z2.y), 0.5f * (z2.x - z1.x));
            int p = 4 * i + t;
            int q = 4 * i2 + tp;
            Ha[p] = ha;
            Hb[p] = hb;
            Ha[q] = make_float2(ha.x, -ha.y);
            Hb[q] = make_float2(hb.x, -hb.y);
        }
    }
}

// ---- fused fftconv ----
__global__ __launch_bounds__(512) void k_fftconv(const float* __restrict__ skw, const float* __restrict__ skb,
                                                 const float* __restrict__ svw, const float* __restrict__ svb) {
    extern __shared__ float2 sm[];
    const int bc = blockIdx.x;
    const int b = bc / (DMOD / 2);
    const int c = bc - b * (DMOD / 2);
    const int d0 = 2 * c, d1 = 2 * c + 1;
    const int tid = threadIdx.x, nthr = blockDim.x;

    const float* k0 = g_kT + ((size_t)b * DMOD + d0) * LSEQ;
    const float* k1 = g_kT + ((size_t)b * DMOD + d1) * LSEQ;
    const float* v0 = g_vT + ((size_t)b * DMOD + d0) * LSEQ;
    const float* v1 = g_vT + ((size_t)b * DMOD + d1) * LSEQ;

    float kw00 = skw[d0 * 3], kw01 = skw[d0 * 3 + 1], kw02 = skw[d0 * 3 + 2], kb0 = skb[d0];
    float vw00 = svw[d0 * 3], vw01 = svw[d0 * 3 + 1], vw02 = svw[d0 * 3 + 2], vb0 = svb[d0];
    float kw10 = skw[d1 * 3], kw11 = skw[d1 * 3 + 1], kw12 = skw[d1 * 3 + 2], kb1 = skb[d1];
    float vw10 = svw[d1 * 3], vw11 = svw[d1 * 3 + 1], vw12 = svw[d1 * 3 + 2], vb1 = svb[d1];

#define UPAIR(l, out)                                                                   \
    {                                                                                   \
        int _l = (l);                                                                   \
        float ka2 = k0[_l];                                                             \
        float ka1 = (_l >= 1) ? k0[_l - 1] : 0.f;                                       \
        float ka0 = (_l >= 2) ? k0[_l - 2] : 0.f;                                       \
        float va2 = v0[_l];                                                             \
        float va1 = (_l >= 1) ? v0[_l - 1] : 0.f;                                       \
        float va0 = (_l >= 2) ? v0[_l - 2] : 0.f;                                       \
        float u0 = (kw00 * ka0 + kw01 * ka1 + kw02 * ka2 + kb0) *                       \
                   (vw00 * va0 + vw01 * va1 + vw02 * va2 + vb0);                        \
        float kb2_ = k1[_l];                                                            \
        float kb1_ = (_l >= 1) ? k1[_l - 1] : 0.f;                                      \
        float kb0_ = (_l >= 2) ? k1[_l - 2] : 0.f;                                      \
        float vb2_ = v1[_l];                                                            \
        float vb1_ = (_l >= 1) ? v1[_l - 1] : 0.f;                                      \
        float vb0_ = (_l >= 2) ? v1[_l - 2] : 0.f;                                      \
        float u1 = (kw10 * kb0_ + kw11 * kb1_ + kw12 * kb2_ + kb1) *                    \
                   (vw10 * vb0_ + vw11 * vb1_ + vw12 * vb2_ + vb1);                     \
        out = make_float2(u0, u1);                                                      \
    }

    for (int j = tid; j < 1024; j += nthr) {
        float2 x[16];
#pragma unroll
        for (int t = 0; t < 8; t++) { UPAIR(j + t * 1024, x[t]); }
#pragma unroll
        for (int bb2 = 0; bb2 < 4; bb2++) {
            int e1 = j + bb2 * 1024;
            float2 w = g_tw[e1], w2 = g_tw[2 * e1], w3 = cmul(w, w2);
            float2 a0 = x[bb2], a1 = x[4 + bb2];
            x[bb2]      = cadd(a0, a1);
            x[4 + bb2]  = cmul(make_float2(a0.x + a1.y, a0.y - a1.x), w);
            x[8 + bb2]  = cmul(csub(a0, a1), w2);
            x[12 + bb2] = cmul(make_float2(a0.x - a1.y, a0.y + a1.x), w3);
        }
        {
            int e1 = j << 2;
            float2 w = g_tw[e1], w2 = g_tw[2 * e1], w3 = cmul(w, w2);
#pragma unroll
            for (int a = 0; a < 4; a++)
                bfly_fwd_w(x[4 * a], x[4 * a + 1], x[4 * a + 2], x[4 * a + 3], w, w2, w3);
        }
#pragma unroll
        for (int t = 0; t < 16; t++) sm[SWZ(j + t * 1024)] = x[t];
    }
#undef UPAIR
    __syncthreads();

    fwd_pass2<64, 2>(sm, tid, nthr);
    fwd_pass2<4, 4>(sm, tid, nthr);

    {
        const float2* Ha = g_Hf + (size_t)d0 * NFFT;
        const float2* Hb = g_Hf + (size_t)d1 * NFFT;
        const float hscale = 0.5f / (float)NFFT;
        for (int i = tid; i < 4096; i += nthr) {
            int r = rev4_6(i);
            int i2 = (r == 0) ? 0 : rev4_6(4096 - r);
            if (i2 < i) continue;
            float2 z[4], zz[4];
#pragma unroll
            for (int t = 0; t < 4; t++) z[t] = sm[SWZ(4 * i + t)];
            r4_fwd_nw(z);
            bool self = (i2 == i);
            if (!self) {
#pragma unroll
                for (int t = 0; t < 4; t++) zz[t] = sm[SWZ(4 * i2 + t)];
                r4_fwd_nw(zz);
            }
            float2 o1[4], o2[4];
#pragma unroll
            for (int t = 0; t < 4; t++) {
                int tp = (i == 0) ? ((4 - t) & 3) : (3 - t);
                float2 z1 = z[t];
                float2 z2 = self ? z[tp] : zz[tp];
                float2 za = make_float2(hscale * (z1.x + z2.x), hscale * (z1.y - z2.y));
                float2 zb = make_float2(hscale * (z1.y + z2.y), hscale * (z2.x - z1.x));
                int p = 4 * i + t;
                float2 ya = cmul(za, Ha[p]);
                float2 yb = cmul(zb, Hb[p]);
                o1[t]  = make_float2(ya.x - yb.y, ya.y + yb.x);
                o2[tp] = make_float2(ya.x + yb.y, yb.x - ya.y);
            }
            r4_inv_nw(o1);
#pragma unroll
            for (int t = 0; t < 4; t++) sm[SWZ(4 * i + t)] = o1[t];
            if (!self) {
                r4_inv_nw(o2);
#pragma unroll
                for (int t = 0; t < 4; t++) sm[SWZ(4 * i2 + t)] = o2[t];
            }
        }
    }
    __syncthreads();

    inv_pass2<4, 1>(sm, tid, nthr);
    inv_pass2<64, 3>(sm, tid, nthr);

    const float* q0 = g_qT + ((size_t)b * DMOD + d0) * LSEQ;
    const float* q1 = g_qT + ((size_t)b * DMOD + d1) * LSEQ;
    for (int j = tid; j < 1024; j += nthr) {
        float2 x[16];
#pragma unroll
        for (int t = 0; t < 16; t++) x[t] = sm[SWZ(j + t * 1024)];
        {
            int e1 = j << 2;
            float2 w = g_tw[e1], w2 = g_tw[2 * e1], w3 = cmul(w, w2);
#pragma unroll
            for (int bb2 = 0; bb2 < 4; bb2++)
                bfly_inv_w(x[4 * bb2], x[4 * bb2 + 1], x[4 * bb2 + 2], x[4 * bb2 + 3], w, w2, w3);
        }
#pragma unroll
        for (int a = 0; a < 4; a++) {
            int e1 = a * 1024 + j;
            float2 w = g_tw[e1], w2 = g_tw[2 * e1], w3 = cmul(w, w2);
            float2 c1 = cmulc(x[4 + a], w);
            float2 c2 = cmulc(x[8 + a], w2);
            float2 c3 = cmulc(x[12 + a], w3);
            float2 v0 = cadd(x[a], c2);
            float2 v1 = cadd(c1, c3);
            float2 v2 = csub(x[a], c2);
            float2 v3 = csub(c1, c3);
            float2 y0 = cadd(v0, v1);
            float2 y1 = make_float2(v2.x - v3.y, v2.y + v3.x);
            {
                int l = j + a * 1024;
                float qa = q0[l], qb = q1[l];
                float ga = qa / (1.f + __expf(-qa));
                float gb = qb / (1.f + __expf(-qb));
                *(float2*)&g_yg[((size_t)b * LSEQ + l) * DMOD + d0] = make_float2(ga * y0.x, gb * y0.y);
            }
            {
                int l = j + a * 1024 + 4096;
                float qa = q0[l], qb = q1[l];
                float ga = qa / (1.f + __expf(-qa));
                float gb = qb / (1.f + __expf(-qb));
                *(float2*)&g_yg[((size_t)b * LSEQ + l) * DMOD + d0] = make_float2(ga * y1.x, gb * y1.y);
            }
        }
    }
}

// ---------------- launch: fork filter chain onto side stream, overlap with qkv GEMM --
extern "C" void kernel_launch(void* const* d_in, const int* in_sizes, int n_in,
                              void* d_out, int out_size) {
    const float* x        = (const float*)d_in[0];
    const float* in_proj  = (const float*)d_in[1];
    const float* sck_w    = (const float*)d_in[2];
    const float* sck_b    = (const float*)d_in[3];
    const float* scv_w    = (const float*)d_in[4];
    const float* scv_b    = (const float*)d_in[5];
    const float* mlp_w1   = (const float*)d_in[6];
    const float* mlp_b1   = (const float*)d_in[7];
    const float* mlp_w2   = (const float*)d_in[8];
    const float* mlp_b2   = (const float*)d_in[9];
    const float* mlp_w3   = (const float*)d_in[10];
    const float* mlp_b3   = (const float*)d_in[11];
    const float* log_dec  = (const float*)d_in[12];
    const float* out_proj = (const float*)d_in[13];
    float* out = (float*)d_out;

    static cudaStream_t s2 = nullptr;
    static cudaEvent_t eFork = nullptr, eJoin = nullptr;
    static int smem_set = 0;
    const int smem_fft = NFFT * sizeof(float2);   // 128 KB
    if (!s2) {
        cudaStreamCreateWithFlags(&s2, cudaStreamNonBlocking);
        cudaEventCreateWithFlags(&eFork, cudaEventDisableTiming);
        cudaEventCreateWithFlags(&eJoin, cudaEventDisableTiming);
    }
    if (!smem_set) {
        cudaFuncSetAttribute(k_fft_h,   cudaFuncAttributeMaxDynamicSharedMemorySize, smem_fft);
        cudaFuncSetAttribute(k_fftconv, cudaFuncAttributeMaxDynamicSharedMemorySize, smem_fft);
        smem_set = 1;
    }

    cudaEventRecord(eFork, 0);
    cudaStreamWaitEvent(s2, eFork, 0);

    k_twiddle<<<16, 512, 0, s2>>>();
    k_filter<<<LSEQ / FTL, 256, 0, s2>>>(mlp_w1, mlp_b1, mlp_w2, mlp_b2, mlp_w3, mlp_b3, log_dec);
    k_fft_h<<<DMOD / 2, 512, smem_fft, s2>>>();
    cudaEventRecord(eJoin, s2);

    k_gemm_tc<0><<<dim3(128, 18), 256>>>(in_proj, x, nullptr);

    cudaStreamWaitEvent(0, eJoin, 0);
    k_fftconv<<<BATCH * DMOD / 2, 512, smem_fft>>>(sck_w, sck_b, scv_w, scv_b);
    k_gemm_tc<1><<<dim3(6, 128), 256>>>(nullptr, out_proj, out);
}

// round 15
// speedup vs baseline: 3.4960x; 1.0156x over previous
#include <cuda_runtime.h>
#include <cuda_bf16.h>
#include <cstdint>

// ---------------- problem constants ----------------
#define BATCH 2
#define LSEQ  8192
#define DMOD  768
#define NFFT  16384
#define LOGN  14
#define EMB   64

// ---------------- scratch ----------------
__device__ float  g_qT[BATCH * DMOD * LSEQ];
__device__ float  g_kT[BATCH * DMOD * LSEQ];
__device__ float  g_vT[BATCH * DMOD * LSEQ];
__device__ float  g_h [DMOD * LSEQ];
__device__ float2 g_Hf[DMOD * NFFT];           // filter spectrum, rev4-indexed
__device__ float  g_yg[BATCH * LSEQ * DMOD];
__device__ float2 g_tw[NFFT / 2];

__global__ void k_twiddle() {
    int i = blockIdx.x * blockDim.x + threadIdx.x;
    if (i < NFFT / 2) {
        double ang = -2.0 * 3.14159265358979323846 * (double)i / (double)NFFT;
        g_tw[i] = make_float2((float)cos(ang), (float)sin(ang));
    }
}

// ---------------- complex helpers ----------------
__device__ __forceinline__ float2 cmul(float2 a, float2 b) {
    return make_float2(a.x * b.x - a.y * b.y, a.x * b.y + a.y * b.x);
}
__device__ __forceinline__ float2 cmulc(float2 a, float2 b) {
    return make_float2(a.x * b.x + a.y * b.y, a.y * b.x - a.x * b.y);
}
__device__ __forceinline__ float2 cadd(float2 a, float2 b) { return make_float2(a.x + b.x, a.y + b.y); }
__device__ __forceinline__ float2 csub(float2 a, float2 b) { return make_float2(a.x - b.x, a.y - b.y); }

__device__ __forceinline__ int rev4_6(int x) {
    unsigned y = __brev((unsigned)x) >> 20;
    return (int)(((y & 0x555u) << 1) | ((y >> 1) & 0x555u));
}

__device__ __forceinline__ int SWZ(int e) {
    int h = (e >> 4) & 15;
    return (e & ~15) | ((e ^ (5 * h)) & 15);
}

__device__ __forceinline__ void bfly_fwd_w(float2& x0, float2& x1, float2& x2, float2& x3,
                                           float2 w, float2 w2, float2 w3) {
    float2 t0 = cadd(x0, x2), t1 = csub(x0, x2), t2 = cadd(x1, x3);
    float2 t3 = make_float2(x1.y - x3.y, x3.x - x1.x);
    x0 = cadd(t0, t2);
    x1 = cmul(cadd(t1, t3), w);
    x2 = cmul(csub(t0, t2), w2);
    x3 = cmul(csub(t1, t3), w3);
}
__device__ __forceinline__ void bfly_inv_w(float2& x0, float2& x1, float2& x2, float2& x3,
                                           float2 w, float2 w2, float2 w3) {
    float2 c1 = cmulc(x1, w), c2 = cmulc(x2, w2), c3 = cmulc(x3, w3);
    float2 v0 = cadd(x0, c2), v1 = cadd(c1, c3), v2 = csub(x0, c2), v3 = csub(c1, c3);
    x0 = cadd(v0, v1);
    x1 = make_float2(v2.x - v3.y, v2.y + v3.x);
    x2 = csub(v0, v1);
    x3 = make_float2(v2.x + v3.y, v2.y - v3.x);
}
__device__ __forceinline__ void r4_fwd_nw(float2* z) {
    float2 t0 = cadd(z[0], z[2]), t1 = csub(z[0], z[2]), t2 = cadd(z[1], z[3]);
    float2 t3 = make_float2(z[1].y - z[3].y, z[3].x - z[1].x);
    z[0] = cadd(t0, t2); z[1] = cadd(t1, t3); z[2] = csub(t0, t2); z[3] = csub(t1, t3);
}
__device__ __forceinline__ void r4_inv_nw(float2* z) {
    float2 v0 = cadd(z[0], z[2]), v1 = cadd(z[1], z[3]), v2 = csub(z[0], z[2]), v3 = csub(z[1], z[3]);
    z[0] = cadd(v0, v1);
    z[1] = make_float2(v2.x - v3.y, v2.y + v3.x);
    z[2] = csub(v0, v1);
    z[3] = make_float2(v2.x + v3.y, v2.y - v3.x);
}

template <int M4, int S>
__device__ __forceinline__ void fwd_pass2(float2* sm, int tid, int nthr) {
    for (int g = tid; g < 1024; g += nthr) {
        int j = g & (M4 - 1);
        int base = (g / M4) * (16 * M4) + j;
        float2 x[16];
#pragma unroll
        for (int t = 0; t < 16; t++) x[t] = sm[SWZ(base + t * M4)];
#pragma unroll
        for (int b = 0; b < 4; b++) {
            int e1 = (j + b * M4) << (2 * S);
            float2 w = g_tw[e1], w2 = g_tw[2 * e1], w3 = cmul(w, w2);
            bfly_fwd_w(x[b], x[4 + b], x[8 + b], x[12 + b], w, w2, w3);
        }
        {
            int e1 = j << (2 * (S + 1));
            float2 w = g_tw[e1], w2 = g_tw[2 * e1], w3 = cmul(w, w2);
#pragma unroll
            for (int a = 0; a < 4; a++)
                bfly_fwd_w(x[4 * a], x[4 * a + 1], x[4 * a + 2], x[4 * a + 3], w, w2, w3);
        }
#pragma unroll
        for (int t = 0; t < 16; t++) sm[SWZ(base + t * M4)] = x[t];
    }
    __syncthreads();
}

template <int M, int S>
__device__ __forceinline__ void inv_pass2(float2* sm, int tid, int nthr) {
    for (int g = tid; g < 1024; g += nthr) {
        int j = g & (M - 1);
        int base = (g / M) * (16 * M) + j;
        float2 x[16];
#pragma unroll
        for (int t = 0; t < 16; t++) x[t] = sm[SWZ(base + t * M)];
        {
            int e1 = j << (2 * (6 - S));
            float2 w = g_tw[e1], w2 = g_tw[2 * e1], w3 = cmul(w, w2);
#pragma unroll
            for (int b = 0; b < 4; b++)
                bfly_inv_w(x[4 * b], x[4 * b + 1], x[4 * b + 2], x[4 * b + 3], w, w2, w3);
        }
#pragma unroll
        for (int a = 0; a < 4; a++) {
            int e1 = (a * M + j) << (2 * (5 - S));
            float2 w = g_tw[e1], w2 = g_tw[2 * e1], w3 = cmul(w, w2);
            bfly_inv_w(x[a], x[4 + a], x[8 + a], x[12 + a], w, w2, w3);
        }
#pragma unroll
        for (int t = 0; t < 16; t++) sm[SWZ(base + t * M)] = x[t];
    }
    __syncthreads();
}

// ---------------- bf16 split helpers + tensor-core GEMM ----------------
__device__ __forceinline__ void split_pack(float x, float y, uint32_t& hi, uint32_t& lo) {
    __nv_bfloat16 xh = __float2bfloat16(x);
    __nv_bfloat16 yh = __float2bfloat16(y);
    __nv_bfloat16 xl = __float2bfloat16(x - __bfloat162float(xh));
    __nv_bfloat16 yl = __float2bfloat16(y - __bfloat162float(yh));
    hi = ((uint32_t)__bfloat16_as_ushort(yh) << 16) | (uint32_t)__bfloat16_as_ushort(xh);
    lo = ((uint32_t)__bfloat16_as_ushort(yl) << 16) | (uint32_t)__bfloat16_as_ushort(xl);
}

#define MMA_BF16(c, a, b)                                                     \
    asm volatile(                                                             \
        "mma.sync.aligned.m16n8k16.row.col.f32.bf16.bf16.f32 "                \
        "{%0,%1,%2,%3},{%4,%5,%6,%7},{%8,%9},{%0,%1,%2,%3};"                  \
        : "+f"(c[0]), "+f"(c[1]), "+f"(c[2]), "+f"(c[3])                      \
        : "r"(a[0]), "r"(a[1]), "r"(a[2]), "r"(a[3]), "r"(b[0]), "r"(b[1]))

#define LDSM4(r0, r1, r2, r3, addr)                                           \
    asm volatile("ldmatrix.sync.aligned.m8n8.x4.shared.b16 {%0,%1,%2,%3}, [%4];" \
                 : "=r"(r0), "=r"(r1), "=r"(r2), "=r"(r3) : "r"(addr))

#define BKP2 12
#define ROWB (BKP2 * 4)   // smem row stride in bytes (48)
// EPI=0: base = token offset (applied to j0). EPI=1: base = row offset (applied to i0).
template <int EPI>
__global__ __launch_bounds__(256) void k_gemm_tc(const float* __restrict__ Aarg,
                                                 const float* __restrict__ B,
                                                 float* __restrict__ C, int basearg) {
    __shared__ uint32_t Ah[128][BKP2], Al[128][BKP2];
    __shared__ uint32_t Bh[128][BKP2], Bl[128][BKP2];

    const float* A = (EPI == 1) ? (const float*)g_yg : Aarg;
    const int i0 = blockIdx.y * 128 + ((EPI == 1) ? basearg : 0);
    const int j0 = blockIdx.x * 128 + ((EPI == 0) ? basearg : 0);
    const int tid = threadIdx.x;
    const int wid = tid >> 5;
    const int lane = tid & 31;
    const int g  = lane >> 2;
    const int tg = lane & 3;
    const int wm = wid >> 2;
    const int wn = wid & 3;

    const int r0  = tid >> 2;
    const int kq0 = (tid & 3) * 4;
    const int cc0 = kq0 >> 1;
    const float* Ar0 = A + (size_t)(i0 + r0) * 768 + kq0;
    const float* Ar1 = A + (size_t)(i0 + r0 + 64) * 768 + kq0;
    const float* Br0 = B + (size_t)(j0 + r0) * 768 + kq0;
    const float* Br1 = B + (size_t)(j0 + r0 + 64) * 768 + kq0;

    // ldmatrix lane addresses (bytes)
    const int arow = wm * 64 + (lane & 7) + ((lane >> 3) & 1) * 8;
    const int acol = ((lane >> 4) & 1) * 4;
    const uint32_t aOff = (uint32_t)(arow * ROWB + acol * 4);
    const uint32_t aHadr = (uint32_t)__cvta_generic_to_shared(&Ah[0][0]) + aOff;
    const uint32_t aLadr = (uint32_t)__cvta_generic_to_shared(&Al[0][0]) + aOff;
    const int brow = wn * 32 + (lane & 7) + ((lane >> 4) & 1) * 8;
    const int bcol = ((lane >> 3) & 1) * 4;
    const uint32_t bOff = (uint32_t)(brow * ROWB + bcol * 4);
    const uint32_t bHadr = (uint32_t)__cvta_generic_to_shared(&Bh[0][0]) + bOff;
    const uint32_t bLadr = (uint32_t)__cvta_generic_to_shared(&Bl[0][0]) + bOff;

    float c[4][4][4];
#pragma unroll
    for (int mi = 0; mi < 4; mi++)
#pragma unroll
        for (int ni = 0; ni < 4; ni++)
#pragma unroll
            for (int r = 0; r < 4; r++) c[mi][ni][r] = 0.f;

    float4 va0 = *(const float4*)(Ar0);
    float4 va1 = *(const float4*)(Ar1);
    float4 vb0 = *(const float4*)(Br0);
    float4 vb1 = *(const float4*)(Br1);

    for (int kb = 0; kb < 768; kb += 16) {
        {
            uint32_t h0, l0, h1, l1;
            split_pack(va0.x, va0.y, h0, l0);
            split_pack(va0.z, va0.w, h1, l1);
            Ah[r0][cc0] = h0; Ah[r0][cc0 + 1] = h1;
            Al[r0][cc0] = l0; Al[r0][cc0 + 1] = l1;
            split_pack(va1.x, va1.y, h0, l0);
            split_pack(va1.z, va1.w, h1, l1);
            Ah[r0 + 64][cc0] = h0; Ah[r0 + 64][cc0 + 1] = h1;
            Al[r0 + 64][cc0] = l0; Al[r0 + 64][cc0 + 1] = l1;
            split_pack(vb0.x, vb0.y, h0, l0);
            split_pack(vb0.z, vb0.w, h1, l1);
            Bh[r0][cc0] = h0; Bh[r0][cc0 + 1] = h1;
            Bl[r0][cc0] = l0; Bl[r0][cc0 + 1] = l1;
            split_pack(vb1.x, vb1.y, h0, l0);
            split_pack(vb1.z, vb1.w, h1, l1);
            Bh[r0 + 64][cc0] = h0; Bh[r0 + 64][cc0 + 1] = h1;
            Bl[r0 + 64][cc0] = l0; Bl[r0 + 64][cc0 + 1] = l1;
        }
        __syncthreads();

        if (kb + 16 < 768) {
            va0 = *(const float4*)(Ar0 + kb + 16);
            va1 = *(const float4*)(Ar1 + kb + 16);
            vb0 = *(const float4*)(Br0 + kb + 16);
            vb1 = *(const float4*)(Br1 + kb + 16);
        }

        uint32_t ah[4][4], al[4][4], bh[4][2], bl[4][2];
#pragma unroll
        for (int mi = 0; mi < 4; mi++) {
            LDSM4(ah[mi][0], ah[mi][1], ah[mi][2], ah[mi][3], aHadr + mi * 16 * ROWB);
            LDSM4(al[mi][0], al[mi][1], al[mi][2], al[mi][3], aLadr + mi * 16 * ROWB);
        }
        LDSM4(bh[0][0], bh[0][1], bh[1][0], bh[1][1], bHadr);
        LDSM4(bh[2][0], bh[2][1], bh[3][0], bh[3][1], bHadr + 16 * ROWB);
        LDSM4(bl[0][0], bl[0][1], bl[1][0], bl[1][1], bLadr);
        LDSM4(bl[2][0], bl[2][1], bl[3][0], bl[3][1], bLadr + 16 * ROWB);

#pragma unroll
        for (int mi = 0; mi < 4; mi++)
#pragma unroll
            for (int ni = 0; ni < 4; ni++) {
                MMA_BF16(c[mi][ni], ah[mi], bh[ni]);
                MMA_BF16(c[mi][ni], al[mi], bh[ni]);
                MMA_BF16(c[mi][ni], ah[mi], bl[ni]);
            }
        __syncthreads();
    }

#pragma unroll
    for (int mi = 0; mi < 4; mi++) {
#pragma unroll
        for (int ni = 0; ni < 4; ni++) {
            int rm0 = i0 + wm * 64 + mi * 16 + g;
            int rm1 = rm0 + 8;
            int cn  = j0 + wn * 32 + ni * 8 + 2 * tg;
            if (EPI == 0) {
                int part0 = rm0 / DMOD, dch0 = rm0 - part0 * DMOD;
                int part1 = rm1 / DMOD, dch1 = rm1 - part1 * DMOD;
                float* t0 = (part0 == 0) ? g_qT : (part0 == 1 ? g_kT : g_vT);
                float* t1 = (part1 == 0) ? g_qT : (part1 == 1 ? g_kT : g_vT);
                int bb = cn >> 13;
                int l  = cn & (LSEQ - 1);
                *(float2*)(t0 + ((size_t)bb * DMOD + dch0) * LSEQ + l) =
                    make_float2(c[mi][ni][0], c[mi][ni][1]);
                *(float2*)(t1 + ((size_t)bb * DMOD + dch1) * LSEQ + l) =
                    make_float2(c[mi][ni][2], c[mi][ni][3]);
            } else {
                *(float2*)(C + (size_t)rm0 * DMOD + cn) =
                    make_float2(c[mi][ni][0], c[mi][ni][1]);
                *(float2*)(C + (size_t)rm1 * DMOD + cn) =
                    make_float2(c[mi][ni][2], c[mi][ni][3]);
            }
        }
    }
}

// ---------------- hyena filter MLP + decay ----------------
#define FTL 32
__global__ __launch_bounds__(256) void k_filter(const float* __restrict__ w1, const float* __restrict__ b1,
                                                const float* __restrict__ w2, const float* __restrict__ b2,
                                                const float* __restrict__ w3, const float* __restrict__ b3,
                                                const float* __restrict__ ld) {
    __shared__ float ws [EMB][EMB + 1];
    __shared__ float pe [FTL][EMB + 1];
    __shared__ float h1s[FTL][EMB + 1];
    __shared__ float h2s[FTL][EMB + 1];
    const int l0 = blockIdx.x * FTL;
    const int tid = threadIdx.x;
    const float TWO_PI = 6.2831853071795864769f;
    const float inv = 1.0f / (float)(LSEQ - 1);

    for (int idx = tid; idx < EMB * EMB; idx += 256)
        ws[idx >> 6][idx & 63] = w1[idx];
    for (int idx = tid; idx < FTL * EMB; idx += 256) {
        int li = idx >> 6, e = idx & 63;
        float t = (float)(l0 + li) * inv;
        pe[li][e] = (e < 32) ? sinf(t * TWO_PI * (float)(e + 1))
                             : cosf(t * TWO_PI * (float)(e - 31));
    }
    __syncthreads();
    for (int idx = tid; idx < FTL * EMB; idx += 256) {
        int li = idx >> 6, e = idx & 63;
        float s = b1[e];
#pragma unroll 16
        for (int cc = 0; cc < EMB; cc++) s += pe[li][cc] * ws[e][cc];
        h1s[li][e] = s / (1.f + __expf(-s));
    }
    __syncthreads();
    for (int idx = tid; idx < EMB * EMB; idx += 256)
        ws[idx >> 6][idx & 63] = w2[idx];
    __syncthreads();
    for (int idx = tid; idx < FTL * EMB; idx += 256) {
        int li = idx >> 6, e = idx & 63;
        float s = b2[e];
#pragma unroll 16
        for (int cc = 0; cc < EMB; cc++) s += h1s[li][cc] * ws[e][cc];
        h2s[li][e] = s / (1.f + __expf(-s));
    }
    __syncthreads();
    for (int d = tid; d < DMOD; d += 256) {
        float a = fabsf(ld[d]);
        float* outp = g_h + (size_t)d * LSEQ + l0;
        if (a * (float)l0 > 100.f) {
#pragma unroll
            for (int li = 0; li < FTL; li++) outp[li] = 0.f;
            continue;
        }
        float acc[FTL];
#pragma unroll
        for (int li = 0; li < FTL; li++) acc[li] = 0.f;
        const float* w3r = w3 + d * EMB;
#pragma unroll 8
        for (int e = 0; e < EMB; e++) {
            float wv = w3r[e];
#pragma unroll
            for (int li = 0; li < FTL; li++) acc[li] += h2s[li][e] * wv;
        }
        float b3d = b3[d];
        float dec  = __expf(-a * (float)l0);
        float step = __expf(-a);
#pragma unroll
        for (int li = 0; li < FTL; li++) {
            outp[li] = (acc[li] + b3d) * dec;
            dec *= step;
        }
    }
}

// ---------------- filter spectrum ----------------
__global__ __launch_bounds__(512) void k_fft_h() {
    extern __shared__ float2 sm[];
    const int c = blockIdx.x;
    const int d0 = 2 * c, d1 = 2 * c + 1;
    const int tid = threadIdx.x, nthr = blockDim.x;
    const float* s0 = g_h + (size_t)d0 * LSEQ;
    const float* s1 = g_h + (size_t)d1 * LSEQ;

    for (int j = tid; j < 1024; j += nthr) {
        float2 x[16];
#pragma unroll
        for (int t = 0; t < 8; t++) {
            int l = j + t * 1024;
            x[t] = make_float2(s0[l], s1[l]);
        }
#pragma unroll
        for (int b = 0; b < 4; b++) {
            int e1 = j + b * 1024;
            float2 w = g_tw[e1], w2 = g_tw[2 * e1], w3 = cmul(w, w2);
            float2 a0 = x[b], a1 = x[4 + b];
            x[b]      = cadd(a0, a1);
            x[4 + b]  = cmul(make_float2(a0.x + a1.y, a0.y - a1.x), w);
            x[8 + b]  = cmul(csub(a0, a1), w2);
            x[12 + b] = cmul(make_float2(a0.x - a1.y, a0.y + a1.x), w3);
        }
        {
            int e1 = j << 2;
            float2 w = g_tw[e1], w2 = g_tw[2 * e1], w3 = cmul(w, w2);
#pragma unroll
            for (int a = 0; a < 4; a++)
                bfly_fwd_w(x[4 * a], x[4 * a + 1], x[4 * a + 2], x[4 * a + 3], w, w2, w3);
        }
#pragma unroll
        for (int t = 0; t < 16; t++) sm[SWZ(j + t * 1024)] = x[t];
    }
    __syncthreads();

    fwd_pass2<64, 2>(sm, tid, nthr);
    fwd_pass2<4, 4>(sm, tid, nthr);

    float2* Ha = g_Hf + (size_t)d0 * NFFT;
    float2* Hb = g_Hf + (size_t)d1 * NFFT;
    for (int i = tid; i < 4096; i += nthr) {
        int r = rev4_6(i);
        int i2 = (r == 0) ? 0 : rev4_6(4096 - r);
        if (i2 < i) continue;
        float2 z[4], zz[4];
#pragma unroll
        for (int t = 0; t < 4; t++) z[t] = sm[SWZ(4 * i + t)];
        r4_fwd_nw(z);
        bool self = (i2 == i);
        if (!self) {
#pragma unroll
            for (int t = 0; t < 4; t++) zz[t] = sm[SWZ(4 * i2 + t)];
            r4_fwd_nw(zz);
        }
#pragma unroll
        for (int t = 0; t < 4; t++) {
            int tp = (i == 0) ? ((4 - t) & 3) : (3 - t);
            float2 z1 = z[t];
            float2 z2 = self ? z[tp] : zz[tp];
            float2 ha = make_float2(0.5f * (z1.x + z2.x), 0.5f * (z1.y - z2.y));
            float2 hb = make_float2(0.5f * (z1.y + z2.y), 0.5f * (z2.x - z1.x));
            int p = 4 * i + t;
            int q = 4 * i2 + tp;
            Ha[p] = ha;
            Hb[p] = hb;
            Ha[q] = make_float2(ha.x, -ha.y);
            Hb[q] = make_float2(hb.x, -hb.y);
        }
    }
}

// ---- fused fftconv (block-offset param for batch-split pipelining) ----
__global__ __launch_bounds__(512) void k_fftconv(const float* __restrict__ skw, const float* __restrict__ skb,
                                                 const float* __restrict__ svw, const float* __restrict__ svb,
                                                 int bcbase) {
    extern __shared__ float2 sm[];
    const int bc = blockIdx.x + bcbase;
    const int b = bc / (DMOD / 2);
    const int c = bc - b * (DMOD / 2);
    const int d0 = 2 * c, d1 = 2 * c + 1;
    const int tid = threadIdx.x, nthr = blockDim.x;

    const float* k0 = g_kT + ((size_t)b * DMOD + d0) * LSEQ;
    const float* k1 = g_kT + ((size_t)b * DMOD + d1) * LSEQ;
    const float* v0 = g_vT + ((size_t)b * DMOD + d0) * LSEQ;
    const float* v1 = g_vT + ((size_t)b * DMOD + d1) * LSEQ;

    float kw00 = skw[d0 * 3], kw01 = skw[d0 * 3 + 1], kw02 = skw[d0 * 3 + 2], kb0 = skb[d0];
    float vw00 = svw[d0 * 3], vw01 = svw[d0 * 3 + 1], vw02 = svw[d0 * 3 + 2], vb0 = svb[d0];
    float kw10 = skw[d1 * 3], kw11 = skw[d1 * 3 + 1], kw12 = skw[d1 * 3 + 2], kb1 = skb[d1];
    float vw10 = svw[d1 * 3], vw11 = svw[d1 * 3 + 1], vw12 = svw[d1 * 3 + 2], vb1 = svb[d1];

#define UPAIR(l, out)                                                                   \
    {                                                                                   \
        int _l = (l);                                                                   \
        float ka2 = k0[_l];                                                             \
        float ka1 = (_l >= 1) ? k0[_l - 1] : 0.f;                                       \
        float ka0 = (_l >= 2) ? k0[_l - 2] : 0.f;                                       \
        float va2 = v0[_l];                                                             \
        float va1 = (_l >= 1) ? v0[_l - 1] : 0.f;                                       \
        float va0 = (_l >= 2) ? v0[_l - 2] : 0.f;                                       \
        float u0 = (kw00 * ka0 + kw01 * ka1 + kw02 * ka2 + kb0) *                       \
                   (vw00 * va0 + vw01 * va1 + vw02 * va2 + vb0);                        \
        float kb2_ = k1[_l];                                                            \
        float kb1_ = (_l >= 1) ? k1[_l - 1] : 0.f;                                      \
        float kb0_ = (_l >= 2) ? k1[_l - 2] : 0.f;                                      \
        float vb2_ = v1[_l];                                                            \
        float vb1_ = (_l >= 1) ? v1[_l - 1] : 0.f;                                      \
        float vb0_ = (_l >= 2) ? v1[_l - 2] : 0.f;                                      \
        float u1 = (kw10 * kb0_ + kw11 * kb1_ + kw12 * kb2_ + kb1) *                    \
                   (vw10 * vb0_ + vw11 * vb1_ + vw12 * vb2_ + vb1);                     \
        out = make_float2(u0, u1);                                                      \
    }

    for (int j = tid; j < 1024; j += nthr) {
        float2 x[16];
#pragma unroll
        for (int t = 0; t < 8; t++) { UPAIR(j + t * 1024, x[t]); }
#pragma unroll
        for (int bb2 = 0; bb2 < 4; bb2++) {
            int e1 = j + bb2 * 1024;
            float2 w = g_tw[e1], w2 = g_tw[2 * e1], w3 = cmul(w, w2);
            float2 a0 = x[bb2], a1 = x[4 + bb2];
            x[bb2]      = cadd(a0, a1);
            x[4 + bb2]  = cmul(make_float2(a0.x + a1.y, a0.y - a1.x), w);
            x[8 + bb2]  = cmul(csub(a0, a1), w2);
            x[12 + bb2] = cmul(make_float2(a0.x - a1.y, a0.y + a1.x), w3);
        }
        {
            int e1 = j << 2;
            float2 w = g_tw[e1], w2 = g_tw[2 * e1], w3 = cmul(w, w2);
#pragma unroll
            for (int a = 0; a < 4; a++)
                bfly_fwd_w(x[4 * a], x[4 * a + 1], x[4 * a + 2], x[4 * a + 3], w, w2, w3);
        }
#pragma unroll
        for (int t = 0; t < 16; t++) sm[SWZ(j + t * 1024)] = x[t];
    }
#undef UPAIR
    __syncthreads();

    fwd_pass2<64, 2>(sm, tid, nthr);
    fwd_pass2<4, 4>(sm, tid, nthr);

    {
        const float2* Ha = g_Hf + (size_t)d0 * NFFT;
        const float2* Hb = g_Hf + (size_t)d1 * NFFT;
        const float hscale = 0.5f / (float)NFFT;
        for (int i = tid; i < 4096; i += nthr) {
            int r = rev4_6(i);
            int i2 = (r == 0) ? 0 : rev4_6(4096 - r);
            if (i2 < i) continue;
            float2 z[4], zz[4];
#pragma unroll
            for (int t = 0; t < 4; t++) z[t] = sm[SWZ(4 * i + t)];
            r4_fwd_nw(z);
            bool self = (i2 == i);
            if (!self) {
#pragma unroll
                for (int t = 0; t < 4; t++) zz[t] = sm[SWZ(4 * i2 + t)];
                r4_fwd_nw(zz);
            }
            float2 o1[4], o2[4];
#pragma unroll
            for (int t = 0; t < 4; t++) {
                int tp = (i == 0) ? ((4 - t) & 3) : (3 - t);
                float2 z1 = z[t];
                float2 z2 = self ? z[tp] : zz[tp];
                float2 za = make_float2(hscale * (z1.x + z2.x), hscale * (z1.y - z2.y));
                float2 zb = make_float2(hscale * (z1.y + z2.y), hscale * (z2.x - z1.x));
                int p = 4 * i + t;
                float2 ya = cmul(za, Ha[p]);
                float2 yb = cmul(zb, Hb[p]);
                o1[t]  = make_float2(ya.x - yb.y, ya.y + yb.x);
                o2[tp] = make_float2(ya.x + yb.y, yb.x - ya.y);
            }
            r4_inv_nw(o1);
#pragma unroll
            for (int t = 0; t < 4; t++) sm[SWZ(4 * i + t)] = o1[t];
            if (!self) {
                r4_inv_nw(o2);
#pragma unroll
                for (int t = 0; t < 4; t++) sm[SWZ(4 * i2 + t)] = o2[t];
            }
        }
    }
    __syncthreads();

    inv_pass2<4, 1>(sm, tid, nthr);
    inv_pass2<64, 3>(sm, tid, nthr);

    const float* q0 = g_qT + ((size_t)b * DMOD + d0) * LSEQ;
    const float* q1 = g_qT + ((size_t)b * DMOD + d1) * LSEQ;
    for (int j = tid; j < 1024; j += nthr) {
        float2 x[16];
#pragma unroll
        for (int t = 0; t < 16; t++) x[t] = sm[SWZ(j + t * 1024)];
        {
            int e1 = j << 2;
            float2 w = g_tw[e1], w2 = g_tw[2 * e1], w3 = cmul(w, w2);
#pragma unroll
            for (int bb2 = 0; bb2 < 4; bb2++)
                bfly_inv_w(x[4 * bb2], x[4 * bb2 + 1], x[4 * bb2 + 2], x[4 * bb2 + 3], w, w2, w3);
        }
#pragma unroll
        for (int a = 0; a < 4; a++) {
            int e1 = a * 1024 + j;
            float2 w = g_tw[e1], w2 = g_tw[2 * e1], w3 = cmul(w, w2);
            float2 c1 = cmulc(x[4 + a], w);
            float2 c2 = cmulc(x[8 + a], w2);
            float2 c3 = cmulc(x[12 + a], w3);
            float2 v0 = cadd(x[a], c2);
            float2 v1 = cadd(c1, c3);
            float2 v2 = csub(x[a], c2);
            float2 v3 = csub(c1, c3);
            float2 y0 = cadd(v0, v1);
            float2 y1 = make_float2(v2.x - v3.y, v2.y + v3.x);
            {
                int l = j + a * 1024;
                float qa = q0[l], qb = q1[l];
                float ga = qa / (1.f + __expf(-qa));
                float gb = qb / (1.f + __expf(-qb));
                *(float2*)&g_yg[((size_t)b * LSEQ + l) * DMOD + d0] = make_float2(ga * y0.x, gb * y0.y);
            }
            {
                int l = j + a * 1024 + 4096;
                float qa = q0[l], qb = q1[l];
                float ga = qa / (1.f + __expf(-qa));
                float gb = qb / (1.f + __expf(-qb));
                *(float2*)&g_yg[((size_t)b * LSEQ + l) * DMOD + d0] = make_float2(ga * y1.x, gb * y1.y);
            }
        }
    }
}

// --------- launch: batch-split pipeline across two streams ---------
// main:  qkv(b0) -> qkv(b1) -> [wait ec0] out(b0) -> [wait ec1] out(b1)
// side:  twiddle -> filter -> fft_h -> [wait e0] fftconv(b0) -> [wait e1] fftconv(b1)
extern "C" void kernel_launch(void* const* d_in, const int* in_sizes, int n_in,
                              void* d_out, int out_size) {
    const float* x        = (const float*)d_in[0];
    const float* in_proj  = (const float*)d_in[1];
    const float* sck_w    = (const float*)d_in[2];
    const float* sck_b    = (const float*)d_in[3];
    const float* scv_w    = (const float*)d_in[4];
    const float* scv_b    = (const float*)d_in[5];
    const float* mlp_w1   = (const float*)d_in[6];
    const float* mlp_b1   = (const float*)d_in[7];
    const float* mlp_w2   = (const float*)d_in[8];
    const float* mlp_b2   = (const float*)d_in[9];
    const float* mlp_w3   = (const float*)d_in[10];
    const float* mlp_b3   = (const float*)d_in[11];
    const float* log_dec  = (const float*)d_in[12];
    const float* out_proj = (const float*)d_in[13];
    float* out = (float*)d_out;

    static cudaStream_t s2 = nullptr;
    static cudaEvent_t eFork = nullptr, e0 = nullptr, e1 = nullptr, ec0 = nullptr, ec1 = nullptr;
    static int smem_set = 0;
    const int smem_fft = NFFT * sizeof(float2);   // 128 KB
    if (!s2) {
        cudaStreamCreateWithFlags(&s2, cudaStreamNonBlocking);
        cudaEventCreateWithFlags(&eFork, cudaEventDisableTiming);
        cudaEventCreateWithFlags(&e0, cudaEventDisableTiming);
        cudaEventCreateWithFlags(&e1, cudaEventDisableTiming);
        cudaEventCreateWithFlags(&ec0, cudaEventDisableTiming);
        cudaEventCreateWithFlags(&ec1, cudaEventDisableTiming);
    }
    if (!smem_set) {
        cudaFuncSetAttribute(k_fft_h,   cudaFuncAttributeMaxDynamicSharedMemorySize, smem_fft);
        cudaFuncSetAttribute(k_fftconv, cudaFuncAttributeMaxDynamicSharedMemorySize, smem_fft);
        smem_set = 1;
    }

    // fork
    cudaEventRecord(eFork, 0);
    cudaStreamWaitEvent(s2, eFork, 0);
    k_twiddle<<<16, 512, 0, s2>>>();
    k_filter<<<LSEQ / FTL, 256, 0, s2>>>(mlp_w1, mlp_b1, mlp_w2, mlp_b2, mlp_w3, mlp_b3, log_dec);
    k_fft_h<<<DMOD / 2, 512, smem_fft, s2>>>();

    // qkv batch 0 (tokens 0..8191)
    k_gemm_tc<0><<<dim3(64, 18), 256>>>(in_proj, x, nullptr, 0);
    cudaEventRecord(e0, 0);
    cudaStreamWaitEvent(s2, e0, 0);
    k_fftconv<<<DMOD / 2, 512, smem_fft, s2>>>(sck_w, sck_b, scv_w, scv_b, 0);
    cudaEventRecord(ec0, s2);

    // qkv batch 1 (tokens 8192..16383) — overlaps fftconv(b0)
    k_gemm_tc<0><<<dim3(64, 18), 256>>>(in_proj, x, nullptr, 8192);
    cudaEventRecord(e1, 0);
    cudaStreamWaitEvent(s2, e1, 0);
    k_fftconv<<<DMOD / 2, 512, smem_fft, s2>>>(sck_w, sck_b, scv_w, scv_b, DMOD / 2);
    cudaEventRecord(ec1, s2);

    // out-proj halves — out(b0) overlaps fftconv(b1)
    cudaStreamWaitEvent(0, ec0, 0);
    k_gemm_tc<1><<<dim3(6, 64), 256>>>(nullptr, out_proj, out, 0);
    cudaStreamWaitEvent(0, ec1, 0);
    k_gemm_tc<1><<<dim3(6, 64), 256>>>(nullptr, out_proj, out, 8192);
}